// round 1
// baseline (speedup 1.0000x reference)
#include <cuda_runtime.h>
#include <math.h>

#define DM    768
#define DMLP  3072
#define NH    12
#define DH    64
#define BATCH 2
#define SEQ   2048
#define ROWS  (BATCH*SEQ)     /* 4096 */
#define QKVN  (3*DM)          /* 2304 */

// ---------------- scratch (static device globals; no allocation) -----------
__device__ float g_x   [ROWS*DM];     // ln1 output
__device__ float g_wqkv[DM*QKVN];     // packed [768 x 2304] QKV weight
__device__ float g_bqkv[QKVN];        // packed QKV bias
__device__ float g_qkv [ROWS*QKVN];   // Q|K|V, row = token, col blocks of 768
__device__ float g_z   [ROWS*DM];     // attention output (pre O-proj)
__device__ float g_mid [ROWS*DM];     // resid_mid
__device__ float g_y   [ROWS*DM];     // ln2 output
__device__ float g_h   [ROWS*DMLP];   // MLP hidden

// ---------------- layernorm -------------------------------------------------
__global__ __launch_bounds__(256)
void ln_kernel(const float* __restrict__ in, const float* __restrict__ w,
               const float* __restrict__ b, float* __restrict__ out) {
    int row = blockIdx.x;
    const float* x = in + (size_t)row * DM;
    float s = 0.f, ss = 0.f;
    for (int i = threadIdx.x; i < DM; i += 256) {
        float v = x[i]; s += v; ss += v * v;
    }
    __shared__ float red0[32], red1[32];
    #pragma unroll
    for (int o = 16; o; o >>= 1) {
        s  += __shfl_xor_sync(0xffffffffu, s,  o);
        ss += __shfl_xor_sync(0xffffffffu, ss, o);
    }
    int warp = threadIdx.x >> 5, lane = threadIdx.x & 31;
    if (lane == 0) { red0[warp] = s; red1[warp] = ss; }
    __syncthreads();
    if (warp == 0) {
        s  = (lane < 8) ? red0[lane] : 0.f;
        ss = (lane < 8) ? red1[lane] : 0.f;
        #pragma unroll
        for (int o = 4; o; o >>= 1) {
            s  += __shfl_xor_sync(0xffffffffu, s,  o);
            ss += __shfl_xor_sync(0xffffffffu, ss, o);
        }
        if (lane == 0) {
            float mean = s / DM;
            float var  = ss / DM - mean * mean;
            red0[0] = mean;
            red1[0] = rsqrtf(var + 1e-5f);
        }
    }
    __syncthreads();
    float mean = red0[0], inv = red1[0];
    for (int i = threadIdx.x; i < DM; i += 256)
        out[(size_t)row * DM + i] = (x[i] - mean) * inv * w[i] + b[i];
}

// ---------------- QKV weight repack ----------------------------------------
__global__ void pack_qkv(const float* __restrict__ WQ, const float* __restrict__ WK,
                         const float* __restrict__ WV,
                         const float* __restrict__ bQ, const float* __restrict__ bK,
                         const float* __restrict__ bV,
                         float* __restrict__ W, float* __restrict__ bias) {
    int idx = blockIdx.x * 256 + threadIdx.x;            // over 768*768
    if (idx < DM * DM) {
        int k = idx / DM, c = idx % DM;
        int h = c >> 6, e = c & 63;
        int src = h * (DM * DH) + k * DH + e;            // W[h, k, e]
        W[(size_t)k * QKVN + c]            = WQ[src];
        W[(size_t)k * QKVN + DM + c]       = WK[src];
        W[(size_t)k * QKVN + 2 * DM + c]   = WV[src];
    }
    if (idx < DM) {
        bias[idx]          = bQ[idx];
        bias[DM + idx]     = bK[idx];
        bias[2 * DM + idx] = bV[idx];
    }
}

// ---------------- SGEMM 128x128x8, 256 thr, 8x8 per thread ------------------
__device__ __forceinline__ float gelu_new(float v) {
    float v3 = v * v * v;
    return 0.5f * v * (1.f + tanhf(0.7978845608028654f * (v + 0.044715f * v3)));
}

template<bool GELU, bool RESID>
__global__ __launch_bounds__(256)
void gemm_kernel(const float* __restrict__ A, const float* __restrict__ B,
                 const float* __restrict__ bias, const float* __restrict__ R,
                 float* __restrict__ C, int M, int N, int K) {
    const int BM = 128, BN = 128, BK = 8;
    __shared__ float As[BK][BM];
    __shared__ float Bs[BK][BN];
    int tid = threadIdx.x;
    int bm = blockIdx.y * BM, bn = blockIdx.x * BN;
    int tx = tid & 15, ty = tid >> 4;

    float acc[8][8];
    #pragma unroll
    for (int i = 0; i < 8; i++)
        #pragma unroll
        for (int j = 0; j < 8; j++) acc[i][j] = 0.f;

    int arow = tid >> 1, acol = (tid & 1) * 4;
    int brow = tid >> 5, bcol = (tid & 31) * 4;
    const float* Ag = A + (size_t)(bm + arow) * K + acol;
    const float* Bg = B + (size_t)brow * N + bn + bcol;

    for (int k0 = 0; k0 < K; k0 += BK) {
        float4 av = *(const float4*)(Ag + k0);
        float4 bv = *(const float4*)(Bg + (size_t)k0 * N);
        As[acol + 0][arow] = av.x;
        As[acol + 1][arow] = av.y;
        As[acol + 2][arow] = av.z;
        As[acol + 3][arow] = av.w;
        *(float4*)&Bs[brow][bcol] = bv;
        __syncthreads();
        #pragma unroll
        for (int k = 0; k < BK; k++) {
            float a[8], b[8];
            *(float4*)(a)     = *(const float4*)&As[k][ty * 8];
            *(float4*)(a + 4) = *(const float4*)&As[k][ty * 8 + 4];
            *(float4*)(b)     = *(const float4*)&Bs[k][tx * 8];
            *(float4*)(b + 4) = *(const float4*)&Bs[k][tx * 8 + 4];
            #pragma unroll
            for (int i = 0; i < 8; i++)
                #pragma unroll
                for (int j = 0; j < 8; j++)
                    acc[i][j] += a[i] * b[j];
        }
        __syncthreads();
    }

    #pragma unroll
    for (int i = 0; i < 8; i++) {
        int row = bm + ty * 8 + i;
        #pragma unroll
        for (int j = 0; j < 8; j++) {
            int col = bn + tx * 8 + j;
            float v = acc[i][j] + bias[col];
            if (GELU)  v = gelu_new(v);
            if (RESID) v += R[(size_t)row * N + col];
            C[(size_t)row * N + col] = v;
        }
    }
}

// ---------------- flash attention (fp32, causal) ----------------------------
// grid: (SEQ/64, NH, BATCH); block 256. Q tile = 64 rows, K/V tiles = 32 rows.
// thread t: q-row = t/4, dh segment = (t%4)*16 .. +15
__global__ __launch_bounds__(256)
void attn_kernel(const float* __restrict__ QKV, float* __restrict__ Z) {
    int qt = blockIdx.x, h = blockIdx.y, b = blockIdx.z;
    __shared__ float Qs[64][65];
    __shared__ float Ks[32][65];
    __shared__ float Vs[32][64];

    int tid  = threadIdx.x;
    int row  = tid >> 2;
    int cseg = tid & 3;
    int lane = tid & 31;
    int gbase = lane & ~3;

    const float scale = 0.125f;                          // 1/sqrt(64)
    const float* qbase = QKV + ((size_t)(b * SEQ + qt * 64)) * QKVN + h * DH;

    for (int i = tid; i < 64 * 64; i += 256) {
        int r = i >> 6, e = i & 63;
        Qs[r][e] = qbase[(size_t)r * QKVN + e] * scale;
    }

    float acc[16];
    #pragma unroll
    for (int i = 0; i < 16; i++) acc[i] = 0.f;
    float m = -1e30f, l = 0.f;
    int q_glob = qt * 64 + row;
    int ntiles = 2 * qt + 2;                             // 32-row K tiles

    for (int kt = 0; kt < ntiles; kt++) {
        const float* kbase = QKV + ((size_t)(b * SEQ + kt * 32)) * QKVN + DM     + h * DH;
        const float* vbase = QKV + ((size_t)(b * SEQ + kt * 32)) * QKVN + 2 * DM + h * DH;
        __syncthreads();
        for (int i = tid; i < 32 * 64; i += 256) {
            int r = i >> 6, e = i & 63;
            Ks[r][e] = kbase[(size_t)r * QKVN + e];
            Vs[r][e] = vbase[(size_t)r * QKVN + e];
        }
        __syncthreads();

        float s[8];
        #pragma unroll
        for (int j = 0; j < 8; j++) s[j] = 0.f;
        #pragma unroll 4
        for (int e = 0; e < 64; e++) {
            float qv = Qs[row][e];
            #pragma unroll
            for (int j = 0; j < 8; j++)
                s[j] += qv * Ks[cseg * 8 + j][e];
        }
        // causal mask
        #pragma unroll
        for (int j = 0; j < 8; j++) {
            int k_glob = kt * 32 + cseg * 8 + j;
            if (k_glob > q_glob) s[j] = -1e30f;
        }
        // tile max across 4 lanes in group
        float mt = s[0];
        #pragma unroll
        for (int j = 1; j < 8; j++) mt = fmaxf(mt, s[j]);
        mt = fmaxf(mt, __shfl_xor_sync(0xffffffffu, mt, 1));
        mt = fmaxf(mt, __shfl_xor_sync(0xffffffffu, mt, 2));

        float mnew = fmaxf(m, mt);
        float corr = __expf(m - mnew);
        float lsum = 0.f;
        #pragma unroll
        for (int j = 0; j < 8; j++) {
            s[j] = __expf(s[j] - mnew);
            lsum += s[j];
        }
        lsum += __shfl_xor_sync(0xffffffffu, lsum, 1);
        lsum += __shfl_xor_sync(0xffffffffu, lsum, 2);
        l = l * corr + lsum;
        m = mnew;
        #pragma unroll
        for (int i = 0; i < 16; i++) acc[i] *= corr;

        #pragma unroll
        for (int k = 0; k < 32; k++) {
            float pk = __shfl_sync(0xffffffffu, s[k & 7], gbase + (k >> 3));
            const float4* vp = (const float4*)&Vs[k][cseg * 16];
            float4 v0 = vp[0], v1 = vp[1], v2 = vp[2], v3 = vp[3];
            acc[0]  += pk * v0.x; acc[1]  += pk * v0.y; acc[2]  += pk * v0.z; acc[3]  += pk * v0.w;
            acc[4]  += pk * v1.x; acc[5]  += pk * v1.y; acc[6]  += pk * v1.z; acc[7]  += pk * v1.w;
            acc[8]  += pk * v2.x; acc[9]  += pk * v2.y; acc[10] += pk * v2.z; acc[11] += pk * v2.w;
            acc[12] += pk * v3.x; acc[13] += pk * v3.y; acc[14] += pk * v3.z; acc[15] += pk * v3.w;
        }
    }

    float invl = 1.f / l;
    float* zp = Z + ((size_t)(b * SEQ + q_glob)) * DM + h * DH + cseg * 16;
    #pragma unroll
    for (int i = 0; i < 16; i++) zp[i] = acc[i] * invl;
}

// ---------------- launch -----------------------------------------------------
extern "C" void kernel_launch(void* const* d_in, const int* in_sizes, int n_in,
                              void* d_out, int out_size) {
    const float* resid_pre = (const float*)d_in[0];
    const float* W_Q   = (const float*)d_in[1];
    const float* b_Q   = (const float*)d_in[2];
    const float* W_K   = (const float*)d_in[3];
    const float* b_K   = (const float*)d_in[4];
    const float* W_V   = (const float*)d_in[5];
    const float* b_V   = (const float*)d_in[6];
    const float* W_O   = (const float*)d_in[7];
    const float* b_O   = (const float*)d_in[8];
    const float* ln1_w = (const float*)d_in[9];
    const float* ln1_b = (const float*)d_in[10];
    const float* ln2_w = (const float*)d_in[11];
    const float* ln2_b = (const float*)d_in[12];
    const float* W_in  = (const float*)d_in[13];
    const float* b_in  = (const float*)d_in[14];
    const float* W_out = (const float*)d_in[15];
    const float* b_out = (const float*)d_in[16];
    float* out = (float*)d_out;

    float *px, *pwqkv, *pbqkv, *pqkv, *pz, *pmid, *py, *ph;
    cudaGetSymbolAddress((void**)&px,    g_x);
    cudaGetSymbolAddress((void**)&pwqkv, g_wqkv);
    cudaGetSymbolAddress((void**)&pbqkv, g_bqkv);
    cudaGetSymbolAddress((void**)&pqkv,  g_qkv);
    cudaGetSymbolAddress((void**)&pz,    g_z);
    cudaGetSymbolAddress((void**)&pmid,  g_mid);
    cudaGetSymbolAddress((void**)&py,    g_y);
    cudaGetSymbolAddress((void**)&ph,    g_h);

    // 1) repack QKV weights
    pack_qkv<<<(DM * DM + 255) / 256, 256>>>(W_Q, W_K, W_V, b_Q, b_K, b_V, pwqkv, pbqkv);
    // 2) ln1
    ln_kernel<<<ROWS, 256>>>(resid_pre, ln1_w, ln1_b, px);
    // 3) QKV projection: [4096 x 768] @ [768 x 2304]
    gemm_kernel<false, false><<<dim3(QKVN / 128, ROWS / 128), 256>>>(
        px, pwqkv, pbqkv, nullptr, pqkv, ROWS, QKVN, DM);
    // 4) attention
    attn_kernel<<<dim3(SEQ / 64, NH, BATCH), 256>>>(pqkv, pz);
    // 5) O projection + residual -> resid_mid
    gemm_kernel<false, true><<<dim3(DM / 128, ROWS / 128), 256>>>(
        pz, W_O, b_O, resid_pre, pmid, ROWS, DM, DM);
    // 6) ln2
    ln_kernel<<<ROWS, 256>>>(pmid, ln2_w, ln2_b, py);
    // 7) MLP in + gelu
    gemm_kernel<true, false><<<dim3(DMLP / 128, ROWS / 128), 256>>>(
        py, W_in, b_in, nullptr, ph, ROWS, DMLP, DM);
    // 8) MLP out + residual -> output
    gemm_kernel<false, true><<<dim3(DM / 128, ROWS / 128), 256>>>(
        ph, W_out, b_out, pmid, out, ROWS, DM, DMLP);
}

// round 3
// speedup vs baseline: 1.4819x; 1.4819x over previous
#include <cuda_runtime.h>
#include <cstdint>
#include <math.h>

#define DM    768
#define DMLP  3072
#define NH    12
#define DH    64
#define BATCH 2
#define SEQ   2048
#define ROWS  (BATCH*SEQ)     /* 4096 */
#define QKVN  (3*DM)          /* 2304 */

// ---------------- scratch (static device globals; no allocation) -----------
__device__ float g_x    [ROWS*DM];      // ln1 output (tf32-rounded)
__device__ float g_wqkvT[QKVN*DM];      // packed QKV weight, [N=2304, K=768] (tf32)
__device__ float g_bqkv [QKVN];
__device__ float g_woT  [DM*DM];        // W_O^T   [768, 768]  (tf32)
__device__ float g_winT [DMLP*DM];      // W_in^T  [3072, 768] (tf32)
__device__ float g_woutT[DM*DMLP];      // W_out^T [768, 3072] (tf32)
__device__ float g_qkv  [ROWS*QKVN];    // Q|K|V per token (fp32)
__device__ float g_z    [ROWS*DM];      // attention output (tf32-rounded)
__device__ float g_mid  [ROWS*DM];      // resid_mid (fp32)
__device__ float g_y    [ROWS*DM];      // ln2 output (tf32-rounded)
__device__ float g_h    [ROWS*DMLP];    // MLP hidden (tf32-rounded)

// ======================= helpers ============================================
__device__ __forceinline__ uint32_t smem_u32(const void* p) {
    uint32_t a;
    asm("{ .reg .u64 t; cvta.to.shared.u64 t, %1; cvt.u32.u64 %0, t; }"
        : "=r"(a) : "l"(p));
    return a;
}
__device__ __forceinline__ float to_tf32(float x) {
    uint32_t u;
    asm("cvt.rna.tf32.f32 %0, %1;" : "=r"(u) : "f"(x));
    return __uint_as_float(u);
}
__device__ __forceinline__ float gelu_new(float v) {
    float v3 = v * v * v;
    return 0.5f * v * (1.f + tanhf(0.7978845608028654f * (v + 0.044715f * v3)));
}
#define CP_ASYNC16(sa, gp) \
    asm volatile("cp.async.cg.shared.global [%0], [%1], 16;" :: "r"(sa), "l"(gp))
#define CP_COMMIT() asm volatile("cp.async.commit_group;" ::: "memory")
#define CP_WAIT(n)  asm volatile("cp.async.wait_group %0;" :: "n"(n) : "memory")

__device__ __forceinline__ void mma_tf32(float* c, uint32_t a0, uint32_t a1,
                                         uint32_t a2, uint32_t a3,
                                         uint32_t b0, uint32_t b1) {
    asm volatile(
        "mma.sync.aligned.m16n8k8.row.col.f32.tf32.tf32.f32 "
        "{%0,%1,%2,%3}, {%4,%5,%6,%7}, {%8,%9}, {%0,%1,%2,%3};\n"
        : "+f"(c[0]), "+f"(c[1]), "+f"(c[2]), "+f"(c[3])
        : "r"(a0), "r"(a1), "r"(a2), "r"(a3), "r"(b0), "r"(b1));
}

// ================= tf32 mma.sync GEMM: C[M,N] = A[M,K] @ Bt[N,K]^T ==========
// BM=BN=128, BK=32, 256 threads = 8 warps (4 M x 2 N), warp tile 32x64.
// Smem rows padded to 36 floats (144 B) -> conflict-free fragment LDS.
// EPI: 0 = bias, 1 = bias+gelu(tf32 out), 2 = bias+residual
#define LDA 36
#define STAGE_FLOATS (2*128*LDA)          /* A + B per stage = 9216 floats */
#define GEMM_SMEM (2*STAGE_FLOATS*4)      /* 73728 bytes */

template<int EPI>
__global__ __launch_bounds__(256)
void gemm_mma(const float* __restrict__ A, const float* __restrict__ Bt,
              const float* __restrict__ bias, const float* __restrict__ R,
              float* __restrict__ C, int M, int N, int K) {
    extern __shared__ float sm[];
    const uint32_t sbase = smem_u32(sm);
    const int tid = threadIdx.x, lane = tid & 31, wid = tid >> 5;
    const int wm = wid & 3, wn = wid >> 2;
    const int bm = blockIdx.y * 128, bn = blockIdx.x * 128;
    const int niter = K >> 5;

    // per-thread load slots: 4 chunks A + 4 chunks B (16B each)
    int crow[4], cj[4];
    #pragma unroll
    for (int t = 0; t < 4; t++) {
        int c = tid + t * 256;
        crow[t] = c >> 3;
        cj[t]   = c & 7;
    }

    float acc[2][8][4];
    #pragma unroll
    for (int mi = 0; mi < 2; mi++)
        #pragma unroll
        for (int nj = 0; nj < 8; nj++)
            #pragma unroll
            for (int r = 0; r < 4; r++) acc[mi][nj][r] = 0.f;

    // prefetch tile 0 into stage 0
    {
        const int k0 = 0;
        #pragma unroll
        for (int t = 0; t < 4; t++) {
            uint32_t sa = sbase + (uint32_t)(crow[t] * 144 + cj[t] * 16);
            CP_ASYNC16(sa, A + (size_t)(bm + crow[t]) * K + k0 + cj[t] * 4);
            CP_ASYNC16(sa + 128u * LDA * 4u,
                       Bt + (size_t)(bn + crow[t]) * K + k0 + cj[t] * 4);
        }
        CP_COMMIT();
    }

    for (int i = 0; i < niter; i++) {
        if (i + 1 < niter) {
            const int k0 = (i + 1) << 5;
            const uint32_t stOff = (uint32_t)(((i + 1) & 1) * STAGE_FLOATS * 4);
            #pragma unroll
            for (int t = 0; t < 4; t++) {
                uint32_t sa = sbase + stOff + (uint32_t)(crow[t] * 144 + cj[t] * 16);
                CP_ASYNC16(sa, A + (size_t)(bm + crow[t]) * K + k0 + cj[t] * 4);
                CP_ASYNC16(sa + 128u * LDA * 4u,
                           Bt + (size_t)(bn + crow[t]) * K + k0 + cj[t] * 4);
            }
            CP_COMMIT();
            CP_WAIT(1);
        } else {
            CP_WAIT(0);
        }
        __syncthreads();

        const uint32_t* As = (const uint32_t*)(sm + (i & 1) * STAGE_FLOATS);
        const uint32_t* Bs = As + 128 * LDA;
        const int ar0 = wm * 32 + (lane >> 2);
        const int br0 = wn * 64 + (lane >> 2);
        const int kc  = lane & 3;

        #pragma unroll
        for (int kk = 0; kk < 32; kk += 8) {
            uint32_t a[2][4];
            #pragma unroll
            for (int mi = 0; mi < 2; mi++) {
                const uint32_t* ap = As + (ar0 + mi * 16) * LDA + kk + kc;
                a[mi][0] = ap[0];
                a[mi][1] = ap[8 * LDA];
                a[mi][2] = ap[4];
                a[mi][3] = ap[8 * LDA + 4];
            }
            #pragma unroll
            for (int nj = 0; nj < 8; nj++) {
                const uint32_t* bp = Bs + (br0 + nj * 8) * LDA + kk + kc;
                uint32_t b0 = bp[0], b1 = bp[4];
                #pragma unroll
                for (int mi = 0; mi < 2; mi++)
                    mma_tf32(acc[mi][nj], a[mi][0], a[mi][1], a[mi][2], a[mi][3], b0, b1);
            }
        }
        __syncthreads();
    }

    // ---- epilogue ----
    #pragma unroll
    for (int mi = 0; mi < 2; mi++) {
        const int row0 = bm + wm * 32 + mi * 16 + (lane >> 2);
        #pragma unroll
        for (int nj = 0; nj < 8; nj++) {
            const int col0 = bn + wn * 64 + nj * 8 + (lane & 3) * 2;
            const float b0 = bias[col0], b1 = bias[col0 + 1];
            #pragma unroll
            for (int h = 0; h < 2; h++) {                 // h=0 -> row0, h=1 -> row0+8
                const int row = row0 + h * 8;
                float v0 = acc[mi][nj][h * 2 + 0] + b0;
                float v1 = acc[mi][nj][h * 2 + 1] + b1;
                if (EPI == 1) { v0 = to_tf32(gelu_new(v0)); v1 = to_tf32(gelu_new(v1)); }
                size_t g = (size_t)row * N + col0;
                if (EPI == 2) {
                    float2 rv = *(const float2*)(R + g);
                    v0 += rv.x; v1 += rv.y;
                }
                float2 o; o.x = v0; o.y = v1;
                *(float2*)(C + g) = o;
            }
        }
    }
}

// ---------------- layernorm (tf32-rounded output) ----------------------------
__global__ __launch_bounds__(256)
void ln_kernel(const float* __restrict__ in, const float* __restrict__ w,
               const float* __restrict__ b, float* __restrict__ out) {
    int row = blockIdx.x;
    const float* x = in + (size_t)row * DM;
    float s = 0.f, ss = 0.f;
    for (int i = threadIdx.x; i < DM; i += 256) {
        float v = x[i]; s += v; ss += v * v;
    }
    __shared__ float red0[32], red1[32];
    #pragma unroll
    for (int o = 16; o; o >>= 1) {
        s  += __shfl_xor_sync(0xffffffffu, s,  o);
        ss += __shfl_xor_sync(0xffffffffu, ss, o);
    }
    int warp = threadIdx.x >> 5, lane = threadIdx.x & 31;
    if (lane == 0) { red0[warp] = s; red1[warp] = ss; }
    __syncthreads();
    if (warp == 0) {
        s  = (lane < 8) ? red0[lane] : 0.f;
        ss = (lane < 8) ? red1[lane] : 0.f;
        #pragma unroll
        for (int o = 4; o; o >>= 1) {
            s  += __shfl_xor_sync(0xffffffffu, s,  o);
            ss += __shfl_xor_sync(0xffffffffu, ss, o);
        }
        if (lane == 0) {
            float mean = s / DM;
            float var  = ss / DM - mean * mean;
            red0[0] = mean;
            red1[0] = rsqrtf(var + 1e-5f);
        }
    }
    __syncthreads();
    float mean = red0[0], inv = red1[0];
    for (int i = threadIdx.x; i < DM; i += 256)
        out[(size_t)row * DM + i] = to_tf32((x[i] - mean) * inv * w[i] + b[i]);
}

// ---------------- weight repacks (transposed to [N,K], tf32) ----------------
__global__ void pack_qkv_t(const float* __restrict__ WQ, const float* __restrict__ WK,
                           const float* __restrict__ WV,
                           const float* __restrict__ bQ, const float* __restrict__ bK,
                           const float* __restrict__ bV,
                           float* __restrict__ Wt, float* __restrict__ bias) {
    int idx = blockIdx.x * 256 + threadIdx.x;       // over 768*768
    if (idx < DM * DM) {
        int cc = idx / DM;     // output column (h*64+e)
        int k  = idx % DM;
        int h = cc >> 6, e = cc & 63;
        int src = h * (DM * DH) + k * DH + e;
        Wt[(size_t)cc * DM + k]            = to_tf32(WQ[src]);
        Wt[(size_t)(DM + cc) * DM + k]     = to_tf32(WK[src]);
        Wt[(size_t)(2 * DM + cc) * DM + k] = to_tf32(WV[src]);
    }
    if (idx < DM) {
        bias[idx]          = bQ[idx];
        bias[DM + idx]     = bK[idx];
        bias[2 * DM + idx] = bV[idx];
    }
}

__global__ void transpose_k(const float* __restrict__ in, float* __restrict__ out,
                            int Rr, int Cc) {   // in [Rr,Cc] -> out [Cc,Rr], tf32
    int idx = blockIdx.x * 256 + threadIdx.x;
    if (idx < Rr * Cc) {
        int r = idx % Rr;
        int c = idx / Rr;
        out[(size_t)c * Rr + r] = to_tf32(in[(size_t)r * Cc + c]);
    }
}

// ---------------- flash attention (fp32, causal) ----------------------------
__global__ __launch_bounds__(256)
void attn_kernel(const float* __restrict__ QKV, float* __restrict__ Z) {
    int qt = blockIdx.x, h = blockIdx.y, b = blockIdx.z;
    __shared__ float Qs[64][65];
    __shared__ float Ks[32][65];
    __shared__ float Vs[32][64];

    int tid  = threadIdx.x;
    int row  = tid >> 2;
    int cseg = tid & 3;
    int lane = tid & 31;
    int gbase = lane & ~3;

    const float scale = 0.125f;
    const float* qbase = QKV + ((size_t)(b * SEQ + qt * 64)) * QKVN + h * DH;

    for (int i = tid; i < 64 * 64; i += 256) {
        int r = i >> 6, e = i & 63;
        Qs[r][e] = qbase[(size_t)r * QKVN + e] * scale;
    }

    float acc[16];
    #pragma unroll
    for (int i = 0; i < 16; i++) acc[i] = 0.f;
    float m = -1e30f, l = 0.f;
    int q_glob = qt * 64 + row;
    int ntiles = 2 * qt + 2;

    for (int kt = 0; kt < ntiles; kt++) {
        const float* kbase = QKV + ((size_t)(b * SEQ + kt * 32)) * QKVN + DM     + h * DH;
        const float* vbase = QKV + ((size_t)(b * SEQ + kt * 32)) * QKVN + 2 * DM + h * DH;
        __syncthreads();
        for (int i = tid; i < 32 * 64; i += 256) {
            int r = i >> 6, e = i & 63;
            Ks[r][e] = kbase[(size_t)r * QKVN + e];
            Vs[r][e] = vbase[(size_t)r * QKVN + e];
        }
        __syncthreads();

        float s[8];
        #pragma unroll
        for (int j = 0; j < 8; j++) s[j] = 0.f;
        #pragma unroll 4
        for (int e = 0; e < 64; e++) {
            float qv = Qs[row][e];
            #pragma unroll
            for (int j = 0; j < 8; j++)
                s[j] += qv * Ks[cseg * 8 + j][e];
        }
        #pragma unroll
        for (int j = 0; j < 8; j++) {
            int k_glob = kt * 32 + cseg * 8 + j;
            if (k_glob > q_glob) s[j] = -1e30f;
        }
        float mt = s[0];
        #pragma unroll
        for (int j = 1; j < 8; j++) mt = fmaxf(mt, s[j]);
        mt = fmaxf(mt, __shfl_xor_sync(0xffffffffu, mt, 1));
        mt = fmaxf(mt, __shfl_xor_sync(0xffffffffu, mt, 2));

        float mnew = fmaxf(m, mt);
        float corr = __expf(m - mnew);
        float lsum = 0.f;
        #pragma unroll
        for (int j = 0; j < 8; j++) {
            s[j] = __expf(s[j] - mnew);
            lsum += s[j];
        }
        lsum += __shfl_xor_sync(0xffffffffu, lsum, 1);
        lsum += __shfl_xor_sync(0xffffffffu, lsum, 2);
        l = l * corr + lsum;
        m = mnew;
        #pragma unroll
        for (int i = 0; i < 16; i++) acc[i] *= corr;

        #pragma unroll
        for (int k = 0; k < 32; k++) {
            float pk = __shfl_sync(0xffffffffu, s[k & 7], gbase + (k >> 3));
            const float4* vp = (const float4*)&Vs[k][cseg * 16];
            float4 v0 = vp[0], v1 = vp[1], v2 = vp[2], v3 = vp[3];
            acc[0]  += pk * v0.x; acc[1]  += pk * v0.y; acc[2]  += pk * v0.z; acc[3]  += pk * v0.w;
            acc[4]  += pk * v1.x; acc[5]  += pk * v1.y; acc[6]  += pk * v1.z; acc[7]  += pk * v1.w;
            acc[8]  += pk * v2.x; acc[9]  += pk * v2.y; acc[10] += pk * v2.z; acc[11] += pk * v2.w;
            acc[12] += pk * v3.x; acc[13] += pk * v3.y; acc[14] += pk * v3.z; acc[15] += pk * v3.w;
        }
    }

    float invl = 1.f / l;
    float* zp = Z + ((size_t)(b * SEQ + q_glob)) * DM + h * DH + cseg * 16;
    #pragma unroll
    for (int i = 0; i < 16; i++) zp[i] = to_tf32(acc[i] * invl);
}

// ---------------- launch -----------------------------------------------------
extern "C" void kernel_launch(void* const* d_in, const int* in_sizes, int n_in,
                              void* d_out, int out_size) {
    const float* resid_pre = (const float*)d_in[0];
    const float* W_Q   = (const float*)d_in[1];
    const float* b_Q   = (const float*)d_in[2];
    const float* W_K   = (const float*)d_in[3];
    const float* b_K   = (const float*)d_in[4];
    const float* W_V   = (const float*)d_in[5];
    const float* b_V   = (const float*)d_in[6];
    const float* W_O   = (const float*)d_in[7];
    const float* b_O   = (const float*)d_in[8];
    const float* ln1_w = (const float*)d_in[9];
    const float* ln1_b = (const float*)d_in[10];
    const float* ln2_w = (const float*)d_in[11];
    const float* ln2_b = (const float*)d_in[12];
    const float* W_in  = (const float*)d_in[13];
    const float* b_in  = (const float*)d_in[14];
    const float* W_out = (const float*)d_in[15];
    const float* b_out = (const float*)d_in[16];
    float* out = (float*)d_out;

    float *px, *pwqkvT, *pbqkv, *pwoT, *pwinT, *pwoutT, *pqkv, *pz, *pmid, *py, *ph;
    cudaGetSymbolAddress((void**)&px,     g_x);
    cudaGetSymbolAddress((void**)&pwqkvT, g_wqkvT);
    cudaGetSymbolAddress((void**)&pbqkv,  g_bqkv);
    cudaGetSymbolAddress((void**)&pwoT,   g_woT);
    cudaGetSymbolAddress((void**)&pwinT,  g_winT);
    cudaGetSymbolAddress((void**)&pwoutT, g_woutT);
    cudaGetSymbolAddress((void**)&pqkv,   g_qkv);
    cudaGetSymbolAddress((void**)&pz,     g_z);
    cudaGetSymbolAddress((void**)&pmid,   g_mid);
    cudaGetSymbolAddress((void**)&py,     g_y);
    cudaGetSymbolAddress((void**)&ph,     g_h);

    cudaFuncSetAttribute(gemm_mma<0>, cudaFuncAttributeMaxDynamicSharedMemorySize, GEMM_SMEM);
    cudaFuncSetAttribute(gemm_mma<1>, cudaFuncAttributeMaxDynamicSharedMemorySize, GEMM_SMEM);
    cudaFuncSetAttribute(gemm_mma<2>, cudaFuncAttributeMaxDynamicSharedMemorySize, GEMM_SMEM);

    // weight repacks ([N,K] + tf32 rounding)
    pack_qkv_t<<<(DM * DM + 255) / 256, 256>>>(W_Q, W_K, W_V, b_Q, b_K, b_V, pwqkvT, pbqkv);
    transpose_k<<<(DM * DM + 255) / 256, 256>>>(W_O, pwoT, DM, DM);
    transpose_k<<<(DM * DMLP + 255) / 256, 256>>>(W_in, pwinT, DM, DMLP);
    transpose_k<<<(DMLP * DM + 255) / 256, 256>>>(W_out, pwoutT, DMLP, DM);

    // ln1
    ln_kernel<<<ROWS, 256>>>(resid_pre, ln1_w, ln1_b, px);
    // QKV projection: [4096 x 768] @ [768 x 2304]
    gemm_mma<0><<<dim3(QKVN / 128, ROWS / 128), 256, GEMM_SMEM>>>(
        px, pwqkvT, pbqkv, nullptr, pqkv, ROWS, QKVN, DM);
    // attention
    attn_kernel<<<dim3(SEQ / 64, NH, BATCH), 256>>>(pqkv, pz);
    // O projection + residual -> resid_mid
    gemm_mma<2><<<dim3(DM / 128, ROWS / 128), 256, GEMM_SMEM>>>(
        pz, pwoT, b_O, resid_pre, pmid, ROWS, DM, DM);
    // ln2
    ln_kernel<<<ROWS, 256>>>(pmid, ln2_w, ln2_b, py);
    // MLP in + gelu
    gemm_mma<1><<<dim3(DMLP / 128, ROWS / 128), 256, GEMM_SMEM>>>(
        py, pwinT, b_in, nullptr, ph, ROWS, DMLP, DM);
    // MLP out + residual -> output
    gemm_mma<2><<<dim3(DM / 128, ROWS / 128), 256, GEMM_SMEM>>>(
        ph, pwoutT, b_out, pmid, out, ROWS, DM, DMLP);
}

// round 4
// speedup vs baseline: 4.2515x; 2.8690x over previous
#include <cuda_runtime.h>
#include <cstdint>
#include <math.h>

#define DM    768
#define DMLP  3072
#define NH    12
#define DH    64
#define BATCH 2
#define SEQ   2048
#define ROWS  (BATCH*SEQ)     /* 4096 */
#define QKVN  (3*DM)          /* 2304 */

// ---------------- scratch (static device globals; no allocation) -----------
__device__ float g_x    [ROWS*DM];      // ln1 output (tf32-rounded)
__device__ float g_wqkvT[QKVN*DM];      // packed QKV weight, [N=2304, K=768] (tf32)
__device__ float g_bqkv [QKVN];
__device__ float g_woT  [DM*DM];        // W_O^T   [768, 768]  (tf32)
__device__ float g_winT [DMLP*DM];      // W_in^T  [3072, 768] (tf32)
__device__ float g_woutT[DM*DMLP];      // W_out^T [768, 3072] (tf32)
__device__ float g_qkv  [ROWS*QKVN];    // Q|K|V per token (fp32)
__device__ float g_z    [ROWS*DM];      // attention output (tf32-rounded)
__device__ float g_mid  [ROWS*DM];      // resid_mid (fp32)
__device__ float g_y    [ROWS*DM];      // ln2 output (tf32-rounded)
__device__ float g_h    [ROWS*DMLP];    // MLP hidden (tf32-rounded)

// ======================= helpers ============================================
__device__ __forceinline__ uint32_t smem_u32(const void* p) {
    uint32_t a;
    asm("{ .reg .u64 t; cvta.to.shared.u64 t, %1; cvt.u32.u64 %0, t; }"
        : "=r"(a) : "l"(p));
    return a;
}
__device__ __forceinline__ float to_tf32(float x) {
    uint32_t u;
    asm("cvt.rna.tf32.f32 %0, %1;" : "=r"(u) : "f"(x));
    return __uint_as_float(u);
}
__device__ __forceinline__ float gelu_new(float v) {
    float v3 = v * v * v;
    return 0.5f * v * (1.f + tanhf(0.7978845608028654f * (v + 0.044715f * v3)));
}
#define CP_ASYNC16(sa, gp) \
    asm volatile("cp.async.cg.shared.global [%0], [%1], 16;" :: "r"(sa), "l"(gp))
#define CP_COMMIT() asm volatile("cp.async.commit_group;" ::: "memory")
#define CP_WAIT(n)  asm volatile("cp.async.wait_group %0;" :: "n"(n) : "memory")

__device__ __forceinline__ void mma_tf32(float* c, uint32_t a0, uint32_t a1,
                                         uint32_t a2, uint32_t a3,
                                         uint32_t b0, uint32_t b1) {
    asm volatile(
        "mma.sync.aligned.m16n8k8.row.col.f32.tf32.tf32.f32 "
        "{%0,%1,%2,%3}, {%4,%5,%6,%7}, {%8,%9}, {%0,%1,%2,%3};\n"
        : "+f"(c[0]), "+f"(c[1]), "+f"(c[2]), "+f"(c[3])
        : "r"(a0), "r"(a1), "r"(a2), "r"(a3), "r"(b0), "r"(b1));
}

// ================= tf32 mma.sync GEMM: C[M,N] = A[M,K] @ Bt[N,K]^T ==========
#define LDA 36
#define STAGE_FLOATS (2*128*LDA)
#define GEMM_SMEM (2*STAGE_FLOATS*4)

template<int EPI>
__global__ __launch_bounds__(256)
void gemm_mma(const float* __restrict__ A, const float* __restrict__ Bt,
              const float* __restrict__ bias, const float* __restrict__ R,
              float* __restrict__ C, int M, int N, int K) {
    extern __shared__ float sm[];
    const uint32_t sbase = smem_u32(sm);
    const int tid = threadIdx.x, lane = tid & 31, wid = tid >> 5;
    const int wm = wid & 3, wn = wid >> 2;
    const int bm = blockIdx.y * 128, bn = blockIdx.x * 128;
    const int niter = K >> 5;

    int crow[4], cj[4];
    #pragma unroll
    for (int t = 0; t < 4; t++) {
        int c = tid + t * 256;
        crow[t] = c >> 3;
        cj[t]   = c & 7;
    }

    float acc[2][8][4];
    #pragma unroll
    for (int mi = 0; mi < 2; mi++)
        #pragma unroll
        for (int nj = 0; nj < 8; nj++)
            #pragma unroll
            for (int r = 0; r < 4; r++) acc[mi][nj][r] = 0.f;

    {
        #pragma unroll
        for (int t = 0; t < 4; t++) {
            uint32_t sa = sbase + (uint32_t)(crow[t] * 144 + cj[t] * 16);
            CP_ASYNC16(sa, A + (size_t)(bm + crow[t]) * K + cj[t] * 4);
            CP_ASYNC16(sa + 128u * LDA * 4u,
                       Bt + (size_t)(bn + crow[t]) * K + cj[t] * 4);
        }
        CP_COMMIT();
    }

    for (int i = 0; i < niter; i++) {
        if (i + 1 < niter) {
            const int k0 = (i + 1) << 5;
            const uint32_t stOff = (uint32_t)(((i + 1) & 1) * STAGE_FLOATS * 4);
            #pragma unroll
            for (int t = 0; t < 4; t++) {
                uint32_t sa = sbase + stOff + (uint32_t)(crow[t] * 144 + cj[t] * 16);
                CP_ASYNC16(sa, A + (size_t)(bm + crow[t]) * K + k0 + cj[t] * 4);
                CP_ASYNC16(sa + 128u * LDA * 4u,
                           Bt + (size_t)(bn + crow[t]) * K + k0 + cj[t] * 4);
            }
            CP_COMMIT();
            CP_WAIT(1);
        } else {
            CP_WAIT(0);
        }
        __syncthreads();

        const uint32_t* As = (const uint32_t*)(sm + (i & 1) * STAGE_FLOATS);
        const uint32_t* Bs = As + 128 * LDA;
        const int ar0 = wm * 32 + (lane >> 2);
        const int br0 = wn * 64 + (lane >> 2);
        const int kc  = lane & 3;

        #pragma unroll
        for (int kk = 0; kk < 32; kk += 8) {
            uint32_t a[2][4];
            #pragma unroll
            for (int mi = 0; mi < 2; mi++) {
                const uint32_t* ap = As + (ar0 + mi * 16) * LDA + kk + kc;
                a[mi][0] = ap[0];
                a[mi][1] = ap[8 * LDA];
                a[mi][2] = ap[4];
                a[mi][3] = ap[8 * LDA + 4];
            }
            #pragma unroll
            for (int nj = 0; nj < 8; nj++) {
                const uint32_t* bp = Bs + (br0 + nj * 8) * LDA + kk + kc;
                uint32_t b0 = bp[0], b1 = bp[4];
                #pragma unroll
                for (int mi = 0; mi < 2; mi++)
                    mma_tf32(acc[mi][nj], a[mi][0], a[mi][1], a[mi][2], a[mi][3], b0, b1);
            }
        }
        __syncthreads();
    }

    #pragma unroll
    for (int mi = 0; mi < 2; mi++) {
        const int row0 = bm + wm * 32 + mi * 16 + (lane >> 2);
        #pragma unroll
        for (int nj = 0; nj < 8; nj++) {
            const int col0 = bn + wn * 64 + nj * 8 + (lane & 3) * 2;
            const float b0 = bias[col0], b1 = bias[col0 + 1];
            #pragma unroll
            for (int h = 0; h < 2; h++) {
                const int row = row0 + h * 8;
                float v0 = acc[mi][nj][h * 2 + 0] + b0;
                float v1 = acc[mi][nj][h * 2 + 1] + b1;
                if (EPI == 1) { v0 = to_tf32(gelu_new(v0)); v1 = to_tf32(gelu_new(v1)); }
                size_t g = (size_t)row * N + col0;
                if (EPI == 2) {
                    float2 rv = *(const float2*)(R + g);
                    v0 += rv.x; v1 += rv.y;
                }
                float2 o; o.x = v0; o.y = v1;
                *(float2*)(C + g) = o;
            }
        }
    }
}

// ---------------- layernorm (tf32-rounded output) ----------------------------
__global__ __launch_bounds__(256)
void ln_kernel(const float* __restrict__ in, const float* __restrict__ w,
               const float* __restrict__ b, float* __restrict__ out) {
    int row = blockIdx.x;
    const float* x = in + (size_t)row * DM;
    float s = 0.f, ss = 0.f;
    for (int i = threadIdx.x; i < DM; i += 256) {
        float v = x[i]; s += v; ss += v * v;
    }
    __shared__ float red0[32], red1[32];
    #pragma unroll
    for (int o = 16; o; o >>= 1) {
        s  += __shfl_xor_sync(0xffffffffu, s,  o);
        ss += __shfl_xor_sync(0xffffffffu, ss, o);
    }
    int warp = threadIdx.x >> 5, lane = threadIdx.x & 31;
    if (lane == 0) { red0[warp] = s; red1[warp] = ss; }
    __syncthreads();
    if (warp == 0) {
        s  = (lane < 8) ? red0[lane] : 0.f;
        ss = (lane < 8) ? red1[lane] : 0.f;
        #pragma unroll
        for (int o = 4; o; o >>= 1) {
            s  += __shfl_xor_sync(0xffffffffu, s,  o);
            ss += __shfl_xor_sync(0xffffffffu, ss, o);
        }
        if (lane == 0) {
            float mean = s / DM;
            float var  = ss / DM - mean * mean;
            red0[0] = mean;
            red1[0] = rsqrtf(var + 1e-5f);
        }
    }
    __syncthreads();
    float mean = red0[0], inv = red1[0];
    for (int i = threadIdx.x; i < DM; i += 256)
        out[(size_t)row * DM + i] = to_tf32((x[i] - mean) * inv * w[i] + b[i]);
}

// ---------------- weight repacks (transposed to [N,K], tf32) ----------------
__global__ void pack_qkv_t(const float* __restrict__ WQ, const float* __restrict__ WK,
                           const float* __restrict__ WV,
                           const float* __restrict__ bQ, const float* __restrict__ bK,
                           const float* __restrict__ bV,
                           float* __restrict__ Wt, float* __restrict__ bias) {
    int idx = blockIdx.x * 256 + threadIdx.x;
    if (idx < DM * DM) {
        int cc = idx / DM;
        int k  = idx % DM;
        int h = cc >> 6, e = cc & 63;
        int src = h * (DM * DH) + k * DH + e;
        Wt[(size_t)cc * DM + k]            = to_tf32(WQ[src]);
        Wt[(size_t)(DM + cc) * DM + k]     = to_tf32(WK[src]);
        Wt[(size_t)(2 * DM + cc) * DM + k] = to_tf32(WV[src]);
    }
    if (idx < DM) {
        bias[idx]          = bQ[idx];
        bias[DM + idx]     = bK[idx];
        bias[2 * DM + idx] = bV[idx];
    }
}

__global__ void transpose_k(const float* __restrict__ in, float* __restrict__ out,
                            int Rr, int Cc) {
    int idx = blockIdx.x * 256 + threadIdx.x;
    if (idx < Rr * Cc) {
        int r = idx % Rr;
        int c = idx / Rr;
        out[(size_t)c * Rr + r] = to_tf32(in[(size_t)r * Cc + c]);
    }
}

// ============== flash attention via tf32 mma.sync (causal) ==================
// CTA: 256 thr / 8 warps. Q tile = 128 rows (16/warp). K/V tile = 64 keys.
// Smem: Ks[64][68] (K [key][e]), Vt[64][68] (V^T [e][key]),
//       QP[128][68]: Q staging at start, then per-warp P staging [16][68].
#define LDK 68
#define ATTN_SMEM ((2*64*LDK + 128*LDK) * 4)

__global__ __launch_bounds__(256)
void attn_mma(const float* __restrict__ QKV, float* __restrict__ Z) {
    extern __shared__ float sm[];
    float* Ks = sm;                 // 64*68
    float* Vt = sm + 64 * LDK;      // 64*68
    float* QP = sm + 2 * 64 * LDK;  // 128*68

    const int tid = threadIdx.x, lane = tid & 31, wid = tid >> 5;
    const int r = lane >> 2, c = lane & 3;
    const int qt0 = blockIdx.x * 128;
    const int h = blockIdx.y, b = blockIdx.z;

    // ---- load Q tile (scaled, tf32) then build A fragments
    const float* qbase = QKV + ((size_t)(b * SEQ + qt0)) * QKVN + h * DH;
    for (int i = tid; i < 128 * 64; i += 256) {
        int rr = i >> 6, e = i & 63;
        QP[rr * LDK + e] = to_tf32(qbase[(size_t)rr * QKVN + e] * 0.125f);
    }
    __syncthreads();
    uint32_t qf[8][4];
    {
        const uint32_t* Qw = (const uint32_t*)(QP + wid * 16 * LDK);
        #pragma unroll
        for (int kk = 0; kk < 8; kk++) {
            qf[kk][0] = Qw[r * LDK + kk * 8 + c];
            qf[kk][1] = Qw[(r + 8) * LDK + kk * 8 + c];
            qf[kk][2] = Qw[r * LDK + kk * 8 + c + 4];
            qf[kk][3] = Qw[(r + 8) * LDK + kk * 8 + c + 4];
        }
    }

    float o[8][4];
    #pragma unroll
    for (int nj = 0; nj < 8; nj++)
        #pragma unroll
        for (int t = 0; t < 4; t++) o[nj][t] = 0.f;
    float m0 = -1e30f, m1 = -1e30f, l0 = 0.f, l1 = 0.f;

    const int q0g = qt0 + wid * 16 + r;    // this thread's first q row
    const int qmax_warp = qt0 + wid * 16 + 15;
    const int ntiles = qt0 / 64 + 2;

    uint32_t* Pw = (uint32_t*)(QP + wid * 16 * LDK);

    for (int kt = 0; kt < ntiles; kt++) {
        __syncthreads();   // previous tile fully consumed (incl. Q frags on kt==0)
        const float* kb = QKV + ((size_t)(b * SEQ + kt * 64)) * QKVN + DM     + h * DH;
        const float* vb = QKV + ((size_t)(b * SEQ + kt * 64)) * QKVN + 2 * DM + h * DH;
        for (int i = tid; i < 64 * 64; i += 256) {
            int key = i >> 6, e = i & 63;
            Ks[key * LDK + e]  = to_tf32(kb[(size_t)key * QKVN + e]);
            Vt[e * LDK + key]  = to_tf32(vb[(size_t)key * QKVN + e]);
        }
        __syncthreads();

        if (kt * 64 > qmax_warp) continue;   // whole warp-tile above diagonal

        // ---- S = Q @ K^T  (per warp: 16 q x 64 k)
        float s[8][4];
        #pragma unroll
        for (int nj = 0; nj < 8; nj++)
            #pragma unroll
            for (int t = 0; t < 4; t++) s[nj][t] = 0.f;
        const uint32_t* Ksu = (const uint32_t*)Ks;
        #pragma unroll
        for (int kk = 0; kk < 8; kk++) {
            #pragma unroll
            for (int nj = 0; nj < 8; nj++) {
                const uint32_t* bp = Ksu + (nj * 8 + r) * LDK + kk * 8 + c;
                mma_tf32(s[nj], qf[kk][0], qf[kk][1], qf[kk][2], qf[kk][3],
                         bp[0], bp[4]);
            }
        }

        // ---- causal mask (only tiles crossing the diagonal)
        if (kt * 64 + 63 > qt0 + wid * 16) {
            #pragma unroll
            for (int nj = 0; nj < 8; nj++) {
                int k0c = kt * 64 + nj * 8 + c * 2;
                if (k0c     > q0g)     s[nj][0] = -1e30f;
                if (k0c + 1 > q0g)     s[nj][1] = -1e30f;
                if (k0c     > q0g + 8) s[nj][2] = -1e30f;
                if (k0c + 1 > q0g + 8) s[nj][3] = -1e30f;
            }
        }

        // ---- online softmax (rows q0g -> regs 0,1 ; q0g+8 -> regs 2,3)
        float mt0 = -1e30f, mt1 = -1e30f;
        #pragma unroll
        for (int nj = 0; nj < 8; nj++) {
            mt0 = fmaxf(mt0, fmaxf(s[nj][0], s[nj][1]));
            mt1 = fmaxf(mt1, fmaxf(s[nj][2], s[nj][3]));
        }
        mt0 = fmaxf(mt0, __shfl_xor_sync(0xffffffffu, mt0, 1));
        mt0 = fmaxf(mt0, __shfl_xor_sync(0xffffffffu, mt0, 2));
        mt1 = fmaxf(mt1, __shfl_xor_sync(0xffffffffu, mt1, 1));
        mt1 = fmaxf(mt1, __shfl_xor_sync(0xffffffffu, mt1, 2));

        float mn0 = fmaxf(m0, mt0), mn1 = fmaxf(m1, mt1);
        float cr0 = __expf(m0 - mn0), cr1 = __expf(m1 - mn1);
        float ls0 = 0.f, ls1 = 0.f;
        #pragma unroll
        for (int nj = 0; nj < 8; nj++) {
            s[nj][0] = __expf(s[nj][0] - mn0);
            s[nj][1] = __expf(s[nj][1] - mn0);
            s[nj][2] = __expf(s[nj][2] - mn1);
            s[nj][3] = __expf(s[nj][3] - mn1);
            ls0 += s[nj][0] + s[nj][1];
            ls1 += s[nj][2] + s[nj][3];
        }
        ls0 += __shfl_xor_sync(0xffffffffu, ls0, 1);
        ls0 += __shfl_xor_sync(0xffffffffu, ls0, 2);
        ls1 += __shfl_xor_sync(0xffffffffu, ls1, 1);
        ls1 += __shfl_xor_sync(0xffffffffu, ls1, 2);
        l0 = l0 * cr0 + ls0;
        l1 = l1 * cr1 + ls1;
        m0 = mn0; m1 = mn1;
        #pragma unroll
        for (int nj = 0; nj < 8; nj++) {
            o[nj][0] *= cr0; o[nj][1] *= cr0;
            o[nj][2] *= cr1; o[nj][3] *= cr1;
        }

        // ---- stage P (tf32) to per-warp smem, reload as A fragments
        #pragma unroll
        for (int nj = 0; nj < 8; nj++) {
            int colb = nj * 8 + c * 2;
            Pw[r * LDK + colb]           = __float_as_uint(to_tf32(s[nj][0]));
            Pw[r * LDK + colb + 1]       = __float_as_uint(to_tf32(s[nj][1]));
            Pw[(r + 8) * LDK + colb]     = __float_as_uint(to_tf32(s[nj][2]));
            Pw[(r + 8) * LDK + colb + 1] = __float_as_uint(to_tf32(s[nj][3]));
        }
        __syncwarp();

        // ---- O += P @ V  (V^T in smem: Vt[e][key])
        const uint32_t* Vtu = (const uint32_t*)Vt;
        #pragma unroll
        for (int kk = 0; kk < 8; kk++) {
            uint32_t a0 = Pw[r * LDK + kk * 8 + c];
            uint32_t a1 = Pw[(r + 8) * LDK + kk * 8 + c];
            uint32_t a2 = Pw[r * LDK + kk * 8 + c + 4];
            uint32_t a3 = Pw[(r + 8) * LDK + kk * 8 + c + 4];
            #pragma unroll
            for (int nj = 0; nj < 8; nj++) {
                const uint32_t* bp = Vtu + (nj * 8 + r) * LDK + kk * 8 + c;
                mma_tf32(o[nj], a0, a1, a2, a3, bp[0], bp[4]);
            }
        }
        __syncwarp();
    }

    // ---- epilogue: normalize + store (tf32 for next GEMM's A operand)
    float inv0 = 1.f / l0, inv1 = 1.f / l1;
    #pragma unroll
    for (int nj = 0; nj < 8; nj++) {
        int col = h * DH + nj * 8 + c * 2;
        size_t g0 = (size_t)(b * SEQ + q0g) * DM + col;
        size_t g1 = (size_t)(b * SEQ + q0g + 8) * DM + col;
        float2 v0, v1;
        v0.x = to_tf32(o[nj][0] * inv0); v0.y = to_tf32(o[nj][1] * inv0);
        v1.x = to_tf32(o[nj][2] * inv1); v1.y = to_tf32(o[nj][3] * inv1);
        *(float2*)(Z + g0) = v0;
        *(float2*)(Z + g1) = v1;
    }
}

// ---------------- launch -----------------------------------------------------
extern "C" void kernel_launch(void* const* d_in, const int* in_sizes, int n_in,
                              void* d_out, int out_size) {
    const float* resid_pre = (const float*)d_in[0];
    const float* W_Q   = (const float*)d_in[1];
    const float* b_Q   = (const float*)d_in[2];
    const float* W_K   = (const float*)d_in[3];
    const float* b_K   = (const float*)d_in[4];
    const float* W_V   = (const float*)d_in[5];
    const float* b_V   = (const float*)d_in[6];
    const float* W_O   = (const float*)d_in[7];
    const float* b_O   = (const float*)d_in[8];
    const float* ln1_w = (const float*)d_in[9];
    const float* ln1_b = (const float*)d_in[10];
    const float* ln2_w = (const float*)d_in[11];
    const float* ln2_b = (const float*)d_in[12];
    const float* W_in  = (const float*)d_in[13];
    const float* b_in  = (const float*)d_in[14];
    const float* W_out = (const float*)d_in[15];
    const float* b_out = (const float*)d_in[16];
    float* out = (float*)d_out;

    float *px, *pwqkvT, *pbqkv, *pwoT, *pwinT, *pwoutT, *pqkv, *pz, *pmid, *py, *ph;
    cudaGetSymbolAddress((void**)&px,     g_x);
    cudaGetSymbolAddress((void**)&pwqkvT, g_wqkvT);
    cudaGetSymbolAddress((void**)&pbqkv,  g_bqkv);
    cudaGetSymbolAddress((void**)&pwoT,   g_woT);
    cudaGetSymbolAddress((void**)&pwinT,  g_winT);
    cudaGetSymbolAddress((void**)&pwoutT, g_woutT);
    cudaGetSymbolAddress((void**)&pqkv,   g_qkv);
    cudaGetSymbolAddress((void**)&pz,     g_z);
    cudaGetSymbolAddress((void**)&pmid,   g_mid);
    cudaGetSymbolAddress((void**)&py,     g_y);
    cudaGetSymbolAddress((void**)&ph,     g_h);

    cudaFuncSetAttribute(gemm_mma<0>, cudaFuncAttributeMaxDynamicSharedMemorySize, GEMM_SMEM);
    cudaFuncSetAttribute(gemm_mma<1>, cudaFuncAttributeMaxDynamicSharedMemorySize, GEMM_SMEM);
    cudaFuncSetAttribute(gemm_mma<2>, cudaFuncAttributeMaxDynamicSharedMemorySize, GEMM_SMEM);
    cudaFuncSetAttribute(attn_mma,    cudaFuncAttributeMaxDynamicSharedMemorySize, ATTN_SMEM);

    pack_qkv_t<<<(DM * DM + 255) / 256, 256>>>(W_Q, W_K, W_V, b_Q, b_K, b_V, pwqkvT, pbqkv);
    transpose_k<<<(DM * DM + 255) / 256, 256>>>(W_O, pwoT, DM, DM);
    transpose_k<<<(DM * DMLP + 255) / 256, 256>>>(W_in, pwinT, DM, DMLP);
    transpose_k<<<(DMLP * DM + 255) / 256, 256>>>(W_out, pwoutT, DMLP, DM);

    ln_kernel<<<ROWS, 256>>>(resid_pre, ln1_w, ln1_b, px);
    gemm_mma<0><<<dim3(QKVN / 128, ROWS / 128), 256, GEMM_SMEM>>>(
        px, pwqkvT, pbqkv, nullptr, pqkv, ROWS, QKVN, DM);
    attn_mma<<<dim3(SEQ / 128, NH, BATCH), 256, ATTN_SMEM>>>(pqkv, pz);
    gemm_mma<2><<<dim3(DM / 128, ROWS / 128), 256, GEMM_SMEM>>>(
        pz, pwoT, b_O, resid_pre, pmid, ROWS, DM, DM);
    ln_kernel<<<ROWS, 256>>>(pmid, ln2_w, ln2_b, py);
    gemm_mma<1><<<dim3(DMLP / 128, ROWS / 128), 256, GEMM_SMEM>>>(
        py, pwinT, b_in, nullptr, ph, ROWS, DMLP, DM);
    gemm_mma<2><<<dim3(DM / 128, ROWS / 128), 256, GEMM_SMEM>>>(
        ph, pwoutT, b_out, pmid, out, ROWS, DM, DMLP);
}

// round 5
// speedup vs baseline: 4.8174x; 1.1331x over previous
#include <cuda_runtime.h>
#include <cstdint>
#include <math.h>

#define DM    768
#define DMLP  3072
#define NH    12
#define DH    64
#define BATCH 2
#define SEQ   2048
#define ROWS  (BATCH*SEQ)     /* 4096 */
#define QKVN  (3*DM)          /* 2304 */

// ---------------- scratch (static device globals; no allocation) -----------
__device__ float g_x    [ROWS*DM];      // ln1 output (tf32-rounded)
__device__ float g_wqkv [DM*QKVN];      // packed QKV weight, [K=768, N=2304]
__device__ float g_bqkv [QKVN];
__device__ float g_qkv  [ROWS*QKVN];    // Q|K|V per token
__device__ float g_z    [ROWS*DM];      // attention output (tf32-rounded)
__device__ float g_mid  [ROWS*DM];      // resid_mid (fp32)
__device__ float g_y    [ROWS*DM];      // ln2 output (tf32-rounded)
__device__ float g_h    [ROWS*DMLP];    // MLP hidden (tf32-rounded)

// ======================= helpers ============================================
__device__ __forceinline__ uint32_t smem_u32(const void* p) {
    uint32_t a;
    asm("{ .reg .u64 t; cvta.to.shared.u64 t, %1; cvt.u32.u64 %0, t; }"
        : "=r"(a) : "l"(p));
    return a;
}
__device__ __forceinline__ float to_tf32(float x) {
    uint32_t u;
    asm("cvt.rna.tf32.f32 %0, %1;" : "=r"(u) : "f"(x));
    return __uint_as_float(u);
}
__device__ __forceinline__ float gelu_new(float v) {
    float v3 = v * v * v;
    return 0.5f * v * (1.f + tanhf(0.7978845608028654f * (v + 0.044715f * v3)));
}
#define CP_ASYNC16(sa, gp) \
    asm volatile("cp.async.cg.shared.global [%0], [%1], 16;" :: "r"(sa), "l"(gp))
#define CP_COMMIT() asm volatile("cp.async.commit_group;" ::: "memory")
#define CP_WAIT(n)  asm volatile("cp.async.wait_group %0;" :: "n"(n) : "memory")

__device__ __forceinline__ void mma_tf32(float* c, uint32_t a0, uint32_t a1,
                                         uint32_t a2, uint32_t a3,
                                         uint32_t b0, uint32_t b1) {
    asm volatile(
        "mma.sync.aligned.m16n8k8.row.col.f32.tf32.tf32.f32 "
        "{%0,%1,%2,%3}, {%4,%5,%6,%7}, {%8,%9}, {%0,%1,%2,%3};\n"
        : "+f"(c[0]), "+f"(c[1]), "+f"(c[2]), "+f"(c[3])
        : "r"(a0), "r"(a1), "r"(a2), "r"(a3), "r"(b0), "r"(b1));
}

// ====== tf32 mma.sync GEMM: C[M,N] = A[M,K] @ B[K,N]   (B row-major!) =======
// BM=BN=128, BK=32, 256 thr / 8 warps (4M x 2N), warp tile 32x64.
// A smem [m][k] pad 36 (conflict-free A frags); B smem [k][n] pad 136
// (8*kc + r spans 0..31 -> conflict-free B frags). 3-stage cp.async pipeline,
// single __syncthreads per K-iter.
#define LDA 36
#define LDB 136
#define A_STAGE (128*LDA)              /* 4608 floats */
#define B_STAGE (32*LDB)               /* 4352 floats */
#define STAGE_F (A_STAGE + B_STAGE)    /* 8960 floats */
#define GEMM_SMEM (3*STAGE_F*4)        /* 107520 bytes */

template<int EPI>   // 0 = bias, 1 = bias+gelu(tf32), 2 = bias+residual
__global__ __launch_bounds__(256)
void gemm_mma(const float* __restrict__ A, const float* __restrict__ B,
              const float* __restrict__ bias, const float* __restrict__ R,
              float* __restrict__ C, int M, int N, int K) {
    extern __shared__ float sm[];
    const uint32_t sbase = smem_u32(sm);
    const int tid = threadIdx.x, lane = tid & 31, wid = tid >> 5;
    const int wm = wid & 3, wn = wid >> 2;
    const int bm = blockIdx.y * 128, bn = blockIdx.x * 128;
    const int niter = K >> 5;

    // per-thread load slots: 4 A chunks + 4 B chunks (16B each)
    int arow[4], acol[4], bkr[4], bnc[4];
    #pragma unroll
    for (int t = 0; t < 4; t++) {
        int ci = tid + t * 256;             // 0..1023
        arow[t] = ci >> 3;  acol[t] = (ci & 7) * 4;
        bkr[t]  = ci >> 5;  bnc[t]  = (ci & 31) * 4;
    }

    float acc[2][8][4];
    #pragma unroll
    for (int mi = 0; mi < 2; mi++)
        #pragma unroll
        for (int nj = 0; nj < 8; nj++)
            #pragma unroll
            for (int r = 0; r < 4; r++) acc[mi][nj][r] = 0.f;

    // stage issuer
    auto issue = [&](int ks, int buf) {
        const int k0 = ks << 5;
        const uint32_t s0 = sbase + (uint32_t)buf * STAGE_F * 4u;
        #pragma unroll
        for (int t = 0; t < 4; t++)
            CP_ASYNC16(s0 + (uint32_t)(arow[t] * LDA + acol[t]) * 4u,
                       A + (size_t)(bm + arow[t]) * K + k0 + acol[t]);
        const uint32_t s1 = s0 + A_STAGE * 4u;
        #pragma unroll
        for (int t = 0; t < 4; t++)
            CP_ASYNC16(s1 + (uint32_t)(bkr[t] * LDB + bnc[t]) * 4u,
                       B + (size_t)(k0 + bkr[t]) * N + bn + bnc[t]);
        CP_COMMIT();
    };

    issue(0, 0);
    issue(1, 1);

    for (int i = 0; i < niter; i++) {
        if (i + 1 < niter) { CP_WAIT(1); } else { CP_WAIT(0); }
        __syncthreads();
        if (i + 2 < niter) issue(i + 2, (i + 2) % 3);

        const uint32_t* As = (const uint32_t*)(sm + (i % 3) * STAGE_F);
        const uint32_t* Bs = As + A_STAGE;
        const int ar0 = wm * 32 + (lane >> 2);
        const int kc  = lane & 3;
        const int nb  = wn * 64 + (lane >> 2);

        #pragma unroll
        for (int kk = 0; kk < 32; kk += 8) {
            uint32_t a[2][4];
            #pragma unroll
            for (int mi = 0; mi < 2; mi++) {
                const uint32_t* ap = As + (ar0 + mi * 16) * LDA + kk + kc;
                a[mi][0] = ap[0];
                a[mi][1] = ap[8 * LDA];
                a[mi][2] = ap[4];
                a[mi][3] = ap[8 * LDA + 4];
            }
            const uint32_t* b0p = Bs + (kk + kc) * LDB + nb;
            const uint32_t* b1p = b0p + 4 * LDB;
            #pragma unroll
            for (int nj = 0; nj < 8; nj++) {
                uint32_t b0 = b0p[nj * 8], b1 = b1p[nj * 8];
                #pragma unroll
                for (int mi = 0; mi < 2; mi++)
                    mma_tf32(acc[mi][nj], a[mi][0], a[mi][1], a[mi][2], a[mi][3], b0, b1);
            }
        }
    }

    // ---- epilogue ----
    #pragma unroll
    for (int mi = 0; mi < 2; mi++) {
        const int row0 = bm + wm * 32 + mi * 16 + (lane >> 2);
        #pragma unroll
        for (int nj = 0; nj < 8; nj++) {
            const int col0 = bn + wn * 64 + nj * 8 + (lane & 3) * 2;
            const float b0 = bias[col0], b1 = bias[col0 + 1];
            #pragma unroll
            for (int h = 0; h < 2; h++) {
                const int row = row0 + h * 8;
                float v0 = acc[mi][nj][h * 2 + 0] + b0;
                float v1 = acc[mi][nj][h * 2 + 1] + b1;
                if (EPI == 1) { v0 = to_tf32(gelu_new(v0)); v1 = to_tf32(gelu_new(v1)); }
                size_t g = (size_t)row * N + col0;
                if (EPI == 2) {
                    float2 rv = *(const float2*)(R + g);
                    v0 += rv.x; v1 += rv.y;
                }
                float2 o; o.x = v0; o.y = v1;
                *(float2*)(C + g) = o;
            }
        }
    }
}

// ---------------- layernorm (tf32-rounded output) ----------------------------
__global__ __launch_bounds__(256)
void ln_kernel(const float* __restrict__ in, const float* __restrict__ w,
               const float* __restrict__ b, float* __restrict__ out) {
    int row = blockIdx.x;
    const float* x = in + (size_t)row * DM;
    float s = 0.f, ss = 0.f;
    for (int i = threadIdx.x; i < DM; i += 256) {
        float v = x[i]; s += v; ss += v * v;
    }
    __shared__ float red0[32], red1[32];
    #pragma unroll
    for (int o = 16; o; o >>= 1) {
        s  += __shfl_xor_sync(0xffffffffu, s,  o);
        ss += __shfl_xor_sync(0xffffffffu, ss, o);
    }
    int warp = threadIdx.x >> 5, lane = threadIdx.x & 31;
    if (lane == 0) { red0[warp] = s; red1[warp] = ss; }
    __syncthreads();
    if (warp == 0) {
        s  = (lane < 8) ? red0[lane] : 0.f;
        ss = (lane < 8) ? red1[lane] : 0.f;
        #pragma unroll
        for (int o = 4; o; o >>= 1) {
            s  += __shfl_xor_sync(0xffffffffu, s,  o);
            ss += __shfl_xor_sync(0xffffffffu, ss, o);
        }
        if (lane == 0) {
            float mean = s / DM;
            float var  = ss / DM - mean * mean;
            red0[0] = mean;
            red1[0] = rsqrtf(var + 1e-5f);
        }
    }
    __syncthreads();
    float mean = red0[0], inv = red1[0];
    for (int i = threadIdx.x; i < DM; i += 256)
        out[(size_t)row * DM + i] = to_tf32((x[i] - mean) * inv * w[i] + b[i]);
}

// ---------------- QKV weight repack to [K=768, N=2304] ----------------------
__global__ void pack_qkv(const float* __restrict__ WQ, const float* __restrict__ WK,
                         const float* __restrict__ WV,
                         const float* __restrict__ bQ, const float* __restrict__ bK,
                         const float* __restrict__ bV,
                         float* __restrict__ Wp, float* __restrict__ bias) {
    int idx = blockIdx.x * 256 + threadIdx.x;       // over 768*768
    if (idx < DM * DM) {
        int k = idx / DM, n = idx % DM;             // n = h*64+e
        int h = n >> 6, e = n & 63;
        int src = h * (DM * DH) + k * DH + e;
        Wp[(size_t)k * QKVN + n]            = to_tf32(WQ[src]);
        Wp[(size_t)k * QKVN + DM + n]       = to_tf32(WK[src]);
        Wp[(size_t)k * QKVN + 2 * DM + n]   = to_tf32(WV[src]);
    }
    if (idx < DM) {
        bias[idx]          = bQ[idx];
        bias[DM + idx]     = bK[idx];
        bias[2 * DM + idx] = bV[idx];
    }
}

// ============== flash attention via tf32 mma.sync (causal) ==================
#define LDK 68
#define ATTN_SMEM ((2*64*LDK + 128*LDK) * 4)

__global__ __launch_bounds__(256)
void attn_mma(const float* __restrict__ QKV, float* __restrict__ Z) {
    extern __shared__ float sm[];
    float* Ks = sm;                 // 64*68
    float* Vt = sm + 64 * LDK;      // 64*68
    float* QP = sm + 2 * 64 * LDK;  // 128*68

    const int tid = threadIdx.x, lane = tid & 31, wid = tid >> 5;
    const int r = lane >> 2, c = lane & 3;
    const int qt0 = blockIdx.x * 128;
    const int h = blockIdx.y, b = blockIdx.z;

    const float* qbase = QKV + ((size_t)(b * SEQ + qt0)) * QKVN + h * DH;
    for (int i = tid; i < 128 * 64; i += 256) {
        int rr = i >> 6, e = i & 63;
        QP[rr * LDK + e] = to_tf32(qbase[(size_t)rr * QKVN + e] * 0.125f);
    }
    __syncthreads();
    uint32_t qf[8][4];
    {
        const uint32_t* Qw = (const uint32_t*)(QP + wid * 16 * LDK);
        #pragma unroll
        for (int kk = 0; kk < 8; kk++) {
            qf[kk][0] = Qw[r * LDK + kk * 8 + c];
            qf[kk][1] = Qw[(r + 8) * LDK + kk * 8 + c];
            qf[kk][2] = Qw[r * LDK + kk * 8 + c + 4];
            qf[kk][3] = Qw[(r + 8) * LDK + kk * 8 + c + 4];
        }
    }

    float o[8][4];
    #pragma unroll
    for (int nj = 0; nj < 8; nj++)
        #pragma unroll
        for (int t = 0; t < 4; t++) o[nj][t] = 0.f;
    float m0 = -1e30f, m1 = -1e30f, l0 = 0.f, l1 = 0.f;

    const int q0g = qt0 + wid * 16 + r;
    const int qmax_warp = qt0 + wid * 16 + 15;
    const int ntiles = qt0 / 64 + 2;

    uint32_t* Pw = (uint32_t*)(QP + wid * 16 * LDK);

    for (int kt = 0; kt < ntiles; kt++) {
        __syncthreads();
        const float* kb = QKV + ((size_t)(b * SEQ + kt * 64)) * QKVN + DM     + h * DH;
        const float* vb = QKV + ((size_t)(b * SEQ + kt * 64)) * QKVN + 2 * DM + h * DH;
        for (int i = tid; i < 64 * 64; i += 256) {
            int key = i >> 6, e = i & 63;
            Ks[key * LDK + e] = to_tf32(kb[(size_t)key * QKVN + e]);
            Vt[e * LDK + key] = to_tf32(vb[(size_t)key * QKVN + e]);
        }
        __syncthreads();

        if (kt * 64 > qmax_warp) continue;

        float s[8][4];
        #pragma unroll
        for (int nj = 0; nj < 8; nj++)
            #pragma unroll
            for (int t = 0; t < 4; t++) s[nj][t] = 0.f;
        const uint32_t* Ksu = (const uint32_t*)Ks;
        #pragma unroll
        for (int kk = 0; kk < 8; kk++) {
            #pragma unroll
            for (int nj = 0; nj < 8; nj++) {
                const uint32_t* bp = Ksu + (nj * 8 + r) * LDK + kk * 8 + c;
                mma_tf32(s[nj], qf[kk][0], qf[kk][1], qf[kk][2], qf[kk][3],
                         bp[0], bp[4]);
            }
        }

        if (kt * 64 + 63 > qt0 + wid * 16) {
            #pragma unroll
            for (int nj = 0; nj < 8; nj++) {
                int k0c = kt * 64 + nj * 8 + c * 2;
                if (k0c     > q0g)     s[nj][0] = -1e30f;
                if (k0c + 1 > q0g)     s[nj][1] = -1e30f;
                if (k0c     > q0g + 8) s[nj][2] = -1e30f;
                if (k0c + 1 > q0g + 8) s[nj][3] = -1e30f;
            }
        }

        float mt0 = -1e30f, mt1 = -1e30f;
        #pragma unroll
        for (int nj = 0; nj < 8; nj++) {
            mt0 = fmaxf(mt0, fmaxf(s[nj][0], s[nj][1]));
            mt1 = fmaxf(mt1, fmaxf(s[nj][2], s[nj][3]));
        }
        mt0 = fmaxf(mt0, __shfl_xor_sync(0xffffffffu, mt0, 1));
        mt0 = fmaxf(mt0, __shfl_xor_sync(0xffffffffu, mt0, 2));
        mt1 = fmaxf(mt1, __shfl_xor_sync(0xffffffffu, mt1, 1));
        mt1 = fmaxf(mt1, __shfl_xor_sync(0xffffffffu, mt1, 2));

        float mn0 = fmaxf(m0, mt0), mn1 = fmaxf(m1, mt1);
        float cr0 = __expf(m0 - mn0), cr1 = __expf(m1 - mn1);
        float ls0 = 0.f, ls1 = 0.f;
        #pragma unroll
        for (int nj = 0; nj < 8; nj++) {
            s[nj][0] = __expf(s[nj][0] - mn0);
            s[nj][1] = __expf(s[nj][1] - mn0);
            s[nj][2] = __expf(s[nj][2] - mn1);
            s[nj][3] = __expf(s[nj][3] - mn1);
            ls0 += s[nj][0] + s[nj][1];
            ls1 += s[nj][2] + s[nj][3];
        }
        ls0 += __shfl_xor_sync(0xffffffffu, ls0, 1);
        ls0 += __shfl_xor_sync(0xffffffffu, ls0, 2);
        ls1 += __shfl_xor_sync(0xffffffffu, ls1, 1);
        ls1 += __shfl_xor_sync(0xffffffffu, ls1, 2);
        l0 = l0 * cr0 + ls0;
        l1 = l1 * cr1 + ls1;
        m0 = mn0; m1 = mn1;
        #pragma unroll
        for (int nj = 0; nj < 8; nj++) {
            o[nj][0] *= cr0; o[nj][1] *= cr0;
            o[nj][2] *= cr1; o[nj][3] *= cr1;
        }

        #pragma unroll
        for (int nj = 0; nj < 8; nj++) {
            int colb = nj * 8 + c * 2;
            Pw[r * LDK + colb]           = __float_as_uint(to_tf32(s[nj][0]));
            Pw[r * LDK + colb + 1]       = __float_as_uint(to_tf32(s[nj][1]));
            Pw[(r + 8) * LDK + colb]     = __float_as_uint(to_tf32(s[nj][2]));
            Pw[(r + 8) * LDK + colb + 1] = __float_as_uint(to_tf32(s[nj][3]));
        }
        __syncwarp();

        const uint32_t* Vtu = (const uint32_t*)Vt;
        #pragma unroll
        for (int kk = 0; kk < 8; kk++) {
            uint32_t a0 = Pw[r * LDK + kk * 8 + c];
            uint32_t a1 = Pw[(r + 8) * LDK + kk * 8 + c];
            uint32_t a2 = Pw[r * LDK + kk * 8 + c + 4];
            uint32_t a3 = Pw[(r + 8) * LDK + kk * 8 + c + 4];
            #pragma unroll
            for (int nj = 0; nj < 8; nj++) {
                const uint32_t* bp = Vtu + (nj * 8 + r) * LDK + kk * 8 + c;
                mma_tf32(o[nj], a0, a1, a2, a3, bp[0], bp[4]);
            }
        }
        __syncwarp();
    }

    float inv0 = 1.f / l0, inv1 = 1.f / l1;
    #pragma unroll
    for (int nj = 0; nj < 8; nj++) {
        int col = h * DH + nj * 8 + c * 2;
        size_t g0 = (size_t)(b * SEQ + q0g) * DM + col;
        size_t g1 = (size_t)(b * SEQ + q0g + 8) * DM + col;
        float2 v0, v1;
        v0.x = to_tf32(o[nj][0] * inv0); v0.y = to_tf32(o[nj][1] * inv0);
        v1.x = to_tf32(o[nj][2] * inv1); v1.y = to_tf32(o[nj][3] * inv1);
        *(float2*)(Z + g0) = v0;
        *(float2*)(Z + g1) = v1;
    }
}

// ---------------- launch -----------------------------------------------------
extern "C" void kernel_launch(void* const* d_in, const int* in_sizes, int n_in,
                              void* d_out, int out_size) {
    const float* resid_pre = (const float*)d_in[0];
    const float* W_Q   = (const float*)d_in[1];
    const float* b_Q   = (const float*)d_in[2];
    const float* W_K   = (const float*)d_in[3];
    const float* b_K   = (const float*)d_in[4];
    const float* W_V   = (const float*)d_in[5];
    const float* b_V   = (const float*)d_in[6];
    const float* W_O   = (const float*)d_in[7];
    const float* b_O   = (const float*)d_in[8];
    const float* ln1_w = (const float*)d_in[9];
    const float* ln1_b = (const float*)d_in[10];
    const float* ln2_w = (const float*)d_in[11];
    const float* ln2_b = (const float*)d_in[12];
    const float* W_in  = (const float*)d_in[13];
    const float* b_in  = (const float*)d_in[14];
    const float* W_out = (const float*)d_in[15];
    const float* b_out = (const float*)d_in[16];
    float* out = (float*)d_out;

    float *px, *pwqkv, *pbqkv, *pqkv, *pz, *pmid, *py, *ph;
    cudaGetSymbolAddress((void**)&px,    g_x);
    cudaGetSymbolAddress((void**)&pwqkv, g_wqkv);
    cudaGetSymbolAddress((void**)&pbqkv, g_bqkv);
    cudaGetSymbolAddress((void**)&pqkv,  g_qkv);
    cudaGetSymbolAddress((void**)&pz,    g_z);
    cudaGetSymbolAddress((void**)&pmid,  g_mid);
    cudaGetSymbolAddress((void**)&py,    g_y);
    cudaGetSymbolAddress((void**)&ph,    g_h);

    cudaFuncSetAttribute(gemm_mma<0>, cudaFuncAttributeMaxDynamicSharedMemorySize, GEMM_SMEM);
    cudaFuncSetAttribute(gemm_mma<1>, cudaFuncAttributeMaxDynamicSharedMemorySize, GEMM_SMEM);
    cudaFuncSetAttribute(gemm_mma<2>, cudaFuncAttributeMaxDynamicSharedMemorySize, GEMM_SMEM);
    cudaFuncSetAttribute(attn_mma,    cudaFuncAttributeMaxDynamicSharedMemorySize, ATTN_SMEM);

    // QKV weight pack ([K,N] + tf32 rounding); W_O / W_in / W_out used directly.
    pack_qkv<<<(DM * DM + 255) / 256, 256>>>(W_Q, W_K, W_V, b_Q, b_K, b_V, pwqkv, pbqkv);

    ln_kernel<<<ROWS, 256>>>(resid_pre, ln1_w, ln1_b, px);
    gemm_mma<0><<<dim3(QKVN / 128, ROWS / 128), 256, GEMM_SMEM>>>(
        px, pwqkv, pbqkv, nullptr, pqkv, ROWS, QKVN, DM);
    attn_mma<<<dim3(SEQ / 128, NH, BATCH), 256, ATTN_SMEM>>>(pqkv, pz);
    gemm_mma<2><<<dim3(DM / 128, ROWS / 128), 256, GEMM_SMEM>>>(
        pz, W_O, b_O, resid_pre, pmid, ROWS, DM, DM);
    ln_kernel<<<ROWS, 256>>>(pmid, ln2_w, ln2_b, py);
    gemm_mma<1><<<dim3(DMLP / 128, ROWS / 128), 256, GEMM_SMEM>>>(
        py, W_in, b_in, nullptr, ph, ROWS, DMLP, DM);
    gemm_mma<2><<<dim3(DM / 128, ROWS / 128), 256, GEMM_SMEM>>>(
        ph, W_out, b_out, pmid, out, ROWS, DM, DMLP);
}

// round 6
// speedup vs baseline: 5.1663x; 1.0724x over previous
#include <cuda_runtime.h>
#include <cstdint>
#include <math.h>

#define DM    768
#define DMLP  3072
#define NH    12
#define DH    64
#define BATCH 2
#define SEQ   2048
#define ROWS  (BATCH*SEQ)     /* 4096 */
#define QKVN  (3*DM)          /* 2304 */

// ---------------- scratch (static device globals; no allocation) -----------
__device__ float g_x    [ROWS*DM];      // ln1 output (tf32-rounded)
__device__ float g_wqkv [DM*QKVN];      // packed QKV weight, [K=768, N=2304]
__device__ float g_bqkv [QKVN];
__device__ float g_qkv  [ROWS*QKVN];    // Q|K|V per token
__device__ float g_z    [ROWS*DM];      // attention output (tf32-rounded)
__device__ float g_mid  [ROWS*DM];      // resid_mid (fp32)
__device__ float g_y    [ROWS*DM];      // ln2 output (tf32-rounded)
__device__ float g_h    [ROWS*DMLP];    // MLP hidden (tf32-rounded)

// ======================= helpers ============================================
__device__ __forceinline__ uint32_t smem_u32(const void* p) {
    uint32_t a;
    asm("{ .reg .u64 t; cvta.to.shared.u64 t, %1; cvt.u32.u64 %0, t; }"
        : "=r"(a) : "l"(p));
    return a;
}
__device__ __forceinline__ float to_tf32(float x) {
    uint32_t u;
    asm("cvt.rna.tf32.f32 %0, %1;" : "=r"(u) : "f"(x));
    return __uint_as_float(u);
}
__device__ __forceinline__ float gelu_new(float v) {
    float v3 = v * v * v;
    return 0.5f * v * (1.f + tanhf(0.7978845608028654f * (v + 0.044715f * v3)));
}
#define CP_ASYNC16(sa, gp) \
    asm volatile("cp.async.cg.shared.global [%0], [%1], 16;" :: "r"(sa), "l"(gp))
#define CP_COMMIT() asm volatile("cp.async.commit_group;" ::: "memory")
#define CP_WAIT(n)  asm volatile("cp.async.wait_group %0;" :: "n"(n) : "memory")

__device__ __forceinline__ void mma_tf32(float* c, uint32_t a0, uint32_t a1,
                                         uint32_t a2, uint32_t a3,
                                         uint32_t b0, uint32_t b1) {
    asm volatile(
        "mma.sync.aligned.m16n8k8.row.col.f32.tf32.tf32.f32 "
        "{%0,%1,%2,%3}, {%4,%5,%6,%7}, {%8,%9}, {%0,%1,%2,%3};\n"
        : "+f"(c[0]), "+f"(c[1]), "+f"(c[2]), "+f"(c[3])
        : "r"(a0), "r"(a1), "r"(a2), "r"(a3), "r"(b0), "r"(b1));
}

// ====== tf32 mma.sync GEMM: C[M,N] = A[M,K] @ B[K,N]   (B row-major) ========
#define LDA 36
#define LDB 136
#define A_STAGE (128*LDA)
#define B_STAGE (32*LDB)
#define STAGE_F (A_STAGE + B_STAGE)
#define GEMM_SMEM (3*STAGE_F*4)

template<int EPI>   // 0 = bias, 1 = bias+gelu(tf32), 2 = bias+residual
__global__ __launch_bounds__(256)
void gemm_mma(const float* __restrict__ A, const float* __restrict__ B,
              const float* __restrict__ bias, const float* __restrict__ R,
              float* __restrict__ C, int M, int N, int K) {
    extern __shared__ float sm[];
    const uint32_t sbase = smem_u32(sm);
    const int tid = threadIdx.x, lane = tid & 31, wid = tid >> 5;
    const int wm = wid & 3, wn = wid >> 2;
    const int bm = blockIdx.y * 128, bn = blockIdx.x * 128;
    const int niter = K >> 5;

    int arow[4], acol[4], bkr[4], bnc[4];
    #pragma unroll
    for (int t = 0; t < 4; t++) {
        int ci = tid + t * 256;
        arow[t] = ci >> 3;  acol[t] = (ci & 7) * 4;
        bkr[t]  = ci >> 5;  bnc[t]  = (ci & 31) * 4;
    }

    float acc[2][8][4];
    #pragma unroll
    for (int mi = 0; mi < 2; mi++)
        #pragma unroll
        for (int nj = 0; nj < 8; nj++)
            #pragma unroll
            for (int r = 0; r < 4; r++) acc[mi][nj][r] = 0.f;

    auto issue = [&](int ks, int buf) {
        const int k0 = ks << 5;
        const uint32_t s0 = sbase + (uint32_t)buf * STAGE_F * 4u;
        #pragma unroll
        for (int t = 0; t < 4; t++)
            CP_ASYNC16(s0 + (uint32_t)(arow[t] * LDA + acol[t]) * 4u,
                       A + (size_t)(bm + arow[t]) * K + k0 + acol[t]);
        const uint32_t s1 = s0 + A_STAGE * 4u;
        #pragma unroll
        for (int t = 0; t < 4; t++)
            CP_ASYNC16(s1 + (uint32_t)(bkr[t] * LDB + bnc[t]) * 4u,
                       B + (size_t)(k0 + bkr[t]) * N + bn + bnc[t]);
        CP_COMMIT();
    };

    issue(0, 0);
    issue(1, 1);

    for (int i = 0; i < niter; i++) {
        if (i + 1 < niter) { CP_WAIT(1); } else { CP_WAIT(0); }
        __syncthreads();
        if (i + 2 < niter) issue(i + 2, (i + 2) % 3);

        const uint32_t* As = (const uint32_t*)(sm + (i % 3) * STAGE_F);
        const uint32_t* Bs = As + A_STAGE;
        const int ar0 = wm * 32 + (lane >> 2);
        const int kc  = lane & 3;
        const int nb  = wn * 64 + (lane >> 2);

        #pragma unroll
        for (int kk = 0; kk < 32; kk += 8) {
            uint32_t a[2][4];
            #pragma unroll
            for (int mi = 0; mi < 2; mi++) {
                const uint32_t* ap = As + (ar0 + mi * 16) * LDA + kk + kc;
                a[mi][0] = ap[0];
                a[mi][1] = ap[8 * LDA];
                a[mi][2] = ap[4];
                a[mi][3] = ap[8 * LDA + 4];
            }
            const uint32_t* b0p = Bs + (kk + kc) * LDB + nb;
            const uint32_t* b1p = b0p + 4 * LDB;
            #pragma unroll
            for (int nj = 0; nj < 8; nj++) {
                uint32_t b0 = b0p[nj * 8], b1 = b1p[nj * 8];
                #pragma unroll
                for (int mi = 0; mi < 2; mi++)
                    mma_tf32(acc[mi][nj], a[mi][0], a[mi][1], a[mi][2], a[mi][3], b0, b1);
            }
        }
    }

    #pragma unroll
    for (int mi = 0; mi < 2; mi++) {
        const int row0 = bm + wm * 32 + mi * 16 + (lane >> 2);
        #pragma unroll
        for (int nj = 0; nj < 8; nj++) {
            const int col0 = bn + wn * 64 + nj * 8 + (lane & 3) * 2;
            const float b0 = bias[col0], b1 = bias[col0 + 1];
            #pragma unroll
            for (int h = 0; h < 2; h++) {
                const int row = row0 + h * 8;
                float v0 = acc[mi][nj][h * 2 + 0] + b0;
                float v1 = acc[mi][nj][h * 2 + 1] + b1;
                if (EPI == 1) { v0 = to_tf32(gelu_new(v0)); v1 = to_tf32(gelu_new(v1)); }
                size_t g = (size_t)row * N + col0;
                if (EPI == 2) {
                    float2 rv = *(const float2*)(R + g);
                    v0 += rv.x; v1 += rv.y;
                }
                float2 o; o.x = v0; o.y = v1;
                *(float2*)(C + g) = o;
            }
        }
    }
}

// ---------------- layernorm (tf32-rounded output) ----------------------------
__global__ __launch_bounds__(256)
void ln_kernel(const float* __restrict__ in, const float* __restrict__ w,
               const float* __restrict__ b, float* __restrict__ out) {
    int row = blockIdx.x;
    const float* x = in + (size_t)row * DM;
    float s = 0.f, ss = 0.f;
    for (int i = threadIdx.x; i < DM; i += 256) {
        float v = x[i]; s += v; ss += v * v;
    }
    __shared__ float red0[32], red1[32];
    #pragma unroll
    for (int o = 16; o; o >>= 1) {
        s  += __shfl_xor_sync(0xffffffffu, s,  o);
        ss += __shfl_xor_sync(0xffffffffu, ss, o);
    }
    int warp = threadIdx.x >> 5, lane = threadIdx.x & 31;
    if (lane == 0) { red0[warp] = s; red1[warp] = ss; }
    __syncthreads();
    if (warp == 0) {
        s  = (lane < 8) ? red0[lane] : 0.f;
        ss = (lane < 8) ? red1[lane] : 0.f;
        #pragma unroll
        for (int o = 4; o; o >>= 1) {
            s  += __shfl_xor_sync(0xffffffffu, s,  o);
            ss += __shfl_xor_sync(0xffffffffu, ss, o);
        }
        if (lane == 0) {
            float mean = s / DM;
            float var  = ss / DM - mean * mean;
            red0[0] = mean;
            red1[0] = rsqrtf(var + 1e-5f);
        }
    }
    __syncthreads();
    float mean = red0[0], inv = red1[0];
    for (int i = threadIdx.x; i < DM; i += 256)
        out[(size_t)row * DM + i] = to_tf32((x[i] - mean) * inv * w[i] + b[i]);
}

// ---------------- QKV weight repack to [K=768, N=2304] ----------------------
__global__ void pack_qkv(const float* __restrict__ WQ, const float* __restrict__ WK,
                         const float* __restrict__ WV,
                         const float* __restrict__ bQ, const float* __restrict__ bK,
                         const float* __restrict__ bV,
                         float* __restrict__ Wp, float* __restrict__ bias) {
    int idx = blockIdx.x * 256 + threadIdx.x;
    if (idx < DM * DM) {
        int k = idx / DM, n = idx % DM;
        int h = n >> 6, e = n & 63;
        int src = h * (DM * DH) + k * DH + e;
        Wp[(size_t)k * QKVN + n]            = to_tf32(WQ[src]);
        Wp[(size_t)k * QKVN + DM + n]       = to_tf32(WK[src]);
        Wp[(size_t)k * QKVN + 2 * DM + n]   = to_tf32(WV[src]);
    }
    if (idx < DM) {
        bias[idx]          = bQ[idx];
        bias[DM + idx]     = bK[idx];
        bias[2 * DM + idx] = bV[idx];
    }
}

// ============== flash attention via tf32 mma.sync (causal, cp.async) ========
// CTA 256 thr / 8 warps; Q tile 128 rows (16/warp); K/V tile 64 keys, 2 bufs.
// Smem floats: QP[128*68] (Q then per-warp P staging), K0/K1[64*68], V0/V1[64*72].
#define LDK 68
#define LDV 72
#define QP_OFF  0
#define K_OFF   (128*LDK)                 /* 8704 */
#define V_OFF   (K_OFF + 2*64*LDK)        /* 8704 + 8704 = 17408 */
#define ATTN_F  (V_OFF + 2*64*LDV)        /* 17408 + 9216 = 26624 floats */
#define ATTN_SMEM (ATTN_F*4)              /* 106496 bytes */

__global__ __launch_bounds__(256)
void attn_mma(const float* __restrict__ QKV, float* __restrict__ Z) {
    extern __shared__ float sm[];
    const uint32_t sbase = smem_u32(sm);

    const int tid = threadIdx.x, lane = tid & 31, wid = tid >> 5;
    const int r = lane >> 2, c = lane & 3;
    const int qt = gridDim.x - 1 - blockIdx.x;       // heavy blocks first
    const int qt0 = qt * 128;
    const int h = blockIdx.y, b = blockIdx.z;

    const float* qbase = QKV + ((size_t)(b * SEQ + qt0)) * QKVN + h * DH;
    const float* kbase = QKV + ((size_t)b * SEQ) * QKVN + DM     + h * DH;
    const float* vbase = QKV + ((size_t)b * SEQ) * QKVN + 2 * DM + h * DH;

    const int ntiles = qt0 / 64 + 2;

    // ---- async loaders -------------------------------------------------
    auto issue_kv = [&](int kt, int buf) {
        const float* kb = kbase + (size_t)(kt * 64) * QKVN;
        const float* vb = vbase + (size_t)(kt * 64) * QKVN;
        const uint32_t ks = sbase + (K_OFF + buf * 64 * LDK) * 4u;
        const uint32_t vs = sbase + (V_OFF + buf * 64 * LDV) * 4u;
        #pragma unroll
        for (int t = 0; t < 4; t++) {
            int ci = tid + t * 256;               // 0..1023
            int row = ci >> 4, c16 = ci & 15;
            CP_ASYNC16(ks + (uint32_t)(row * LDK + c16 * 4) * 4u,
                       kb + (size_t)row * QKVN + c16 * 4);
            CP_ASYNC16(vs + (uint32_t)(row * LDV + c16 * 4) * 4u,
                       vb + (size_t)row * QKVN + c16 * 4);
        }
        CP_COMMIT();
    };

    // group 0: Q + KV tile 0
    {
        #pragma unroll
        for (int t = 0; t < 8; t++) {
            int ci = tid + t * 256;               // 0..2047
            int row = ci >> 4, c16 = ci & 15;
            CP_ASYNC16(sbase + (uint32_t)(row * LDK + c16 * 4) * 4u,
                       qbase + (size_t)row * QKVN + c16 * 4);
        }
        const float* kb = kbase;
        const float* vb = vbase;
        const uint32_t ks = sbase + K_OFF * 4u;
        const uint32_t vs = sbase + V_OFF * 4u;
        #pragma unroll
        for (int t = 0; t < 4; t++) {
            int ci = tid + t * 256;
            int row = ci >> 4, c16 = ci & 15;
            CP_ASYNC16(ks + (uint32_t)(row * LDK + c16 * 4) * 4u,
                       kb + (size_t)row * QKVN + c16 * 4);
            CP_ASYNC16(vs + (uint32_t)(row * LDV + c16 * 4) * 4u,
                       vb + (size_t)row * QKVN + c16 * 4);
        }
        CP_COMMIT();
    }
    if (ntiles > 1) issue_kv(1, 1);

    float o[8][4];
    #pragma unroll
    for (int nj = 0; nj < 8; nj++)
        #pragma unroll
        for (int t = 0; t < 4; t++) o[nj][t] = 0.f;
    float m0 = -1e30f, m1 = -1e30f, l0 = 0.f, l1 = 0.f;

    const int q0g = qt0 + wid * 16 + r;
    const int qmax_warp = qt0 + wid * 16 + 15;

    uint32_t qf[8][4];
    uint32_t* Pw = (uint32_t*)(sm + wid * 16 * LDK);

    for (int kt = 0; kt < ntiles; kt++) {
        if (kt + 1 < ntiles) { CP_WAIT(1); } else { CP_WAIT(0); }
        __syncthreads();

        if (kt == 0) {
            // build Q fragments: cvt.rna(raw * scale)
            const float* Qw = sm + wid * 16 * LDK;
            #pragma unroll
            for (int kk = 0; kk < 8; kk++) {
                qf[kk][0] = __float_as_uint(to_tf32(0.125f * Qw[r * LDK + kk * 8 + c]));
                qf[kk][1] = __float_as_uint(to_tf32(0.125f * Qw[(r + 8) * LDK + kk * 8 + c]));
                qf[kk][2] = __float_as_uint(to_tf32(0.125f * Qw[r * LDK + kk * 8 + c + 4]));
                qf[kk][3] = __float_as_uint(to_tf32(0.125f * Qw[(r + 8) * LDK + kk * 8 + c + 4]));
            }
        }

        if (kt * 64 <= qmax_warp) {
            const int buf = kt & 1;
            const uint32_t* Ksu = (const uint32_t*)(sm + K_OFF + buf * 64 * LDK);
            const uint32_t* Vsu = (const uint32_t*)(sm + V_OFF + buf * 64 * LDV);

            // ---- S = Q @ K^T   (K smem [key][e], B-frag row-major [n][k])
            float s[8][4];
            #pragma unroll
            for (int nj = 0; nj < 8; nj++)
                #pragma unroll
                for (int t = 0; t < 4; t++) s[nj][t] = 0.f;
            #pragma unroll
            for (int kk = 0; kk < 8; kk++) {
                #pragma unroll
                for (int nj = 0; nj < 8; nj++) {
                    const uint32_t* bp = Ksu + (nj * 8 + r) * LDK + kk * 8 + c;
                    mma_tf32(s[nj], qf[kk][0], qf[kk][1], qf[kk][2], qf[kk][3],
                             bp[0], bp[4]);
                }
            }

            // ---- causal mask
            if (kt * 64 + 63 > qt0 + wid * 16) {
                #pragma unroll
                for (int nj = 0; nj < 8; nj++) {
                    int k0c = kt * 64 + nj * 8 + c * 2;
                    if (k0c     > q0g)     s[nj][0] = -1e30f;
                    if (k0c + 1 > q0g)     s[nj][1] = -1e30f;
                    if (k0c     > q0g + 8) s[nj][2] = -1e30f;
                    if (k0c + 1 > q0g + 8) s[nj][3] = -1e30f;
                }
            }

            // ---- online softmax
            float mt0 = -1e30f, mt1 = -1e30f;
            #pragma unroll
            for (int nj = 0; nj < 8; nj++) {
                mt0 = fmaxf(mt0, fmaxf(s[nj][0], s[nj][1]));
                mt1 = fmaxf(mt1, fmaxf(s[nj][2], s[nj][3]));
            }
            mt0 = fmaxf(mt0, __shfl_xor_sync(0xffffffffu, mt0, 1));
            mt0 = fmaxf(mt0, __shfl_xor_sync(0xffffffffu, mt0, 2));
            mt1 = fmaxf(mt1, __shfl_xor_sync(0xffffffffu, mt1, 1));
            mt1 = fmaxf(mt1, __shfl_xor_sync(0xffffffffu, mt1, 2));

            float mn0 = fmaxf(m0, mt0), mn1 = fmaxf(m1, mt1);
            float cr0 = __expf(m0 - mn0), cr1 = __expf(m1 - mn1);
            float ls0 = 0.f, ls1 = 0.f;
            #pragma unroll
            for (int nj = 0; nj < 8; nj++) {
                s[nj][0] = __expf(s[nj][0] - mn0);
                s[nj][1] = __expf(s[nj][1] - mn0);
                s[nj][2] = __expf(s[nj][2] - mn1);
                s[nj][3] = __expf(s[nj][3] - mn1);
                ls0 += s[nj][0] + s[nj][1];
                ls1 += s[nj][2] + s[nj][3];
            }
            ls0 += __shfl_xor_sync(0xffffffffu, ls0, 1);
            ls0 += __shfl_xor_sync(0xffffffffu, ls0, 2);
            ls1 += __shfl_xor_sync(0xffffffffu, ls1, 1);
            ls1 += __shfl_xor_sync(0xffffffffu, ls1, 2);
            l0 = l0 * cr0 + ls0;
            l1 = l1 * cr1 + ls1;
            m0 = mn0; m1 = mn1;
            #pragma unroll
            for (int nj = 0; nj < 8; nj++) {
                o[nj][0] *= cr0; o[nj][1] *= cr0;
                o[nj][2] *= cr1; o[nj][3] *= cr1;
            }

            // ---- stage P (tf32-rounded) to per-warp smem
            #pragma unroll
            for (int nj = 0; nj < 8; nj++) {
                int colb = nj * 8 + c * 2;
                Pw[r * LDK + colb]           = __float_as_uint(to_tf32(s[nj][0]));
                Pw[r * LDK + colb + 1]       = __float_as_uint(to_tf32(s[nj][1]));
                Pw[(r + 8) * LDK + colb]     = __float_as_uint(to_tf32(s[nj][2]));
                Pw[(r + 8) * LDK + colb + 1] = __float_as_uint(to_tf32(s[nj][3]));
            }
            __syncwarp();

            // ---- O += P @ V   (V smem [key][e], B-frag [k][n] pattern)
            #pragma unroll
            for (int kk = 0; kk < 8; kk++) {
                uint32_t a0 = Pw[r * LDK + kk * 8 + c];
                uint32_t a1 = Pw[(r + 8) * LDK + kk * 8 + c];
                uint32_t a2 = Pw[r * LDK + kk * 8 + c + 4];
                uint32_t a3 = Pw[(r + 8) * LDK + kk * 8 + c + 4];
                const uint32_t* b0p = Vsu + (kk * 8 + c /*kc*/) * LDV + r;
                const uint32_t* b1p = b0p + 4 * LDV;
                #pragma unroll
                for (int nj = 0; nj < 8; nj++) {
                    mma_tf32(o[nj], a0, a1, a2, a3, b0p[nj * 8], b1p[nj * 8]);
                }
            }
        }

        __syncthreads();           // all warps done with buf before refill
        if (kt + 2 < ntiles) issue_kv(kt + 2, kt & 1);
    }

    // ---- epilogue: normalize + store (tf32 for next GEMM's A operand)
    float inv0 = 1.f / l0, inv1 = 1.f / l1;
    #pragma unroll
    for (int nj = 0; nj < 8; nj++) {
        int col = h * DH + nj * 8 + c * 2;
        size_t g0 = (size_t)(b * SEQ + q0g) * DM + col;
        size_t g1 = (size_t)(b * SEQ + q0g + 8) * DM + col;
        float2 v0, v1;
        v0.x = to_tf32(o[nj][0] * inv0); v0.y = to_tf32(o[nj][1] * inv0);
        v1.x = to_tf32(o[nj][2] * inv1); v1.y = to_tf32(o[nj][3] * inv1);
        *(float2*)(Z + g0) = v0;
        *(float2*)(Z + g1) = v1;
    }
}

// ---------------- launch -----------------------------------------------------
extern "C" void kernel_launch(void* const* d_in, const int* in_sizes, int n_in,
                              void* d_out, int out_size) {
    const float* resid_pre = (const float*)d_in[0];
    const float* W_Q   = (const float*)d_in[1];
    const float* b_Q   = (const float*)d_in[2];
    const float* W_K   = (const float*)d_in[3];
    const float* b_K   = (const float*)d_in[4];
    const float* W_V   = (const float*)d_in[5];
    const float* b_V   = (const float*)d_in[6];
    const float* W_O   = (const float*)d_in[7];
    const float* b_O   = (const float*)d_in[8];
    const float* ln1_w = (const float*)d_in[9];
    const float* ln1_b = (const float*)d_in[10];
    const float* ln2_w = (const float*)d_in[11];
    const float* ln2_b = (const float*)d_in[12];
    const float* W_in  = (const float*)d_in[13];
    const float* b_in  = (const float*)d_in[14];
    const float* W_out = (const float*)d_in[15];
    const float* b_out = (const float*)d_in[16];
    float* out = (float*)d_out;

    float *px, *pwqkv, *pbqkv, *pqkv, *pz, *pmid, *py, *ph;
    cudaGetSymbolAddress((void**)&px,    g_x);
    cudaGetSymbolAddress((void**)&pwqkv, g_wqkv);
    cudaGetSymbolAddress((void**)&pbqkv, g_bqkv);
    cudaGetSymbolAddress((void**)&pqkv,  g_qkv);
    cudaGetSymbolAddress((void**)&pz,    g_z);
    cudaGetSymbolAddress((void**)&pmid,  g_mid);
    cudaGetSymbolAddress((void**)&py,    g_y);
    cudaGetSymbolAddress((void**)&ph,    g_h);

    cudaFuncSetAttribute(gemm_mma<0>, cudaFuncAttributeMaxDynamicSharedMemorySize, GEMM_SMEM);
    cudaFuncSetAttribute(gemm_mma<1>, cudaFuncAttributeMaxDynamicSharedMemorySize, GEMM_SMEM);
    cudaFuncSetAttribute(gemm_mma<2>, cudaFuncAttributeMaxDynamicSharedMemorySize, GEMM_SMEM);
    cudaFuncSetAttribute(attn_mma,    cudaFuncAttributeMaxDynamicSharedMemorySize, ATTN_SMEM);

    pack_qkv<<<(DM * DM + 255) / 256, 256>>>(W_Q, W_K, W_V, b_Q, b_K, b_V, pwqkv, pbqkv);

    ln_kernel<<<ROWS, 256>>>(resid_pre, ln1_w, ln1_b, px);
    gemm_mma<0><<<dim3(QKVN / 128, ROWS / 128), 256, GEMM_SMEM>>>(
        px, pwqkv, pbqkv, nullptr, pqkv, ROWS, QKVN, DM);
    attn_mma<<<dim3(SEQ / 128, NH, BATCH), 256, ATTN_SMEM>>>(pqkv, pz);
    gemm_mma<2><<<dim3(DM / 128, ROWS / 128), 256, GEMM_SMEM>>>(
        pz, W_O, b_O, resid_pre, pmid, ROWS, DM, DM);
    ln_kernel<<<ROWS, 256>>>(pmid, ln2_w, ln2_b, py);
    gemm_mma<1><<<dim3(DMLP / 128, ROWS / 128), 256, GEMM_SMEM>>>(
        py, W_in, b_in, nullptr, ph, ROWS, DMLP, DM);
    gemm_mma<2><<<dim3(DM / 128, ROWS / 128), 256, GEMM_SMEM>>>(
        ph, W_out, b_out, pmid, out, ROWS, DM, DMLP);
}

// round 7
// speedup vs baseline: 5.5360x; 1.0716x over previous
#include <cuda_runtime.h>
#include <cstdint>
#include <math.h>

#define DM    768
#define DMLP  3072
#define NH    12
#define DH    64
#define BATCH 2
#define SEQ   2048
#define ROWS  (BATCH*SEQ)     /* 4096 */
#define QKVN  (3*DM)          /* 2304 */

// ---------------- scratch (static device globals; no allocation) -----------
__device__ float g_x    [ROWS*DM];      // ln1 output (tf32-rounded)
__device__ float g_wqkv [DM*QKVN];      // packed QKV weight, [K=768, N=2304]
__device__ float g_bqkv [QKVN];
__device__ float g_qkv  [ROWS*QKVN];    // Q|K|V per token
__device__ float g_z    [ROWS*DM];      // attention output (tf32-rounded)
__device__ float g_mid  [ROWS*DM];      // resid_mid (fp32)
__device__ float g_y    [ROWS*DM];      // ln2 output (tf32-rounded)
__device__ float g_h    [ROWS*DMLP];    // MLP hidden (tf32-rounded)

// ======================= helpers ============================================
__device__ __forceinline__ uint32_t smem_u32(const void* p) {
    uint32_t a;
    asm("{ .reg .u64 t; cvta.to.shared.u64 t, %1; cvt.u32.u64 %0, t; }"
        : "=r"(a) : "l"(p));
    return a;
}
__device__ __forceinline__ float to_tf32(float x) {
    uint32_t u;
    asm("cvt.rna.tf32.f32 %0, %1;" : "=r"(u) : "f"(x));
    return __uint_as_float(u);
}
__device__ __forceinline__ float gelu_new(float v) {
    float v3 = v * v * v;
    return 0.5f * v * (1.f + tanhf(0.7978845608028654f * (v + 0.044715f * v3)));
}
#define CP_ASYNC16(sa, gp) \
    asm volatile("cp.async.cg.shared.global [%0], [%1], 16;" :: "r"(sa), "l"(gp))
#define CP_COMMIT() asm volatile("cp.async.commit_group;" ::: "memory")
#define CP_WAIT(n)  asm volatile("cp.async.wait_group %0;" :: "n"(n) : "memory")

__device__ __forceinline__ void mma_tf32(float* c, uint32_t a0, uint32_t a1,
                                         uint32_t a2, uint32_t a3,
                                         uint32_t b0, uint32_t b1) {
    asm volatile(
        "mma.sync.aligned.m16n8k8.row.col.f32.tf32.tf32.f32 "
        "{%0,%1,%2,%3}, {%4,%5,%6,%7}, {%8,%9}, {%0,%1,%2,%3};\n"
        : "+f"(c[0]), "+f"(c[1]), "+f"(c[2]), "+f"(c[3])
        : "r"(a0), "r"(a1), "r"(a2), "r"(a3), "r"(b0), "r"(b1));
}

// ====== tf32 mma.sync GEMM: C[M,N] = A[M,K] @ B[K,N]   (B row-major) ========
// BM=128, BN = NJ*16 (NJ=8 -> 128, NJ=4 -> 64). 256 thr / 8 warps (4M x 2N),
// warp tile 32 x NJ*8. 3-stage cp.async pipeline, 1 sync per K-iter.
#define LDA 36
#define A_STAGE (128*LDA)

template<int NJ> struct GemmCfg {
    static const int BN      = NJ * 16;
    static const int LDB_    = BN + 8;
    static const int B_STAGE = 32 * LDB_;
    static const int STAGE   = A_STAGE + B_STAGE;
    static const int SMEM    = 3 * STAGE * 4;
    static const int TB      = BN / 32;          // B chunks per thread
};

template<int EPI, int NJ>   // EPI: 0 = bias, 1 = bias+gelu(tf32), 2 = bias+residual
__global__ __launch_bounds__(256, 2)
void gemm_mma(const float* __restrict__ A, const float* __restrict__ B,
              const float* __restrict__ bias, const float* __restrict__ R,
              float* __restrict__ C, int M, int N, int K) {
    typedef GemmCfg<NJ> CFG;
    extern __shared__ float sm[];
    const uint32_t sbase = smem_u32(sm);
    const int tid = threadIdx.x, lane = tid & 31, wid = tid >> 5;
    const int wm = wid & 3, wn = wid >> 2;
    const int bm = blockIdx.y * 128, bn = blockIdx.x * CFG::BN;
    const int niter = K >> 5;

    int arow[4], acol[4];
    #pragma unroll
    for (int t = 0; t < 4; t++) {
        int ci = tid + t * 256;
        arow[t] = ci >> 3;  acol[t] = (ci & 7) * 4;
    }
    int bkr[CFG::TB], bnc[CFG::TB];
    #pragma unroll
    for (int t = 0; t < CFG::TB; t++) {
        int ci = tid + t * 256;
        bkr[t] = ci / (CFG::BN / 4);
        bnc[t] = (ci % (CFG::BN / 4)) * 4;
    }

    float acc[2][NJ][4];
    #pragma unroll
    for (int mi = 0; mi < 2; mi++)
        #pragma unroll
        for (int nj = 0; nj < NJ; nj++)
            #pragma unroll
            for (int r = 0; r < 4; r++) acc[mi][nj][r] = 0.f;

    auto issue = [&](int ks, int buf) {
        const int k0 = ks << 5;
        const uint32_t s0 = sbase + (uint32_t)buf * CFG::STAGE * 4u;
        #pragma unroll
        for (int t = 0; t < 4; t++)
            CP_ASYNC16(s0 + (uint32_t)(arow[t] * LDA + acol[t]) * 4u,
                       A + (size_t)(bm + arow[t]) * K + k0 + acol[t]);
        const uint32_t s1 = s0 + A_STAGE * 4u;
        #pragma unroll
        for (int t = 0; t < CFG::TB; t++)
            CP_ASYNC16(s1 + (uint32_t)(bkr[t] * CFG::LDB_ + bnc[t]) * 4u,
                       B + (size_t)(k0 + bkr[t]) * N + bn + bnc[t]);
        CP_COMMIT();
    };

    issue(0, 0);
    issue(1, 1);

    for (int i = 0; i < niter; i++) {
        if (i + 1 < niter) { CP_WAIT(1); } else { CP_WAIT(0); }
        __syncthreads();
        if (i + 2 < niter) issue(i + 2, (i + 2) % 3);

        const uint32_t* As = (const uint32_t*)(sm + (i % 3) * CFG::STAGE);
        const uint32_t* Bs = As + A_STAGE;
        const int ar0 = wm * 32 + (lane >> 2);
        const int kc  = lane & 3;
        const int nb  = wn * (NJ * 8) + (lane >> 2);

        #pragma unroll
        for (int kk = 0; kk < 32; kk += 8) {
            uint32_t a[2][4];
            #pragma unroll
            for (int mi = 0; mi < 2; mi++) {
                const uint32_t* ap = As + (ar0 + mi * 16) * LDA + kk + kc;
                a[mi][0] = ap[0];
                a[mi][1] = ap[8 * LDA];
                a[mi][2] = ap[4];
                a[mi][3] = ap[8 * LDA + 4];
            }
            const uint32_t* b0p = Bs + (kk + kc) * CFG::LDB_ + nb;
            const uint32_t* b1p = b0p + 4 * CFG::LDB_;
            #pragma unroll
            for (int nj = 0; nj < NJ; nj++) {
                uint32_t b0 = b0p[nj * 8], b1 = b1p[nj * 8];
                #pragma unroll
                for (int mi = 0; mi < 2; mi++)
                    mma_tf32(acc[mi][nj], a[mi][0], a[mi][1], a[mi][2], a[mi][3], b0, b1);
            }
        }
    }

    #pragma unroll
    for (int mi = 0; mi < 2; mi++) {
        const int row0 = bm + wm * 32 + mi * 16 + (lane >> 2);
        #pragma unroll
        for (int nj = 0; nj < NJ; nj++) {
            const int col0 = bn + wn * (NJ * 8) + nj * 8 + (lane & 3) * 2;
            const float b0 = bias[col0], b1 = bias[col0 + 1];
            #pragma unroll
            for (int h = 0; h < 2; h++) {
                const int row = row0 + h * 8;
                float v0 = acc[mi][nj][h * 2 + 0] + b0;
                float v1 = acc[mi][nj][h * 2 + 1] + b1;
                if (EPI == 1) { v0 = to_tf32(gelu_new(v0)); v1 = to_tf32(gelu_new(v1)); }
                size_t g = (size_t)row * N + col0;
                if (EPI == 2) {
                    float2 rv = *(const float2*)(R + g);
                    v0 += rv.x; v1 += rv.y;
                }
                float2 o; o.x = v0; o.y = v1;
                *(float2*)(C + g) = o;
            }
        }
    }
}

// ---------------- layernorm (tf32-rounded output) ----------------------------
__global__ __launch_bounds__(256)
void ln_kernel(const float* __restrict__ in, const float* __restrict__ w,
               const float* __restrict__ b, float* __restrict__ out) {
    int row = blockIdx.x;
    const float* x = in + (size_t)row * DM;
    float s = 0.f, ss = 0.f;
    for (int i = threadIdx.x; i < DM; i += 256) {
        float v = x[i]; s += v; ss += v * v;
    }
    __shared__ float red0[32], red1[32];
    #pragma unroll
    for (int o = 16; o; o >>= 1) {
        s  += __shfl_xor_sync(0xffffffffu, s,  o);
        ss += __shfl_xor_sync(0xffffffffu, ss, o);
    }
    int warp = threadIdx.x >> 5, lane = threadIdx.x & 31;
    if (lane == 0) { red0[warp] = s; red1[warp] = ss; }
    __syncthreads();
    if (warp == 0) {
        s  = (lane < 8) ? red0[lane] : 0.f;
        ss = (lane < 8) ? red1[lane] : 0.f;
        #pragma unroll
        for (int o = 4; o; o >>= 1) {
            s  += __shfl_xor_sync(0xffffffffu, s,  o);
            ss += __shfl_xor_sync(0xffffffffu, ss, o);
        }
        if (lane == 0) {
            float mean = s / DM;
            float var  = ss / DM - mean * mean;
            red0[0] = mean;
            red1[0] = rsqrtf(var + 1e-5f);
        }
    }
    __syncthreads();
    float mean = red0[0], inv = red1[0];
    for (int i = threadIdx.x; i < DM; i += 256)
        out[(size_t)row * DM + i] = to_tf32((x[i] - mean) * inv * w[i] + b[i]);
}

// ---------------- QKV weight repack to [K=768, N=2304] ----------------------
__global__ void pack_qkv(const float* __restrict__ WQ, const float* __restrict__ WK,
                         const float* __restrict__ WV,
                         const float* __restrict__ bQ, const float* __restrict__ bK,
                         const float* __restrict__ bV,
                         float* __restrict__ Wp, float* __restrict__ bias) {
    int idx = blockIdx.x * 256 + threadIdx.x;
    if (idx < DM * DM) {
        int k = idx / DM, n = idx % DM;
        int h = n >> 6, e = n & 63;
        int src = h * (DM * DH) + k * DH + e;
        Wp[(size_t)k * QKVN + n]            = to_tf32(WQ[src]);
        Wp[(size_t)k * QKVN + DM + n]       = to_tf32(WK[src]);
        Wp[(size_t)k * QKVN + 2 * DM + n]   = to_tf32(WV[src]);
    }
    if (idx < DM) {
        bias[idx]          = bQ[idx];
        bias[DM + idx]     = bK[idx];
        bias[2 * DM + idx] = bV[idx];
    }
}

// ============== flash attention via tf32 mma.sync (causal, cp.async) ========
#define LDK 68
#define LDV 72
#define K_OFF   (128*LDK)
#define V_OFF   (K_OFF + 2*64*LDK)
#define ATTN_F  (V_OFF + 2*64*LDV)
#define ATTN_SMEM (ATTN_F*4)

__global__ __launch_bounds__(256, 2)
void attn_mma(const float* __restrict__ QKV, float* __restrict__ Z) {
    extern __shared__ float sm[];
    const uint32_t sbase = smem_u32(sm);

    const int tid = threadIdx.x, lane = tid & 31, wid = tid >> 5;
    const int r = lane >> 2, c = lane & 3;
    const int qt = gridDim.x - 1 - blockIdx.x;       // heavy blocks first
    const int qt0 = qt * 128;
    const int h = blockIdx.y, b = blockIdx.z;

    const float* qbase = QKV + ((size_t)(b * SEQ + qt0)) * QKVN + h * DH;
    const float* kbase = QKV + ((size_t)b * SEQ) * QKVN + DM     + h * DH;
    const float* vbase = QKV + ((size_t)b * SEQ) * QKVN + 2 * DM + h * DH;

    const int ntiles = qt0 / 64 + 2;

    auto issue_kv = [&](int kt, int buf) {
        const float* kb = kbase + (size_t)(kt * 64) * QKVN;
        const float* vb = vbase + (size_t)(kt * 64) * QKVN;
        const uint32_t ks = sbase + (K_OFF + buf * 64 * LDK) * 4u;
        const uint32_t vs = sbase + (V_OFF + buf * 64 * LDV) * 4u;
        #pragma unroll
        for (int t = 0; t < 4; t++) {
            int ci = tid + t * 256;
            int row = ci >> 4, c16 = ci & 15;
            CP_ASYNC16(ks + (uint32_t)(row * LDK + c16 * 4) * 4u,
                       kb + (size_t)row * QKVN + c16 * 4);
            CP_ASYNC16(vs + (uint32_t)(row * LDV + c16 * 4) * 4u,
                       vb + (size_t)row * QKVN + c16 * 4);
        }
        CP_COMMIT();
    };

    {
        #pragma unroll
        for (int t = 0; t < 8; t++) {
            int ci = tid + t * 256;
            int row = ci >> 4, c16 = ci & 15;
            CP_ASYNC16(sbase + (uint32_t)(row * LDK + c16 * 4) * 4u,
                       qbase + (size_t)row * QKVN + c16 * 4);
        }
        const uint32_t ks = sbase + K_OFF * 4u;
        const uint32_t vs = sbase + V_OFF * 4u;
        #pragma unroll
        for (int t = 0; t < 4; t++) {
            int ci = tid + t * 256;
            int row = ci >> 4, c16 = ci & 15;
            CP_ASYNC16(ks + (uint32_t)(row * LDK + c16 * 4) * 4u,
                       kbase + (size_t)row * QKVN + c16 * 4);
            CP_ASYNC16(vs + (uint32_t)(row * LDV + c16 * 4) * 4u,
                       vbase + (size_t)row * QKVN + c16 * 4);
        }
        CP_COMMIT();
    }
    if (ntiles > 1) issue_kv(1, 1);

    float o[8][4];
    #pragma unroll
    for (int nj = 0; nj < 8; nj++)
        #pragma unroll
        for (int t = 0; t < 4; t++) o[nj][t] = 0.f;
    float m0 = -1e30f, m1 = -1e30f, l0 = 0.f, l1 = 0.f;

    const int q0g = qt0 + wid * 16 + r;
    const int qmax_warp = qt0 + wid * 16 + 15;

    uint32_t qf[8][4];
    uint32_t* Pw = (uint32_t*)(sm + wid * 16 * LDK);

    for (int kt = 0; kt < ntiles; kt++) {
        if (kt + 1 < ntiles) { CP_WAIT(1); } else { CP_WAIT(0); }
        __syncthreads();

        if (kt == 0) {
            const float* Qw = sm + wid * 16 * LDK;
            #pragma unroll
            for (int kk = 0; kk < 8; kk++) {
                qf[kk][0] = __float_as_uint(to_tf32(0.125f * Qw[r * LDK + kk * 8 + c]));
                qf[kk][1] = __float_as_uint(to_tf32(0.125f * Qw[(r + 8) * LDK + kk * 8 + c]));
                qf[kk][2] = __float_as_uint(to_tf32(0.125f * Qw[r * LDK + kk * 8 + c + 4]));
                qf[kk][3] = __float_as_uint(to_tf32(0.125f * Qw[(r + 8) * LDK + kk * 8 + c + 4]));
            }
        }

        if (kt * 64 <= qmax_warp) {
            const int buf = kt & 1;
            const uint32_t* Ksu = (const uint32_t*)(sm + K_OFF + buf * 64 * LDK);
            const uint32_t* Vsu = (const uint32_t*)(sm + V_OFF + buf * 64 * LDV);

            float s[8][4];
            #pragma unroll
            for (int nj = 0; nj < 8; nj++)
                #pragma unroll
                for (int t = 0; t < 4; t++) s[nj][t] = 0.f;
            #pragma unroll
            for (int kk = 0; kk < 8; kk++) {
                #pragma unroll
                for (int nj = 0; nj < 8; nj++) {
                    const uint32_t* bp = Ksu + (nj * 8 + r) * LDK + kk * 8 + c;
                    mma_tf32(s[nj], qf[kk][0], qf[kk][1], qf[kk][2], qf[kk][3],
                             bp[0], bp[4]);
                }
            }

            if (kt * 64 + 63 > qt0 + wid * 16) {
                #pragma unroll
                for (int nj = 0; nj < 8; nj++) {
                    int k0c = kt * 64 + nj * 8 + c * 2;
                    if (k0c     > q0g)     s[nj][0] = -1e30f;
                    if (k0c + 1 > q0g)     s[nj][1] = -1e30f;
                    if (k0c     > q0g + 8) s[nj][2] = -1e30f;
                    if (k0c + 1 > q0g + 8) s[nj][3] = -1e30f;
                }
            }

            float mt0 = -1e30f, mt1 = -1e30f;
            #pragma unroll
            for (int nj = 0; nj < 8; nj++) {
                mt0 = fmaxf(mt0, fmaxf(s[nj][0], s[nj][1]));
                mt1 = fmaxf(mt1, fmaxf(s[nj][2], s[nj][3]));
            }
            mt0 = fmaxf(mt0, __shfl_xor_sync(0xffffffffu, mt0, 1));
            mt0 = fmaxf(mt0, __shfl_xor_sync(0xffffffffu, mt0, 2));
            mt1 = fmaxf(mt1, __shfl_xor_sync(0xffffffffu, mt1, 1));
            mt1 = fmaxf(mt1, __shfl_xor_sync(0xffffffffu, mt1, 2));

            float mn0 = fmaxf(m0, mt0), mn1 = fmaxf(m1, mt1);
            float cr0 = __expf(m0 - mn0), cr1 = __expf(m1 - mn1);
            float ls0 = 0.f, ls1 = 0.f;
            #pragma unroll
            for (int nj = 0; nj < 8; nj++) {
                s[nj][0] = __expf(s[nj][0] - mn0);
                s[nj][1] = __expf(s[nj][1] - mn0);
                s[nj][2] = __expf(s[nj][2] - mn1);
                s[nj][3] = __expf(s[nj][3] - mn1);
                ls0 += s[nj][0] + s[nj][1];
                ls1 += s[nj][2] + s[nj][3];
            }
            ls0 += __shfl_xor_sync(0xffffffffu, ls0, 1);
            ls0 += __shfl_xor_sync(0xffffffffu, ls0, 2);
            ls1 += __shfl_xor_sync(0xffffffffu, ls1, 1);
            ls1 += __shfl_xor_sync(0xffffffffu, ls1, 2);
            l0 = l0 * cr0 + ls0;
            l1 = l1 * cr1 + ls1;
            m0 = mn0; m1 = mn1;
            #pragma unroll
            for (int nj = 0; nj < 8; nj++) {
                o[nj][0] *= cr0; o[nj][1] *= cr0;
                o[nj][2] *= cr1; o[nj][3] *= cr1;
            }

            #pragma unroll
            for (int nj = 0; nj < 8; nj++) {
                int colb = nj * 8 + c * 2;
                Pw[r * LDK + colb]           = __float_as_uint(to_tf32(s[nj][0]));
                Pw[r * LDK + colb + 1]       = __float_as_uint(to_tf32(s[nj][1]));
                Pw[(r + 8) * LDK + colb]     = __float_as_uint(to_tf32(s[nj][2]));
                Pw[(r + 8) * LDK + colb + 1] = __float_as_uint(to_tf32(s[nj][3]));
            }
            __syncwarp();

            #pragma unroll
            for (int kk = 0; kk < 8; kk++) {
                uint32_t a0 = Pw[r * LDK + kk * 8 + c];
                uint32_t a1 = Pw[(r + 8) * LDK + kk * 8 + c];
                uint32_t a2 = Pw[r * LDK + kk * 8 + c + 4];
                uint32_t a3 = Pw[(r + 8) * LDK + kk * 8 + c + 4];
                const uint32_t* b0p = Vsu + (kk * 8 + c) * LDV + r;
                const uint32_t* b1p = b0p + 4 * LDV;
                #pragma unroll
                for (int nj = 0; nj < 8; nj++) {
                    mma_tf32(o[nj], a0, a1, a2, a3, b0p[nj * 8], b1p[nj * 8]);
                }
            }
        }

        __syncthreads();
        if (kt + 2 < ntiles) issue_kv(kt + 2, kt & 1);
    }

    float inv0 = 1.f / l0, inv1 = 1.f / l1;
    #pragma unroll
    for (int nj = 0; nj < 8; nj++) {
        int col = h * DH + nj * 8 + c * 2;
        size_t g0 = (size_t)(b * SEQ + q0g) * DM + col;
        size_t g1 = (size_t)(b * SEQ + q0g + 8) * DM + col;
        float2 v0, v1;
        v0.x = to_tf32(o[nj][0] * inv0); v0.y = to_tf32(o[nj][1] * inv0);
        v1.x = to_tf32(o[nj][2] * inv1); v1.y = to_tf32(o[nj][3] * inv1);
        *(float2*)(Z + g0) = v0;
        *(float2*)(Z + g1) = v1;
    }
}

// ---------------- launch -----------------------------------------------------
extern "C" void kernel_launch(void* const* d_in, const int* in_sizes, int n_in,
                              void* d_out, int out_size) {
    const float* resid_pre = (const float*)d_in[0];
    const float* W_Q   = (const float*)d_in[1];
    const float* b_Q   = (const float*)d_in[2];
    const float* W_K   = (const float*)d_in[3];
    const float* b_K   = (const float*)d_in[4];
    const float* W_V   = (const float*)d_in[5];
    const float* b_V   = (const float*)d_in[6];
    const float* W_O   = (const float*)d_in[7];
    const float* b_O   = (const float*)d_in[8];
    const float* ln1_w = (const float*)d_in[9];
    const float* ln1_b = (const float*)d_in[10];
    const float* ln2_w = (const float*)d_in[11];
    const float* ln2_b = (const float*)d_in[12];
    const float* W_in  = (const float*)d_in[13];
    const float* b_in  = (const float*)d_in[14];
    const float* W_out = (const float*)d_in[15];
    const float* b_out = (const float*)d_in[16];
    float* out = (float*)d_out;

    float *px, *pwqkv, *pbqkv, *pqkv, *pz, *pmid, *py, *ph;
    cudaGetSymbolAddress((void**)&px,    g_x);
    cudaGetSymbolAddress((void**)&pwqkv, g_wqkv);
    cudaGetSymbolAddress((void**)&pbqkv, g_bqkv);
    cudaGetSymbolAddress((void**)&pqkv,  g_qkv);
    cudaGetSymbolAddress((void**)&pz,    g_z);
    cudaGetSymbolAddress((void**)&pmid,  g_mid);
    cudaGetSymbolAddress((void**)&py,    g_y);
    cudaGetSymbolAddress((void**)&ph,    g_h);

    cudaFuncSetAttribute((const void*)gemm_mma<0,8>, cudaFuncAttributeMaxDynamicSharedMemorySize, GemmCfg<8>::SMEM);
    cudaFuncSetAttribute((const void*)gemm_mma<1,8>, cudaFuncAttributeMaxDynamicSharedMemorySize, GemmCfg<8>::SMEM);
    cudaFuncSetAttribute((const void*)gemm_mma<2,4>, cudaFuncAttributeMaxDynamicSharedMemorySize, GemmCfg<4>::SMEM);
    cudaFuncSetAttribute((const void*)attn_mma,      cudaFuncAttributeMaxDynamicSharedMemorySize, ATTN_SMEM);

    pack_qkv<<<(DM * DM + 255) / 256, 256>>>(W_Q, W_K, W_V, b_Q, b_K, b_V, pwqkv, pbqkv);

    ln_kernel<<<ROWS, 256>>>(resid_pre, ln1_w, ln1_b, px);
    // QKV projection: [4096 x 768] @ [768 x 2304], BN=128
    gemm_mma<0,8><<<dim3(QKVN / 128, ROWS / 128), 256, GemmCfg<8>::SMEM>>>(
        px, pwqkv, pbqkv, nullptr, pqkv, ROWS, QKVN, DM);
    attn_mma<<<dim3(SEQ / 128, NH, BATCH), 256, ATTN_SMEM>>>(pqkv, pz);
    // O projection + residual, N=768, BN=64 (384 blocks)
    gemm_mma<2,4><<<dim3(DM / 64, ROWS / 128), 256, GemmCfg<4>::SMEM>>>(
        pz, W_O, b_O, resid_pre, pmid, ROWS, DM, DM);
    ln_kernel<<<ROWS, 256>>>(pmid, ln2_w, ln2_b, py);
    // MLP in + gelu, N=3072, BN=128
    gemm_mma<1,8><<<dim3(DMLP / 128, ROWS / 128), 256, GemmCfg<8>::SMEM>>>(
        py, W_in, b_in, nullptr, ph, ROWS, DMLP, DM);
    // MLP out + residual, N=768, BN=64
    gemm_mma<2,4><<<dim3(DM / 64, ROWS / 128), 256, GemmCfg<4>::SMEM>>>(
        ph, W_out, b_out, pmid, out, ROWS, DM, DMLP);
}

// round 8
// speedup vs baseline: 6.8375x; 1.2351x over previous
#include <cuda_runtime.h>
#include <cuda_fp16.h>
#include <cstdint>
#include <math.h>

#define DM    768
#define DMLP  3072
#define NH    12
#define DH    64
#define BATCH 2
#define SEQ   2048
#define ROWS  (BATCH*SEQ)     /* 4096 */
#define QKVN  (3*DM)          /* 2304 */

// ---------------- scratch (static device globals; no allocation) -----------
__device__ float  g_x    [ROWS*DM];      // ln1 output (tf32-rounded)
__device__ float  g_wqkv [DM*QKVN];      // packed QKV weight, [K=768, N=2304]
__device__ float  g_bqkv [QKVN];
__device__ float  g_qkv  [ROWS*QKVN];    // Q|K|V per token
__device__ float  g_z    [ROWS*DM];      // attention output (tf32-rounded)
__device__ float  g_mid  [ROWS*DM];      // resid_mid (fp32)
__device__ __align__(16) __half g_y_h [ROWS*DM];    // ln2 output (fp16)
__device__ __align__(16) __half g_h_h [ROWS*DMLP];  // MLP hidden (fp16)
__device__ __align__(16) __half g_win_h [DM*DMLP];  // W_in  fp16 [K,N]
__device__ __align__(16) __half g_wout_h[DMLP*DM];  // W_out fp16 [K,N]

// ======================= helpers ============================================
__device__ __forceinline__ uint32_t smem_u32(const void* p) {
    uint32_t a;
    asm("{ .reg .u64 t; cvta.to.shared.u64 t, %1; cvt.u32.u64 %0, t; }"
        : "=r"(a) : "l"(p));
    return a;
}
__device__ __forceinline__ float to_tf32(float x) {
    uint32_t u;
    asm("cvt.rna.tf32.f32 %0, %1;" : "=r"(u) : "f"(x));
    return __uint_as_float(u);
}
__device__ __forceinline__ float gelu_new(float v) {
    float v3 = v * v * v;
    return 0.5f * v * (1.f + tanhf(0.7978845608028654f * (v + 0.044715f * v3)));
}
#define CP_ASYNC16(sa, gp) \
    asm volatile("cp.async.cg.shared.global [%0], [%1], 16;" :: "r"(sa), "l"(gp))
#define CP_COMMIT() asm volatile("cp.async.commit_group;" ::: "memory")
#define CP_WAIT(n)  asm volatile("cp.async.wait_group %0;" :: "n"(n) : "memory")

#define LDMX4(r, addr) \
    asm volatile("ldmatrix.sync.aligned.m8n8.x4.shared.b16 {%0,%1,%2,%3}, [%4];" \
        : "=r"((r)[0]), "=r"((r)[1]), "=r"((r)[2]), "=r"((r)[3]) : "r"(addr))
#define LDMX4T(r, addr) \
    asm volatile("ldmatrix.sync.aligned.m8n8.x4.trans.shared.b16 {%0,%1,%2,%3}, [%4];" \
        : "=r"((r)[0]), "=r"((r)[1]), "=r"((r)[2]), "=r"((r)[3]) : "r"(addr))

__device__ __forceinline__ void mma_tf32(float* c, uint32_t a0, uint32_t a1,
                                         uint32_t a2, uint32_t a3,
                                         uint32_t b0, uint32_t b1) {
    asm volatile(
        "mma.sync.aligned.m16n8k8.row.col.f32.tf32.tf32.f32 "
        "{%0,%1,%2,%3}, {%4,%5,%6,%7}, {%8,%9}, {%0,%1,%2,%3};\n"
        : "+f"(c[0]), "+f"(c[1]), "+f"(c[2]), "+f"(c[3])
        : "r"(a0), "r"(a1), "r"(a2), "r"(a3), "r"(b0), "r"(b1));
}
__device__ __forceinline__ void mma_f16(float* c, const uint32_t* a,
                                        uint32_t b0, uint32_t b1) {
    asm volatile(
        "mma.sync.aligned.m16n8k16.row.col.f32.f16.f16.f32 "
        "{%0,%1,%2,%3}, {%4,%5,%6,%7}, {%8,%9}, {%0,%1,%2,%3};\n"
        : "+f"(c[0]), "+f"(c[1]), "+f"(c[2]), "+f"(c[3])
        : "r"(a[0]), "r"(a[1]), "r"(a[2]), "r"(a[3]), "r"(b0), "r"(b1));
}

// ====== tf32 mma.sync GEMM: C[M,N] = A[M,K] @ B[K,N]   (B row-major) ========
#define LDA 36
#define A_STAGE (128*LDA)

template<int NJ> struct GemmCfg {
    static const int BN      = NJ * 16;
    static const int LDB_    = BN + 8;
    static const int B_STAGE = 32 * LDB_;
    static const int STAGE   = A_STAGE + B_STAGE;
    static const int SMEM    = 3 * STAGE * 4;
    static const int TB      = BN / 32;
};

template<int EPI, int NJ>   // EPI: 0 = bias, 2 = bias+residual
__global__ __launch_bounds__(256, 2)
void gemm_mma(const float* __restrict__ A, const float* __restrict__ B,
              const float* __restrict__ bias, const float* __restrict__ R,
              float* __restrict__ C, int M, int N, int K) {
    typedef GemmCfg<NJ> CFG;
    extern __shared__ float sm[];
    const uint32_t sbase = smem_u32(sm);
    const int tid = threadIdx.x, lane = tid & 31, wid = tid >> 5;
    const int wm = wid & 3, wn = wid >> 2;
    const int bm = blockIdx.y * 128, bn = blockIdx.x * CFG::BN;
    const int niter = K >> 5;

    int arow[4], acol[4];
    #pragma unroll
    for (int t = 0; t < 4; t++) {
        int ci = tid + t * 256;
        arow[t] = ci >> 3;  acol[t] = (ci & 7) * 4;
    }
    int bkr[CFG::TB], bnc[CFG::TB];
    #pragma unroll
    for (int t = 0; t < CFG::TB; t++) {
        int ci = tid + t * 256;
        bkr[t] = ci / (CFG::BN / 4);
        bnc[t] = (ci % (CFG::BN / 4)) * 4;
    }

    float acc[2][NJ][4];
    #pragma unroll
    for (int mi = 0; mi < 2; mi++)
        #pragma unroll
        for (int nj = 0; nj < NJ; nj++)
            #pragma unroll
            for (int r = 0; r < 4; r++) acc[mi][nj][r] = 0.f;

    auto issue = [&](int ks, int buf) {
        const int k0 = ks << 5;
        const uint32_t s0 = sbase + (uint32_t)buf * CFG::STAGE * 4u;
        #pragma unroll
        for (int t = 0; t < 4; t++)
            CP_ASYNC16(s0 + (uint32_t)(arow[t] * LDA + acol[t]) * 4u,
                       A + (size_t)(bm + arow[t]) * K + k0 + acol[t]);
        const uint32_t s1 = s0 + A_STAGE * 4u;
        #pragma unroll
        for (int t = 0; t < CFG::TB; t++)
            CP_ASYNC16(s1 + (uint32_t)(bkr[t] * CFG::LDB_ + bnc[t]) * 4u,
                       B + (size_t)(k0 + bkr[t]) * N + bn + bnc[t]);
        CP_COMMIT();
    };

    issue(0, 0);
    issue(1, 1);

    for (int i = 0; i < niter; i++) {
        if (i + 1 < niter) { CP_WAIT(1); } else { CP_WAIT(0); }
        __syncthreads();
        if (i + 2 < niter) issue(i + 2, (i + 2) % 3);

        const uint32_t* As = (const uint32_t*)(sm + (i % 3) * CFG::STAGE);
        const uint32_t* Bs = As + A_STAGE;
        const int ar0 = wm * 32 + (lane >> 2);
        const int kc  = lane & 3;
        const int nb  = wn * (NJ * 8) + (lane >> 2);

        #pragma unroll
        for (int kk = 0; kk < 32; kk += 8) {
            uint32_t a[2][4];
            #pragma unroll
            for (int mi = 0; mi < 2; mi++) {
                const uint32_t* ap = As + (ar0 + mi * 16) * LDA + kk + kc;
                a[mi][0] = ap[0];
                a[mi][1] = ap[8 * LDA];
                a[mi][2] = ap[4];
                a[mi][3] = ap[8 * LDA + 4];
            }
            const uint32_t* b0p = Bs + (kk + kc) * CFG::LDB_ + nb;
            const uint32_t* b1p = b0p + 4 * CFG::LDB_;
            #pragma unroll
            for (int nj = 0; nj < NJ; nj++) {
                uint32_t b0 = b0p[nj * 8], b1 = b1p[nj * 8];
                #pragma unroll
                for (int mi = 0; mi < 2; mi++)
                    mma_tf32(acc[mi][nj], a[mi][0], a[mi][1], a[mi][2], a[mi][3], b0, b1);
            }
        }
    }

    #pragma unroll
    for (int mi = 0; mi < 2; mi++) {
        const int row0 = bm + wm * 32 + mi * 16 + (lane >> 2);
        #pragma unroll
        for (int nj = 0; nj < NJ; nj++) {
            const int col0 = bn + wn * (NJ * 8) + nj * 8 + (lane & 3) * 2;
            const float b0 = bias[col0], b1 = bias[col0 + 1];
            #pragma unroll
            for (int h = 0; h < 2; h++) {
                const int row = row0 + h * 8;
                float v0 = acc[mi][nj][h * 2 + 0] + b0;
                float v1 = acc[mi][nj][h * 2 + 1] + b1;
                size_t g = (size_t)row * N + col0;
                if (EPI == 2) {
                    float2 rv = *(const float2*)(R + g);
                    v0 += rv.x; v1 += rv.y;
                }
                float2 o; o.x = v0; o.y = v1;
                *(float2*)(C + g) = o;
            }
        }
    }
}

// ====== fp16 mma.sync GEMM (ldmatrix): C[M,N] = A[M,K] @ B[K,N] =============
// BM=BN=128, BK=32, 8 warps (4M x 2N), warp tile 32x64, m16n8k16.
#define LDAH 40      /* halves per A smem row (80B; conflict-free ldmatrix) */
#define LDBH 136     /* halves per B smem row (272B) */
#define AH_STAGE (128*LDAH)
#define BH_STAGE (32*LDBH)
#define STAGE_H  (AH_STAGE + BH_STAGE)
#define GEMMH_SMEM (3*STAGE_H*2)

template<int EPI>   // 1 = bias+gelu -> half out ; 2 = bias+residual -> float out
__global__ __launch_bounds__(256, 2)
void gemm_h(const __half* __restrict__ A, const __half* __restrict__ B,
            const float* __restrict__ bias, const float* __restrict__ R,
            void* __restrict__ Cout, int M, int N, int K) {
    extern __shared__ __half smh[];
    const uint32_t sbase = smem_u32(smh);
    const int tid = threadIdx.x, lane = tid & 31, wid = tid >> 5;
    const int wm = wid & 3, wn = wid >> 2;
    const int bm = blockIdx.y * 128, bn = blockIdx.x * 128;
    const int niter = K >> 5;

    // load slots: A 2 chunks/thread (128 rows x 4 chunks of 8 halves)
    //             B 2 chunks/thread (32 rows x 16 chunks)
    int ar[2], ac[2], br[2], bc[2];
    #pragma unroll
    for (int t = 0; t < 2; t++) {
        int ci = tid + t * 256;
        ar[t] = ci >> 2;  ac[t] = (ci & 3) * 8;
        br[t] = ci >> 4;  bc[t] = (ci & 15) * 8;
    }

    float acc[2][8][4];
    #pragma unroll
    for (int mi = 0; mi < 2; mi++)
        #pragma unroll
        for (int nj = 0; nj < 8; nj++)
            #pragma unroll
            for (int r = 0; r < 4; r++) acc[mi][nj][r] = 0.f;

    auto issue = [&](int ks, int buf) {
        const int k0 = ks << 5;
        const uint32_t s0 = sbase + (uint32_t)buf * STAGE_H * 2u;
        #pragma unroll
        for (int t = 0; t < 2; t++)
            CP_ASYNC16(s0 + (uint32_t)(ar[t] * LDAH + ac[t]) * 2u,
                       A + (size_t)(bm + ar[t]) * K + k0 + ac[t]);
        const uint32_t s1 = s0 + AH_STAGE * 2u;
        #pragma unroll
        for (int t = 0; t < 2; t++)
            CP_ASYNC16(s1 + (uint32_t)(br[t] * LDBH + bc[t]) * 2u,
                       B + (size_t)(k0 + br[t]) * N + bn + bc[t]);
        CP_COMMIT();
    };

    issue(0, 0);
    issue(1, 1);

    // ldmatrix per-thread address components
    const int l15 = lane & 15, lhi = (lane >> 4);   // lhi: 0/1 selects +8 cols
    // A: rows (wm*32 + mi*16 + l15), col halves = kk*16 + lhi*8
    const uint32_t aAddrBase = (uint32_t)(((wm * 32 + l15) * LDAH + lhi * 8) * 2);
    // B: rows kk*16 + l15, col halves = wn*64 + nj2*16 + lhi*8
    const uint32_t bAddrBase = (uint32_t)((l15 * LDBH + wn * 64 + lhi * 8) * 2);

    for (int i = 0; i < niter; i++) {
        if (i + 1 < niter) { CP_WAIT(1); } else { CP_WAIT(0); }
        __syncthreads();
        if (i + 2 < niter) issue(i + 2, (i + 2) % 3);

        const uint32_t sA = sbase + (uint32_t)((i % 3) * STAGE_H) * 2u;
        const uint32_t sB = sA + AH_STAGE * 2u;

        #pragma unroll
        for (int kk = 0; kk < 2; kk++) {                 // two k16 chunks
            uint32_t a[2][4];
            #pragma unroll
            for (int mi = 0; mi < 2; mi++)
                LDMX4(a[mi], sA + aAddrBase + (uint32_t)((mi * 16 * LDAH + kk * 16) * 2));
            uint32_t bf[4][4];
            #pragma unroll
            for (int nj2 = 0; nj2 < 4; nj2++)
                LDMX4T(bf[nj2], sB + bAddrBase + (uint32_t)((kk * 16 * LDBH + nj2 * 16) * 2));
            #pragma unroll
            for (int nj2 = 0; nj2 < 4; nj2++) {
                #pragma unroll
                for (int hh = 0; hh < 2; hh++) {
                    uint32_t b0 = bf[nj2][hh * 2], b1 = bf[nj2][hh * 2 + 1];
                    #pragma unroll
                    for (int mi = 0; mi < 2; mi++)
                        mma_f16(acc[mi][nj2 * 2 + hh], a[mi], b0, b1);
                }
            }
        }
    }

    #pragma unroll
    for (int mi = 0; mi < 2; mi++) {
        const int row0 = bm + wm * 32 + mi * 16 + (lane >> 2);
        #pragma unroll
        for (int nj = 0; nj < 8; nj++) {
            const int col0 = bn + wn * 64 + nj * 8 + (lane & 3) * 2;
            const float b0 = bias[col0], b1 = bias[col0 + 1];
            #pragma unroll
            for (int hh = 0; hh < 2; hh++) {
                const int row = row0 + hh * 8;
                float v0 = acc[mi][nj][hh * 2 + 0] + b0;
                float v1 = acc[mi][nj][hh * 2 + 1] + b1;
                size_t g = (size_t)row * N + col0;
                if (EPI == 1) {
                    v0 = gelu_new(v0); v1 = gelu_new(v1);
                    __half2 hv = __floats2half2_rn(v0, v1);
                    *(__half2*)((__half*)Cout + g) = hv;
                } else {
                    float2 rv = *(const float2*)(R + g);
                    float2 o; o.x = v0 + rv.x; o.y = v1 + rv.y;
                    *(float2*)((float*)Cout + g) = o;
                }
            }
        }
    }
}

// ---------------- layernorms -------------------------------------------------
__global__ __launch_bounds__(256)
void ln_kernel(const float* __restrict__ in, const float* __restrict__ w,
               const float* __restrict__ b, float* __restrict__ out) {
    int row = blockIdx.x;
    const float* x = in + (size_t)row * DM;
    float s = 0.f, ss = 0.f;
    for (int i = threadIdx.x; i < DM; i += 256) {
        float v = x[i]; s += v; ss += v * v;
    }
    __shared__ float red0[32], red1[32];
    #pragma unroll
    for (int o = 16; o; o >>= 1) {
        s  += __shfl_xor_sync(0xffffffffu, s,  o);
        ss += __shfl_xor_sync(0xffffffffu, ss, o);
    }
    int warp = threadIdx.x >> 5, lane = threadIdx.x & 31;
    if (lane == 0) { red0[warp] = s; red1[warp] = ss; }
    __syncthreads();
    if (warp == 0) {
        s  = (lane < 8) ? red0[lane] : 0.f;
        ss = (lane < 8) ? red1[lane] : 0.f;
        #pragma unroll
        for (int o = 4; o; o >>= 1) {
            s  += __shfl_xor_sync(0xffffffffu, s,  o);
            ss += __shfl_xor_sync(0xffffffffu, ss, o);
        }
        if (lane == 0) {
            float mean = s / DM;
            float var  = ss / DM - mean * mean;
            red0[0] = mean;
            red1[0] = rsqrtf(var + 1e-5f);
        }
    }
    __syncthreads();
    float mean = red0[0], inv = red1[0];
    for (int i = threadIdx.x; i < DM; i += 256)
        out[(size_t)row * DM + i] = to_tf32((x[i] - mean) * inv * w[i] + b[i]);
}

__global__ __launch_bounds__(256)
void ln_kernel_h(const float* __restrict__ in, const float* __restrict__ w,
                 const float* __restrict__ b, __half* __restrict__ out) {
    int row = blockIdx.x;
    const float* x = in + (size_t)row * DM;
    float s = 0.f, ss = 0.f;
    for (int i = threadIdx.x; i < DM; i += 256) {
        float v = x[i]; s += v; ss += v * v;
    }
    __shared__ float red0[32], red1[32];
    #pragma unroll
    for (int o = 16; o; o >>= 1) {
        s  += __shfl_xor_sync(0xffffffffu, s,  o);
        ss += __shfl_xor_sync(0xffffffffu, ss, o);
    }
    int warp = threadIdx.x >> 5, lane = threadIdx.x & 31;
    if (lane == 0) { red0[warp] = s; red1[warp] = ss; }
    __syncthreads();
    if (warp == 0) {
        s  = (lane < 8) ? red0[lane] : 0.f;
        ss = (lane < 8) ? red1[lane] : 0.f;
        #pragma unroll
        for (int o = 4; o; o >>= 1) {
            s  += __shfl_xor_sync(0xffffffffu, s,  o);
            ss += __shfl_xor_sync(0xffffffffu, ss, o);
        }
        if (lane == 0) {
            float mean = s / DM;
            float var  = ss / DM - mean * mean;
            red0[0] = mean;
            red1[0] = rsqrtf(var + 1e-5f);
        }
    }
    __syncthreads();
    float mean = red0[0], inv = red1[0];
    for (int i = threadIdx.x; i < DM; i += 256)
        out[(size_t)row * DM + i] = __float2half_rn((x[i] - mean) * inv * w[i] + b[i]);
}

// ---------------- weight preps ------------------------------------------------
__global__ void pack_qkv(const float* __restrict__ WQ, const float* __restrict__ WK,
                         const float* __restrict__ WV,
                         const float* __restrict__ bQ, const float* __restrict__ bK,
                         const float* __restrict__ bV,
                         float* __restrict__ Wp, float* __restrict__ bias) {
    int idx = blockIdx.x * 256 + threadIdx.x;
    if (idx < DM * DM) {
        int k = idx / DM, n = idx % DM;
        int h = n >> 6, e = n & 63;
        int src = h * (DM * DH) + k * DH + e;
        Wp[(size_t)k * QKVN + n]            = to_tf32(WQ[src]);
        Wp[(size_t)k * QKVN + DM + n]       = to_tf32(WK[src]);
        Wp[(size_t)k * QKVN + 2 * DM + n]   = to_tf32(WV[src]);
    }
    if (idx < DM) {
        bias[idx]          = bQ[idx];
        bias[DM + idx]     = bK[idx];
        bias[2 * DM + idx] = bV[idx];
    }
}

__global__ void cvt_half2(const float* __restrict__ a, __half* __restrict__ oa,
                          const float* __restrict__ b, __half* __restrict__ ob,
                          int n) {
    int i = blockIdx.x * 256 + threadIdx.x;
    if (i < n) { oa[i] = __float2half_rn(a[i]); ob[i] = __float2half_rn(b[i]); }
}

// ============== flash attention via tf32 mma.sync (causal, cp.async) ========
#define LDK 68
#define LDV 72
#define K_OFF   (128*LDK)
#define V_OFF   (K_OFF + 2*64*LDK)
#define ATTN_F  (V_OFF + 2*64*LDV)
#define ATTN_SMEM (ATTN_F*4)

__global__ __launch_bounds__(256, 2)
void attn_mma(const float* __restrict__ QKV, float* __restrict__ Z) {
    extern __shared__ float sm[];
    const uint32_t sbase = smem_u32(sm);

    const int tid = threadIdx.x, lane = tid & 31, wid = tid >> 5;
    const int r = lane >> 2, c = lane & 3;
    const int qt = gridDim.x - 1 - blockIdx.x;
    const int qt0 = qt * 128;
    const int h = blockIdx.y, b = blockIdx.z;

    const float* qbase = QKV + ((size_t)(b * SEQ + qt0)) * QKVN + h * DH;
    const float* kbase = QKV + ((size_t)b * SEQ) * QKVN + DM     + h * DH;
    const float* vbase = QKV + ((size_t)b * SEQ) * QKVN + 2 * DM + h * DH;

    const int ntiles = qt0 / 64 + 2;

    auto issue_kv = [&](int kt, int buf) {
        const float* kb = kbase + (size_t)(kt * 64) * QKVN;
        const float* vb = vbase + (size_t)(kt * 64) * QKVN;
        const uint32_t ks = sbase + (K_OFF + buf * 64 * LDK) * 4u;
        const uint32_t vs = sbase + (V_OFF + buf * 64 * LDV) * 4u;
        #pragma unroll
        for (int t = 0; t < 4; t++) {
            int ci = tid + t * 256;
            int row = ci >> 4, c16 = ci & 15;
            CP_ASYNC16(ks + (uint32_t)(row * LDK + c16 * 4) * 4u,
                       kb + (size_t)row * QKVN + c16 * 4);
            CP_ASYNC16(vs + (uint32_t)(row * LDV + c16 * 4) * 4u,
                       vb + (size_t)row * QKVN + c16 * 4);
        }
        CP_COMMIT();
    };

    {
        #pragma unroll
        for (int t = 0; t < 8; t++) {
            int ci = tid + t * 256;
            int row = ci >> 4, c16 = ci & 15;
            CP_ASYNC16(sbase + (uint32_t)(row * LDK + c16 * 4) * 4u,
                       qbase + (size_t)row * QKVN + c16 * 4);
        }
        const uint32_t ks = sbase + K_OFF * 4u;
        const uint32_t vs = sbase + V_OFF * 4u;
        #pragma unroll
        for (int t = 0; t < 4; t++) {
            int ci = tid + t * 256;
            int row = ci >> 4, c16 = ci & 15;
            CP_ASYNC16(ks + (uint32_t)(row * LDK + c16 * 4) * 4u,
                       kbase + (size_t)row * QKVN + c16 * 4);
            CP_ASYNC16(vs + (uint32_t)(row * LDV + c16 * 4) * 4u,
                       vbase + (size_t)row * QKVN + c16 * 4);
        }
        CP_COMMIT();
    }
    if (ntiles > 1) issue_kv(1, 1);

    float o[8][4];
    #pragma unroll
    for (int nj = 0; nj < 8; nj++)
        #pragma unroll
        for (int t = 0; t < 4; t++) o[nj][t] = 0.f;
    float m0 = -1e30f, m1 = -1e30f, l0 = 0.f, l1 = 0.f;

    const int q0g = qt0 + wid * 16 + r;
    const int qmax_warp = qt0 + wid * 16 + 15;

    uint32_t qf[8][4];
    uint32_t* Pw = (uint32_t*)(sm + wid * 16 * LDK);

    for (int kt = 0; kt < ntiles; kt++) {
        if (kt + 1 < ntiles) { CP_WAIT(1); } else { CP_WAIT(0); }
        __syncthreads();

        if (kt == 0) {
            const float* Qw = sm + wid * 16 * LDK;
            #pragma unroll
            for (int kk = 0; kk < 8; kk++) {
                qf[kk][0] = __float_as_uint(to_tf32(0.125f * Qw[r * LDK + kk * 8 + c]));
                qf[kk][1] = __float_as_uint(to_tf32(0.125f * Qw[(r + 8) * LDK + kk * 8 + c]));
                qf[kk][2] = __float_as_uint(to_tf32(0.125f * Qw[r * LDK + kk * 8 + c + 4]));
                qf[kk][3] = __float_as_uint(to_tf32(0.125f * Qw[(r + 8) * LDK + kk * 8 + c + 4]));
            }
        }

        if (kt * 64 <= qmax_warp) {
            const int buf = kt & 1;
            const uint32_t* Ksu = (const uint32_t*)(sm + K_OFF + buf * 64 * LDK);
            const uint32_t* Vsu = (const uint32_t*)(sm + V_OFF + buf * 64 * LDV);

            float s[8][4];
            #pragma unroll
            for (int nj = 0; nj < 8; nj++)
                #pragma unroll
                for (int t = 0; t < 4; t++) s[nj][t] = 0.f;
            #pragma unroll
            for (int kk = 0; kk < 8; kk++) {
                #pragma unroll
                for (int nj = 0; nj < 8; nj++) {
                    const uint32_t* bp = Ksu + (nj * 8 + r) * LDK + kk * 8 + c;
                    mma_tf32(s[nj], qf[kk][0], qf[kk][1], qf[kk][2], qf[kk][3],
                             bp[0], bp[4]);
                }
            }

            if (kt * 64 + 63 > qt0 + wid * 16) {
                #pragma unroll
                for (int nj = 0; nj < 8; nj++) {
                    int k0c = kt * 64 + nj * 8 + c * 2;
                    if (k0c     > q0g)     s[nj][0] = -1e30f;
                    if (k0c + 1 > q0g)     s[nj][1] = -1e30f;
                    if (k0c     > q0g + 8) s[nj][2] = -1e30f;
                    if (k0c + 1 > q0g + 8) s[nj][3] = -1e30f;
                }
            }

            float mt0 = -1e30f, mt1 = -1e30f;
            #pragma unroll
            for (int nj = 0; nj < 8; nj++) {
                mt0 = fmaxf(mt0, fmaxf(s[nj][0], s[nj][1]));
                mt1 = fmaxf(mt1, fmaxf(s[nj][2], s[nj][3]));
            }
            mt0 = fmaxf(mt0, __shfl_xor_sync(0xffffffffu, mt0, 1));
            mt0 = fmaxf(mt0, __shfl_xor_sync(0xffffffffu, mt0, 2));
            mt1 = fmaxf(mt1, __shfl_xor_sync(0xffffffffu, mt1, 1));
            mt1 = fmaxf(mt1, __shfl_xor_sync(0xffffffffu, mt1, 2));

            float mn0 = fmaxf(m0, mt0), mn1 = fmaxf(m1, mt1);
            float cr0 = __expf(m0 - mn0), cr1 = __expf(m1 - mn1);
            float ls0 = 0.f, ls1 = 0.f;
            #pragma unroll
            for (int nj = 0; nj < 8; nj++) {
                s[nj][0] = __expf(s[nj][0] - mn0);
                s[nj][1] = __expf(s[nj][1] - mn0);
                s[nj][2] = __expf(s[nj][2] - mn1);
                s[nj][3] = __expf(s[nj][3] - mn1);
                ls0 += s[nj][0] + s[nj][1];
                ls1 += s[nj][2] + s[nj][3];
            }
            ls0 += __shfl_xor_sync(0xffffffffu, ls0, 1);
            ls0 += __shfl_xor_sync(0xffffffffu, ls0, 2);
            ls1 += __shfl_xor_sync(0xffffffffu, ls1, 1);
            ls1 += __shfl_xor_sync(0xffffffffu, ls1, 2);
            l0 = l0 * cr0 + ls0;
            l1 = l1 * cr1 + ls1;
            m0 = mn0; m1 = mn1;
            #pragma unroll
            for (int nj = 0; nj < 8; nj++) {
                o[nj][0] *= cr0; o[nj][1] *= cr0;
                o[nj][2] *= cr1; o[nj][3] *= cr1;
            }

            #pragma unroll
            for (int nj = 0; nj < 8; nj++) {
                int colb = nj * 8 + c * 2;
                Pw[r * LDK + colb]           = __float_as_uint(to_tf32(s[nj][0]));
                Pw[r * LDK + colb + 1]       = __float_as_uint(to_tf32(s[nj][1]));
                Pw[(r + 8) * LDK + colb]     = __float_as_uint(to_tf32(s[nj][2]));
                Pw[(r + 8) * LDK + colb + 1] = __float_as_uint(to_tf32(s[nj][3]));
            }
            __syncwarp();

            #pragma unroll
            for (int kk = 0; kk < 8; kk++) {
                uint32_t a0 = Pw[r * LDK + kk * 8 + c];
                uint32_t a1 = Pw[(r + 8) * LDK + kk * 8 + c];
                uint32_t a2 = Pw[r * LDK + kk * 8 + c + 4];
                uint32_t a3 = Pw[(r + 8) * LDK + kk * 8 + c + 4];
                const uint32_t* b0p = Vsu + (kk * 8 + c) * LDV + r;
                const uint32_t* b1p = b0p + 4 * LDV;
                #pragma unroll
                for (int nj = 0; nj < 8; nj++) {
                    mma_tf32(o[nj], a0, a1, a2, a3, b0p[nj * 8], b1p[nj * 8]);
                }
            }
        }

        __syncthreads();
        if (kt + 2 < ntiles) issue_kv(kt + 2, kt & 1);
    }

    float inv0 = 1.f / l0, inv1 = 1.f / l1;
    #pragma unroll
    for (int nj = 0; nj < 8; nj++) {
        int col = h * DH + nj * 8 + c * 2;
        size_t g0 = (size_t)(b * SEQ + q0g) * DM + col;
        size_t g1 = (size_t)(b * SEQ + q0g + 8) * DM + col;
        float2 v0, v1;
        v0.x = to_tf32(o[nj][0] * inv0); v0.y = to_tf32(o[nj][1] * inv0);
        v1.x = to_tf32(o[nj][2] * inv1); v1.y = to_tf32(o[nj][3] * inv1);
        *(float2*)(Z + g0) = v0;
        *(float2*)(Z + g1) = v1;
    }
}

// ---------------- launch -----------------------------------------------------
extern "C" void kernel_launch(void* const* d_in, const int* in_sizes, int n_in,
                              void* d_out, int out_size) {
    const float* resid_pre = (const float*)d_in[0];
    const float* W_Q   = (const float*)d_in[1];
    const float* b_Q   = (const float*)d_in[2];
    const float* W_K   = (const float*)d_in[3];
    const float* b_K   = (const float*)d_in[4];
    const float* W_V   = (const float*)d_in[5];
    const float* b_V   = (const float*)d_in[6];
    const float* W_O   = (const float*)d_in[7];
    const float* b_O   = (const float*)d_in[8];
    const float* ln1_w = (const float*)d_in[9];
    const float* ln1_b = (const float*)d_in[10];
    const float* ln2_w = (const float*)d_in[11];
    const float* ln2_b = (const float*)d_in[12];
    const float* W_in  = (const float*)d_in[13];
    const float* b_in  = (const float*)d_in[14];
    const float* W_out = (const float*)d_in[15];
    const float* b_out = (const float*)d_in[16];
    float* out = (float*)d_out;

    float *px, *pwqkv, *pbqkv, *pqkv, *pz, *pmid;
    __half *py_h, *ph_h, *pwin_h, *pwout_h;
    cudaGetSymbolAddress((void**)&px,     g_x);
    cudaGetSymbolAddress((void**)&pwqkv,  g_wqkv);
    cudaGetSymbolAddress((void**)&pbqkv,  g_bqkv);
    cudaGetSymbolAddress((void**)&pqkv,   g_qkv);
    cudaGetSymbolAddress((void**)&pz,     g_z);
    cudaGetSymbolAddress((void**)&pmid,   g_mid);
    cudaGetSymbolAddress((void**)&py_h,   g_y_h);
    cudaGetSymbolAddress((void**)&ph_h,   g_h_h);
    cudaGetSymbolAddress((void**)&pwin_h, g_win_h);
    cudaGetSymbolAddress((void**)&pwout_h,g_wout_h);

    cudaFuncSetAttribute((const void*)gemm_mma<0,8>, cudaFuncAttributeMaxDynamicSharedMemorySize, GemmCfg<8>::SMEM);
    cudaFuncSetAttribute((const void*)gemm_mma<2,4>, cudaFuncAttributeMaxDynamicSharedMemorySize, GemmCfg<4>::SMEM);
    cudaFuncSetAttribute((const void*)gemm_h<1>,     cudaFuncAttributeMaxDynamicSharedMemorySize, GEMMH_SMEM);
    cudaFuncSetAttribute((const void*)gemm_h<2>,     cudaFuncAttributeMaxDynamicSharedMemorySize, GEMMH_SMEM);
    cudaFuncSetAttribute((const void*)attn_mma,      cudaFuncAttributeMaxDynamicSharedMemorySize, ATTN_SMEM);

    pack_qkv<<<(DM * DM + 255) / 256, 256>>>(W_Q, W_K, W_V, b_Q, b_K, b_V, pwqkv, pbqkv);
    cvt_half2<<<(DM * DMLP + 255) / 256, 256>>>(W_in, pwin_h, W_out, pwout_h, DM * DMLP);

    ln_kernel<<<ROWS, 256>>>(resid_pre, ln1_w, ln1_b, px);
    gemm_mma<0,8><<<dim3(QKVN / 128, ROWS / 128), 256, GemmCfg<8>::SMEM>>>(
        px, pwqkv, pbqkv, nullptr, pqkv, ROWS, QKVN, DM);
    attn_mma<<<dim3(SEQ / 128, NH, BATCH), 256, ATTN_SMEM>>>(pqkv, pz);
    gemm_mma<2,4><<<dim3(DM / 64, ROWS / 128), 256, GemmCfg<4>::SMEM>>>(
        pz, W_O, b_O, resid_pre, pmid, ROWS, DM, DM);
    ln_kernel_h<<<ROWS, 256>>>(pmid, ln2_w, ln2_b, py_h);
    // MLP in + gelu (fp16 ldmatrix GEMM) -> h fp16
    gemm_h<1><<<dim3(DMLP / 128, ROWS / 128), 256, GEMMH_SMEM>>>(
        py_h, pwin_h, b_in, nullptr, ph_h, ROWS, DMLP, DM);
    // MLP out + residual (fp16) -> fp32 out
    gemm_h<2><<<dim3(DM / 128, ROWS / 128), 256, GEMMH_SMEM>>>(
        ph_h, pwout_h, b_out, pmid, out, ROWS, DM, DMLP);
}

// round 9
// speedup vs baseline: 9.2369x; 1.3509x over previous
#include <cuda_runtime.h>
#include <cuda_fp16.h>
#include <cstdint>
#include <math.h>

#define DM    768
#define DMLP  3072
#define NH    12
#define DH    64
#define BATCH 2
#define SEQ   2048
#define ROWS  (BATCH*SEQ)     /* 4096 */
#define QKVN  (3*DM)          /* 2304 */

// ---------------- scratch (static device globals; no allocation) -----------
__device__ __align__(16) __half g_x_h   [ROWS*DM];     // ln1 output
__device__ __align__(16) __half g_wqkv_h[DM*QKVN];     // packed QKV W [K,N]
__device__ float g_bqkv [QKVN];
__device__ __align__(16) __half g_qkv_h [ROWS*QKVN];   // Q|K|V per token
__device__ __align__(16) __half g_z_h   [ROWS*DM];     // attention output
__device__ float g_mid  [ROWS*DM];                     // resid_mid (fp32)
__device__ __align__(16) __half g_y_h   [ROWS*DM];     // ln2 output
__device__ __align__(16) __half g_h_h   [ROWS*DMLP];   // MLP hidden
__device__ __align__(16) __half g_wo_h  [DM*DM];       // W_O   fp16 [K,N]
__device__ __align__(16) __half g_win_h [DM*DMLP];     // W_in  fp16 [K,N]
__device__ __align__(16) __half g_wout_h[DMLP*DM];     // W_out fp16 [K,N]

// ======================= helpers ============================================
__device__ __forceinline__ uint32_t smem_u32(const void* p) {
    uint32_t a;
    asm("{ .reg .u64 t; cvta.to.shared.u64 t, %1; cvt.u32.u64 %0, t; }"
        : "=r"(a) : "l"(p));
    return a;
}
__device__ __forceinline__ float gelu_new(float v) {
    float v3 = v * v * v;
    return 0.5f * v * (1.f + tanhf(0.7978845608028654f * (v + 0.044715f * v3)));
}
__device__ __forceinline__ uint32_t pack_h2(float a, float b) {
    __half2 h = __floats2half2_rn(a, b);
    return *reinterpret_cast<uint32_t*>(&h);
}
#define CP_ASYNC16(sa, gp) \
    asm volatile("cp.async.cg.shared.global [%0], [%1], 16;" :: "r"(sa), "l"(gp))
#define CP_COMMIT() asm volatile("cp.async.commit_group;" ::: "memory")
#define CP_WAIT(n)  asm volatile("cp.async.wait_group %0;" :: "n"(n) : "memory")

#define LDMX4(r, addr) \
    asm volatile("ldmatrix.sync.aligned.m8n8.x4.shared.b16 {%0,%1,%2,%3}, [%4];" \
        : "=r"((r)[0]), "=r"((r)[1]), "=r"((r)[2]), "=r"((r)[3]) : "r"(addr))
#define LDMX4T(r, addr) \
    asm volatile("ldmatrix.sync.aligned.m8n8.x4.trans.shared.b16 {%0,%1,%2,%3}, [%4];" \
        : "=r"((r)[0]), "=r"((r)[1]), "=r"((r)[2]), "=r"((r)[3]) : "r"(addr))

__device__ __forceinline__ void mma_f16(float* c, const uint32_t* a,
                                        uint32_t b0, uint32_t b1) {
    asm volatile(
        "mma.sync.aligned.m16n8k16.row.col.f32.f16.f16.f32 "
        "{%0,%1,%2,%3}, {%4,%5,%6,%7}, {%8,%9}, {%0,%1,%2,%3};\n"
        : "+f"(c[0]), "+f"(c[1]), "+f"(c[2]), "+f"(c[3])
        : "r"(a[0]), "r"(a[1]), "r"(a[2]), "r"(a[3]), "r"(b0), "r"(b1));
}

// ====== fp16 mma.sync GEMM (ldmatrix): C[M,N] = A[M,K] @ B[K,N] =============
// BM=128, BN=NJ*16; 8 warps (4M x 2N), warp tile 32 x NJ*8, m16n8k16.
#define LDAH 40
#define AH_STAGE (128*LDAH)

template<int NJ> struct GemmHCfg {
    static const int BN      = NJ * 16;
    static const int LDBH_   = BN + 8;
    static const int B_STAGE = 32 * LDBH_;
    static const int STAGE   = AH_STAGE + B_STAGE;
    static const int SMEM    = 3 * STAGE * 2;
    static const int TBH     = BN / 64;           // B chunks per thread
};

// EPI: 0 = bias -> half out, 1 = bias+gelu -> half out, 2 = bias+residual -> float out
template<int EPI, int NJ>
__global__ __launch_bounds__(256, 2)
void gemm_h(const __half* __restrict__ A, const __half* __restrict__ B,
            const float* __restrict__ bias, const float* __restrict__ R,
            void* __restrict__ Cout, int M, int N, int K) {
    typedef GemmHCfg<NJ> CFG;
    extern __shared__ __half smh[];
    const uint32_t sbase = smem_u32(smh);
    const int tid = threadIdx.x, lane = tid & 31, wid = tid >> 5;
    const int wm = wid & 3, wn = wid >> 2;
    const int bm = blockIdx.y * 128, bn = blockIdx.x * CFG::BN;
    const int niter = K >> 5;

    int ar[2], ac[2];
    #pragma unroll
    for (int t = 0; t < 2; t++) {
        int ci = tid + t * 256;
        ar[t] = ci >> 2;  ac[t] = (ci & 3) * 8;
    }
    int br[CFG::TBH], bc[CFG::TBH];
    #pragma unroll
    for (int t = 0; t < CFG::TBH; t++) {
        int ci = tid + t * 256;
        br[t] = ci / (CFG::BN / 8);
        bc[t] = (ci % (CFG::BN / 8)) * 8;
    }

    float acc[2][NJ][4];
    #pragma unroll
    for (int mi = 0; mi < 2; mi++)
        #pragma unroll
        for (int nj = 0; nj < NJ; nj++)
            #pragma unroll
            for (int r = 0; r < 4; r++) acc[mi][nj][r] = 0.f;

    auto issue = [&](int ks, int buf) {
        const int k0 = ks << 5;
        const uint32_t s0 = sbase + (uint32_t)buf * CFG::STAGE * 2u;
        #pragma unroll
        for (int t = 0; t < 2; t++)
            CP_ASYNC16(s0 + (uint32_t)(ar[t] * LDAH + ac[t]) * 2u,
                       A + (size_t)(bm + ar[t]) * K + k0 + ac[t]);
        const uint32_t s1 = s0 + AH_STAGE * 2u;
        #pragma unroll
        for (int t = 0; t < CFG::TBH; t++)
            CP_ASYNC16(s1 + (uint32_t)(br[t] * CFG::LDBH_ + bc[t]) * 2u,
                       B + (size_t)(k0 + br[t]) * N + bn + bc[t]);
        CP_COMMIT();
    };

    issue(0, 0);
    issue(1, 1);

    const int l15 = lane & 15, lhi = lane >> 4;
    const uint32_t aAddrBase = (uint32_t)(((wm * 32 + l15) * LDAH + lhi * 8) * 2);
    const uint32_t bAddrBase = (uint32_t)((l15 * CFG::LDBH_ + wn * (NJ * 8) + lhi * 8) * 2);

    for (int i = 0; i < niter; i++) {
        if (i + 1 < niter) { CP_WAIT(1); } else { CP_WAIT(0); }
        __syncthreads();
        if (i + 2 < niter) issue(i + 2, (i + 2) % 3);

        const uint32_t sA = sbase + (uint32_t)((i % 3) * CFG::STAGE) * 2u;
        const uint32_t sB = sA + AH_STAGE * 2u;

        #pragma unroll
        for (int kk = 0; kk < 2; kk++) {
            uint32_t a[2][4];
            #pragma unroll
            for (int mi = 0; mi < 2; mi++)
                LDMX4(a[mi], sA + aAddrBase + (uint32_t)((mi * 16 * LDAH + kk * 16) * 2));
            #pragma unroll
            for (int nj2 = 0; nj2 < NJ / 2; nj2++) {
                uint32_t bf[4];
                LDMX4T(bf, sB + bAddrBase + (uint32_t)((kk * 16 * CFG::LDBH_ + nj2 * 16) * 2));
                #pragma unroll
                for (int hh = 0; hh < 2; hh++) {
                    #pragma unroll
                    for (int mi = 0; mi < 2; mi++)
                        mma_f16(acc[mi][nj2 * 2 + hh], a[mi], bf[hh * 2], bf[hh * 2 + 1]);
                }
            }
        }
    }

    #pragma unroll
    for (int mi = 0; mi < 2; mi++) {
        const int row0 = bm + wm * 32 + mi * 16 + (lane >> 2);
        #pragma unroll
        for (int nj = 0; nj < NJ; nj++) {
            const int col0 = bn + wn * (NJ * 8) + nj * 8 + (lane & 3) * 2;
            const float b0 = bias[col0], b1 = bias[col0 + 1];
            #pragma unroll
            for (int hh = 0; hh < 2; hh++) {
                const int row = row0 + hh * 8;
                float v0 = acc[mi][nj][hh * 2 + 0] + b0;
                float v1 = acc[mi][nj][hh * 2 + 1] + b1;
                size_t g = (size_t)row * N + col0;
                if (EPI == 0) {
                    __half2 hv = __floats2half2_rn(v0, v1);
                    *(__half2*)((__half*)Cout + g) = hv;
                } else if (EPI == 1) {
                    __half2 hv = __floats2half2_rn(gelu_new(v0), gelu_new(v1));
                    *(__half2*)((__half*)Cout + g) = hv;
                } else {
                    float2 rv = *(const float2*)(R + g);
                    float2 o; o.x = v0 + rv.x; o.y = v1 + rv.y;
                    *(float2*)((float*)Cout + g) = o;
                }
            }
        }
    }
}

// ---------------- layernorm (fp16 output) -----------------------------------
__global__ __launch_bounds__(256)
void ln_kernel_h(const float* __restrict__ in, const float* __restrict__ w,
                 const float* __restrict__ b, __half* __restrict__ out) {
    int row = blockIdx.x;
    const float* x = in + (size_t)row * DM;
    float s = 0.f, ss = 0.f;
    for (int i = threadIdx.x; i < DM; i += 256) {
        float v = x[i]; s += v; ss += v * v;
    }
    __shared__ float red0[32], red1[32];
    #pragma unroll
    for (int o = 16; o; o >>= 1) {
        s  += __shfl_xor_sync(0xffffffffu, s,  o);
        ss += __shfl_xor_sync(0xffffffffu, ss, o);
    }
    int warp = threadIdx.x >> 5, lane = threadIdx.x & 31;
    if (lane == 0) { red0[warp] = s; red1[warp] = ss; }
    __syncthreads();
    if (warp == 0) {
        s  = (lane < 8) ? red0[lane] : 0.f;
        ss = (lane < 8) ? red1[lane] : 0.f;
        #pragma unroll
        for (int o = 4; o; o >>= 1) {
            s  += __shfl_xor_sync(0xffffffffu, s,  o);
            ss += __shfl_xor_sync(0xffffffffu, ss, o);
        }
        if (lane == 0) {
            float mean = s / DM;
            float var  = ss / DM - mean * mean;
            red0[0] = mean;
            red1[0] = rsqrtf(var + 1e-5f);
        }
    }
    __syncthreads();
    float mean = red0[0], inv = red1[0];
    for (int i = threadIdx.x; i < DM; i += 256)
        out[(size_t)row * DM + i] = __float2half_rn((x[i] - mean) * inv * w[i] + b[i]);
}

// ---------------- weight preps ----------------------------------------------
__global__ void pack_qkv(const float* __restrict__ WQ, const float* __restrict__ WK,
                         const float* __restrict__ WV,
                         const float* __restrict__ bQ, const float* __restrict__ bK,
                         const float* __restrict__ bV,
                         __half* __restrict__ Wp, float* __restrict__ bias) {
    int idx = blockIdx.x * 256 + threadIdx.x;
    if (idx < DM * DM) {
        int k = idx / DM, n = idx % DM;
        int h = n >> 6, e = n & 63;
        int src = h * (DM * DH) + k * DH + e;
        Wp[(size_t)k * QKVN + n]            = __float2half_rn(WQ[src]);
        Wp[(size_t)k * QKVN + DM + n]       = __float2half_rn(WK[src]);
        Wp[(size_t)k * QKVN + 2 * DM + n]   = __float2half_rn(WV[src]);
    }
    if (idx < DM) {
        bias[idx]          = bQ[idx];
        bias[DM + idx]     = bK[idx];
        bias[2 * DM + idx] = bV[idx];
    }
}

__global__ void cvt_half(const float* __restrict__ a, __half* __restrict__ oa, int n) {
    int i = blockIdx.x * 256 + threadIdx.x;
    if (i < n) oa[i] = __float2half_rn(a[i]);
}
__global__ void cvt_half2(const float* __restrict__ a, __half* __restrict__ oa,
                          const float* __restrict__ b, __half* __restrict__ ob, int n) {
    int i = blockIdx.x * 256 + threadIdx.x;
    if (i < n) { oa[i] = __float2half_rn(a[i]); ob[i] = __float2half_rn(b[i]); }
}

// ============== flash attention via fp16 mma.sync (causal, cp.async) ========
// CTA 256 thr / 8 warps; Q tile 128 rows (16/warp); K/V tile 64 keys, 2 bufs.
// All fp16 in smem, pad 72 halves/row. P built from S C-frags in registers.
#define LDH 72
#define AK_OFF (128*LDH)                 /* 9216 halves */
#define AV_OFF (AK_OFF + 2*64*LDH)       /* 18432 */
#define ATTNH_SMEM ((AV_OFF + 2*64*LDH)*2)   /* 55296 bytes */

__global__ __launch_bounds__(256, 2)
void attn_h(const __half* __restrict__ QKV, __half* __restrict__ Z) {
    extern __shared__ __half smh[];
    const uint32_t sbase = smem_u32(smh);

    const int tid = threadIdx.x, lane = tid & 31, wid = tid >> 5;
    const int r = lane >> 2, c = lane & 3;
    const int l15 = lane & 15, lhi = lane >> 4;
    const int qt = gridDim.x - 1 - blockIdx.x;       // heavy blocks first
    const int qt0 = qt * 128;
    const int h = blockIdx.y, b = blockIdx.z;

    const __half* qbase = QKV + ((size_t)(b * SEQ + qt0)) * QKVN + h * DH;
    const __half* kbase = QKV + ((size_t)b * SEQ) * QKVN + DM     + h * DH;
    const __half* vbase = QKV + ((size_t)b * SEQ) * QKVN + 2 * DM + h * DH;

    const int ntiles = qt0 / 64 + 2;

    auto issue_kv = [&](int kt, int buf) {
        const __half* kb = kbase + (size_t)(kt * 64) * QKVN;
        const __half* vb = vbase + (size_t)(kt * 64) * QKVN;
        const uint32_t ks = sbase + (uint32_t)(AK_OFF + buf * 64 * LDH) * 2u;
        const uint32_t vs = sbase + (uint32_t)(AV_OFF + buf * 64 * LDH) * 2u;
        #pragma unroll
        for (int t = 0; t < 2; t++) {
            int ci = tid + t * 256;                 // 0..511
            int row = ci >> 3, ch = (ci & 7) * 8;
            CP_ASYNC16(ks + (uint32_t)(row * LDH + ch) * 2u,
                       kb + (size_t)row * QKVN + ch);
            CP_ASYNC16(vs + (uint32_t)(row * LDH + ch) * 2u,
                       vb + (size_t)row * QKVN + ch);
        }
        CP_COMMIT();
    };

    {   // group 0: Q + KV tile 0
        #pragma unroll
        for (int t = 0; t < 4; t++) {
            int ci = tid + t * 256;                 // 0..1023
            int row = ci >> 3, ch = (ci & 7) * 8;
            CP_ASYNC16(sbase + (uint32_t)(row * LDH + ch) * 2u,
                       qbase + (size_t)row * QKVN + ch);
        }
        const uint32_t ks = sbase + (uint32_t)AK_OFF * 2u;
        const uint32_t vs = sbase + (uint32_t)AV_OFF * 2u;
        #pragma unroll
        for (int t = 0; t < 2; t++) {
            int ci = tid + t * 256;
            int row = ci >> 3, ch = (ci & 7) * 8;
            CP_ASYNC16(ks + (uint32_t)(row * LDH + ch) * 2u,
                       kbase + (size_t)row * QKVN + ch);
            CP_ASYNC16(vs + (uint32_t)(row * LDH + ch) * 2u,
                       vbase + (size_t)row * QKVN + ch);
        }
        CP_COMMIT();
    }
    if (ntiles > 1) issue_kv(1, 1);

    float o[8][4];
    #pragma unroll
    for (int nj = 0; nj < 8; nj++)
        #pragma unroll
        for (int t = 0; t < 4; t++) o[nj][t] = 0.f;
    float m0 = -1e30f, m1 = -1e30f, l0 = 0.f, l1 = 0.f;

    const int q0g = qt0 + wid * 16 + r;
    const int qmax_warp = qt0 + wid * 16 + 15;

    uint32_t qa[4][4];

    for (int kt = 0; kt < ntiles; kt++) {
        if (kt + 1 < ntiles) { CP_WAIT(1); } else { CP_WAIT(0); }
        __syncthreads();

        if (kt == 0) {
            // Q A-fragments, scaled by 1/8
            const uint32_t qaddr = sbase + (uint32_t)(((wid * 16 + l15) * LDH + lhi * 8) * 2);
            __half2 sc = __floats2half2_rn(0.125f, 0.125f);
            #pragma unroll
            for (int kk = 0; kk < 4; kk++) {
                LDMX4(qa[kk], qaddr + (uint32_t)(kk * 16 * 2));
                #pragma unroll
                for (int j = 0; j < 4; j++) {
                    __half2 v = *reinterpret_cast<__half2*>(&qa[kk][j]);
                    v = __hmul2(v, sc);
                    qa[kk][j] = *reinterpret_cast<uint32_t*>(&v);
                }
            }
        }

        if (kt * 64 <= qmax_warp) {
            const int buf = kt & 1;
            const uint32_t Kb = sbase + (uint32_t)(AK_OFF + buf * 64 * LDH) * 2u;
            const uint32_t Vb = sbase + (uint32_t)(AV_OFF + buf * 64 * LDH) * 2u;

            // ---- S = Q @ K^T   (K [key][e]; non-trans ldmatrix gives B-frags)
            float s[8][4];
            #pragma unroll
            for (int nj = 0; nj < 8; nj++)
                #pragma unroll
                for (int t = 0; t < 4; t++) s[nj][t] = 0.f;

            const int g = lane >> 3;   // 0..3
            #pragma unroll
            for (int g2 = 0; g2 < 4; g2++) {
                const uint32_t rowb = Kb +
                    (uint32_t)(((16 * g2 + (g >> 1) * 8 + (lane & 7)) * LDH) * 2);
                #pragma unroll
                for (int kk = 0; kk < 4; kk++) {
                    uint32_t bk[4];
                    LDMX4(bk, rowb + (uint32_t)((kk * 16 + (g & 1) * 8) * 2));
                    mma_f16(s[2 * g2],     qa[kk], bk[0], bk[1]);
                    mma_f16(s[2 * g2 + 1], qa[kk], bk[2], bk[3]);
                }
            }

            // ---- causal mask
            if (kt * 64 + 63 > qt0 + wid * 16) {
                #pragma unroll
                for (int nj = 0; nj < 8; nj++) {
                    int k0c = kt * 64 + nj * 8 + c * 2;
                    if (k0c     > q0g)     s[nj][0] = -1e30f;
                    if (k0c + 1 > q0g)     s[nj][1] = -1e30f;
                    if (k0c     > q0g + 8) s[nj][2] = -1e30f;
                    if (k0c + 1 > q0g + 8) s[nj][3] = -1e30f;
                }
            }

            // ---- online softmax
            float mt0 = -1e30f, mt1 = -1e30f;
            #pragma unroll
            for (int nj = 0; nj < 8; nj++) {
                mt0 = fmaxf(mt0, fmaxf(s[nj][0], s[nj][1]));
                mt1 = fmaxf(mt1, fmaxf(s[nj][2], s[nj][3]));
            }
            mt0 = fmaxf(mt0, __shfl_xor_sync(0xffffffffu, mt0, 1));
            mt0 = fmaxf(mt0, __shfl_xor_sync(0xffffffffu, mt0, 2));
            mt1 = fmaxf(mt1, __shfl_xor_sync(0xffffffffu, mt1, 1));
            mt1 = fmaxf(mt1, __shfl_xor_sync(0xffffffffu, mt1, 2));

            float mn0 = fmaxf(m0, mt0), mn1 = fmaxf(m1, mt1);
            float cr0 = __expf(m0 - mn0), cr1 = __expf(m1 - mn1);
            float ls0 = 0.f, ls1 = 0.f;
            #pragma unroll
            for (int nj = 0; nj < 8; nj++) {
                s[nj][0] = __expf(s[nj][0] - mn0);
                s[nj][1] = __expf(s[nj][1] - mn0);
                s[nj][2] = __expf(s[nj][2] - mn1);
                s[nj][3] = __expf(s[nj][3] - mn1);
                ls0 += s[nj][0] + s[nj][1];
                ls1 += s[nj][2] + s[nj][3];
            }
            ls0 += __shfl_xor_sync(0xffffffffu, ls0, 1);
            ls0 += __shfl_xor_sync(0xffffffffu, ls0, 2);
            ls1 += __shfl_xor_sync(0xffffffffu, ls1, 1);
            ls1 += __shfl_xor_sync(0xffffffffu, ls1, 2);
            l0 = l0 * cr0 + ls0;
            l1 = l1 * cr1 + ls1;
            m0 = mn0; m1 = mn1;
            #pragma unroll
            for (int nj = 0; nj < 8; nj++) {
                o[nj][0] *= cr0; o[nj][1] *= cr0;
                o[nj][2] *= cr1; o[nj][3] *= cr1;
            }

            // ---- O += P @ V : P A-frags packed from S C-frags in registers
            #pragma unroll
            for (int kk = 0; kk < 4; kk++) {
                uint32_t pa[4];
                pa[0] = pack_h2(s[2 * kk][0],     s[2 * kk][1]);
                pa[1] = pack_h2(s[2 * kk][2],     s[2 * kk][3]);
                pa[2] = pack_h2(s[2 * kk + 1][0], s[2 * kk + 1][1]);
                pa[3] = pack_h2(s[2 * kk + 1][2], s[2 * kk + 1][3]);
                const uint32_t rowb = Vb + (uint32_t)(((kk * 16 + l15) * LDH + lhi * 8) * 2);
                #pragma unroll
                for (int nj2 = 0; nj2 < 4; nj2++) {
                    uint32_t bv[4];
                    LDMX4T(bv, rowb + (uint32_t)((nj2 * 16) * 2));
                    mma_f16(o[2 * nj2],     pa, bv[0], bv[1]);
                    mma_f16(o[2 * nj2 + 1], pa, bv[2], bv[3]);
                }
            }
        }

        __syncthreads();
        if (kt + 2 < ntiles) issue_kv(kt + 2, kt & 1);
    }

    // ---- epilogue: normalize + store fp16
    float inv0 = 1.f / l0, inv1 = 1.f / l1;
    #pragma unroll
    for (int nj = 0; nj < 8; nj++) {
        int col = h * DH + nj * 8 + c * 2;
        size_t g0 = (size_t)(b * SEQ + q0g) * DM + col;
        size_t g1 = (size_t)(b * SEQ + q0g + 8) * DM + col;
        __half2 v0 = __floats2half2_rn(o[nj][0] * inv0, o[nj][1] * inv0);
        __half2 v1 = __floats2half2_rn(o[nj][2] * inv1, o[nj][3] * inv1);
        *(__half2*)(Z + g0) = v0;
        *(__half2*)(Z + g1) = v1;
    }
}

// ---------------- launch -----------------------------------------------------
extern "C" void kernel_launch(void* const* d_in, const int* in_sizes, int n_in,
                              void* d_out, int out_size) {
    const float* resid_pre = (const float*)d_in[0];
    const float* W_Q   = (const float*)d_in[1];
    const float* b_Q   = (const float*)d_in[2];
    const float* W_K   = (const float*)d_in[3];
    const float* b_K   = (const float*)d_in[4];
    const float* W_V   = (const float*)d_in[5];
    const float* b_V   = (const float*)d_in[6];
    const float* W_O   = (const float*)d_in[7];
    const float* b_O   = (const float*)d_in[8];
    const float* ln1_w = (const float*)d_in[9];
    const float* ln1_b = (const float*)d_in[10];
    const float* ln2_w = (const float*)d_in[11];
    const float* ln2_b = (const float*)d_in[12];
    const float* W_in  = (const float*)d_in[13];
    const float* b_in  = (const float*)d_in[14];
    const float* W_out = (const float*)d_in[15];
    const float* b_out = (const float*)d_in[16];
    float* out = (float*)d_out;

    float *pbqkv, *pmid;
    __half *px_h, *pwqkv_h, *pqkv_h, *pz_h, *py_h, *ph_h, *pwo_h, *pwin_h, *pwout_h;
    cudaGetSymbolAddress((void**)&px_h,    g_x_h);
    cudaGetSymbolAddress((void**)&pwqkv_h, g_wqkv_h);
    cudaGetSymbolAddress((void**)&pbqkv,   g_bqkv);
    cudaGetSymbolAddress((void**)&pqkv_h,  g_qkv_h);
    cudaGetSymbolAddress((void**)&pz_h,    g_z_h);
    cudaGetSymbolAddress((void**)&pmid,    g_mid);
    cudaGetSymbolAddress((void**)&py_h,    g_y_h);
    cudaGetSymbolAddress((void**)&ph_h,    g_h_h);
    cudaGetSymbolAddress((void**)&pwo_h,   g_wo_h);
    cudaGetSymbolAddress((void**)&pwin_h,  g_win_h);
    cudaGetSymbolAddress((void**)&pwout_h, g_wout_h);

    cudaFuncSetAttribute((const void*)gemm_h<0,8>, cudaFuncAttributeMaxDynamicSharedMemorySize, GemmHCfg<8>::SMEM);
    cudaFuncSetAttribute((const void*)gemm_h<1,8>, cudaFuncAttributeMaxDynamicSharedMemorySize, GemmHCfg<8>::SMEM);
    cudaFuncSetAttribute((const void*)gemm_h<2,4>, cudaFuncAttributeMaxDynamicSharedMemorySize, GemmHCfg<4>::SMEM);
    cudaFuncSetAttribute((const void*)attn_h,      cudaFuncAttributeMaxDynamicSharedMemorySize, ATTNH_SMEM);

    pack_qkv<<<(DM * DM + 255) / 256, 256>>>(W_Q, W_K, W_V, b_Q, b_K, b_V, pwqkv_h, pbqkv);
    cvt_half<<<(DM * DM + 255) / 256, 256>>>(W_O, pwo_h, DM * DM);
    cvt_half2<<<(DM * DMLP + 255) / 256, 256>>>(W_in, pwin_h, W_out, pwout_h, DM * DMLP);

    ln_kernel_h<<<ROWS, 256>>>(resid_pre, ln1_w, ln1_b, px_h);
    // QKV projection: [4096x768] @ [768x2304] -> fp16
    gemm_h<0,8><<<dim3(QKVN / 128, ROWS / 128), 256, GemmHCfg<8>::SMEM>>>(
        px_h, pwqkv_h, pbqkv, nullptr, pqkv_h, ROWS, QKVN, DM);
    attn_h<<<dim3(SEQ / 128, NH, BATCH), 256, ATTNH_SMEM>>>(pqkv_h, pz_h);
    // O projection + residual -> fp32 mid
    gemm_h<2,4><<<dim3(DM / 64, ROWS / 128), 256, GemmHCfg<4>::SMEM>>>(
        pz_h, pwo_h, b_O, resid_pre, pmid, ROWS, DM, DM);
    ln_kernel_h<<<ROWS, 256>>>(pmid, ln2_w, ln2_b, py_h);
    // MLP in + gelu -> fp16
    gemm_h<1,8><<<dim3(DMLP / 128, ROWS / 128), 256, GemmHCfg<8>::SMEM>>>(
        py_h, pwin_h, b_in, nullptr, ph_h, ROWS, DMLP, DM);
    // MLP out + residual -> fp32 out
    gemm_h<2,4><<<dim3(DM / 64, ROWS / 128), 256, GemmHCfg<4>::SMEM>>>(
        ph_h, pwout_h, b_out, pmid, out, ROWS, DM, DMLP);
}

// round 10
// speedup vs baseline: 9.6567x; 1.0455x over previous
#include <cuda_runtime.h>
#include <cuda_fp16.h>
#include <cstdint>
#include <math.h>

#define DM    768
#define DMLP  3072
#define NH    12
#define DH    64
#define BATCH 2
#define SEQ   2048
#define ROWS  (BATCH*SEQ)     /* 4096 */
#define QKVN  (3*DM)          /* 2304 */

// ---------------- scratch (static device globals; no allocation) -----------
__device__ __align__(16) __half g_x_h   [ROWS*DM];     // ln1 output
__device__ __align__(16) __half g_wqkv_h[DM*QKVN];     // packed QKV W [K,N]
__device__ float g_bqkv [QKVN];
__device__ __align__(16) __half g_qkv_h [ROWS*QKVN];   // Q|K|V per token
__device__ __align__(16) __half g_z_h   [ROWS*DM];     // attention output
__device__ float g_mid  [ROWS*DM];                     // resid_mid (fp32)
__device__ __align__(16) __half g_y_h   [ROWS*DM];     // ln2 output
__device__ __align__(16) __half g_h_h   [ROWS*DMLP];   // MLP hidden
__device__ __align__(16) __half g_wo_h  [DM*DM];       // W_O   fp16 [K,N]
__device__ __align__(16) __half g_win_h [DM*DMLP];     // W_in  fp16 [K,N]
__device__ __align__(16) __half g_wout_h[DMLP*DM];     // W_out fp16 [K,N]

// ======================= helpers ============================================
__device__ __forceinline__ uint32_t smem_u32(const void* p) {
    uint32_t a;
    asm("{ .reg .u64 t; cvta.to.shared.u64 t, %1; cvt.u32.u64 %0, t; }"
        : "=r"(a) : "l"(p));
    return a;
}
__device__ __forceinline__ float gelu_new(float v) {
    float v3 = v * v * v;
    return 0.5f * v * (1.f + tanhf(0.7978845608028654f * (v + 0.044715f * v3)));
}
__device__ __forceinline__ uint32_t pack_h2(float a, float b) {
    __half2 h = __floats2half2_rn(a, b);
    return *reinterpret_cast<uint32_t*>(&h);
}
#define CP_ASYNC16(sa, gp) \
    asm volatile("cp.async.cg.shared.global [%0], [%1], 16;" :: "r"(sa), "l"(gp))
#define CP_COMMIT() asm volatile("cp.async.commit_group;" ::: "memory")
#define CP_WAIT(n)  asm volatile("cp.async.wait_group %0;" :: "n"(n) : "memory")

#define LDMX4(r, addr) \
    asm volatile("ldmatrix.sync.aligned.m8n8.x4.shared.b16 {%0,%1,%2,%3}, [%4];" \
        : "=r"((r)[0]), "=r"((r)[1]), "=r"((r)[2]), "=r"((r)[3]) : "r"(addr))
#define LDMX4T(r, addr) \
    asm volatile("ldmatrix.sync.aligned.m8n8.x4.trans.shared.b16 {%0,%1,%2,%3}, [%4];" \
        : "=r"((r)[0]), "=r"((r)[1]), "=r"((r)[2]), "=r"((r)[3]) : "r"(addr))

__device__ __forceinline__ void mma_f16(float* c, const uint32_t* a,
                                        uint32_t b0, uint32_t b1) {
    asm volatile(
        "mma.sync.aligned.m16n8k16.row.col.f32.f16.f16.f32 "
        "{%0,%1,%2,%3}, {%4,%5,%6,%7}, {%8,%9}, {%0,%1,%2,%3};\n"
        : "+f"(c[0]), "+f"(c[1]), "+f"(c[2]), "+f"(c[3])
        : "r"(a[0]), "r"(a[1]), "r"(a[2]), "r"(a[3]), "r"(b0), "r"(b1));
}

// ====== fp16 mma.sync GEMM (ldmatrix): C[M,N] = A[M,K] @ B[K,N] =============
#define LDAH 40
#define AH_STAGE (128*LDAH)

template<int NJ> struct GemmHCfg {
    static const int BN      = NJ * 16;
    static const int LDBH_   = BN + 8;
    static const int B_STAGE = 32 * LDBH_;
    static const int STAGE   = AH_STAGE + B_STAGE;
    static const int SMEM    = 3 * STAGE * 2;
    static const int TBH     = BN / 64;
};

// EPI: 0 = bias->half, 1 = bias+gelu->half, 2 = bias+residual->float
template<int EPI, int NJ>
__global__ __launch_bounds__(256, 2)
void gemm_h(const __half* __restrict__ A, const __half* __restrict__ B,
            const float* __restrict__ bias, const float* __restrict__ R,
            void* __restrict__ Cout, int M, int N, int K) {
    typedef GemmHCfg<NJ> CFG;
    extern __shared__ __half smh[];
    const uint32_t sbase = smem_u32(smh);
    const int tid = threadIdx.x, lane = tid & 31, wid = tid >> 5;
    const int wm = wid & 3, wn = wid >> 2;
    const int bm = blockIdx.y * 128, bn = blockIdx.x * CFG::BN;
    const int niter = K >> 5;

    int ar[2], ac[2];
    #pragma unroll
    for (int t = 0; t < 2; t++) {
        int ci = tid + t * 256;
        ar[t] = ci >> 2;  ac[t] = (ci & 3) * 8;
    }
    int br[CFG::TBH], bc[CFG::TBH];
    #pragma unroll
    for (int t = 0; t < CFG::TBH; t++) {
        int ci = tid + t * 256;
        br[t] = ci / (CFG::BN / 8);
        bc[t] = (ci % (CFG::BN / 8)) * 8;
    }

    float acc[2][NJ][4];
    #pragma unroll
    for (int mi = 0; mi < 2; mi++)
        #pragma unroll
        for (int nj = 0; nj < NJ; nj++)
            #pragma unroll
            for (int r = 0; r < 4; r++) acc[mi][nj][r] = 0.f;

    auto issue = [&](int ks, int buf) {
        const int k0 = ks << 5;
        const uint32_t s0 = sbase + (uint32_t)buf * CFG::STAGE * 2u;
        #pragma unroll
        for (int t = 0; t < 2; t++)
            CP_ASYNC16(s0 + (uint32_t)(ar[t] * LDAH + ac[t]) * 2u,
                       A + (size_t)(bm + ar[t]) * K + k0 + ac[t]);
        const uint32_t s1 = s0 + AH_STAGE * 2u;
        #pragma unroll
        for (int t = 0; t < CFG::TBH; t++)
            CP_ASYNC16(s1 + (uint32_t)(br[t] * CFG::LDBH_ + bc[t]) * 2u,
                       B + (size_t)(k0 + br[t]) * N + bn + bc[t]);
        CP_COMMIT();
    };

    issue(0, 0);
    issue(1, 1);

    const int l15 = lane & 15, lhi = lane >> 4;
    const uint32_t aAddrBase = (uint32_t)(((wm * 32 + l15) * LDAH + lhi * 8) * 2);
    const uint32_t bAddrBase = (uint32_t)((l15 * CFG::LDBH_ + wn * (NJ * 8) + lhi * 8) * 2);

    for (int i = 0; i < niter; i++) {
        if (i + 1 < niter) { CP_WAIT(1); } else { CP_WAIT(0); }
        __syncthreads();
        if (i + 2 < niter) issue(i + 2, (i + 2) % 3);

        const uint32_t sA = sbase + (uint32_t)((i % 3) * CFG::STAGE) * 2u;
        const uint32_t sB = sA + AH_STAGE * 2u;

        #pragma unroll
        for (int kk = 0; kk < 2; kk++) {
            uint32_t a[2][4];
            #pragma unroll
            for (int mi = 0; mi < 2; mi++)
                LDMX4(a[mi], sA + aAddrBase + (uint32_t)((mi * 16 * LDAH + kk * 16) * 2));
            #pragma unroll
            for (int nj2 = 0; nj2 < NJ / 2; nj2++) {
                uint32_t bf[4];
                LDMX4T(bf, sB + bAddrBase + (uint32_t)((kk * 16 * CFG::LDBH_ + nj2 * 16) * 2));
                #pragma unroll
                for (int hh = 0; hh < 2; hh++) {
                    #pragma unroll
                    for (int mi = 0; mi < 2; mi++)
                        mma_f16(acc[mi][nj2 * 2 + hh], a[mi], bf[hh * 2], bf[hh * 2 + 1]);
                }
            }
        }
    }

    #pragma unroll
    for (int mi = 0; mi < 2; mi++) {
        const int row0 = bm + wm * 32 + mi * 16 + (lane >> 2);
        #pragma unroll
        for (int nj = 0; nj < NJ; nj++) {
            const int col0 = bn + wn * (NJ * 8) + nj * 8 + (lane & 3) * 2;
            const float b0 = bias[col0], b1 = bias[col0 + 1];
            #pragma unroll
            for (int hh = 0; hh < 2; hh++) {
                const int row = row0 + hh * 8;
                float v0 = acc[mi][nj][hh * 2 + 0] + b0;
                float v1 = acc[mi][nj][hh * 2 + 1] + b1;
                size_t g = (size_t)row * N + col0;
                if (EPI == 0) {
                    *(__half2*)((__half*)Cout + g) = __floats2half2_rn(v0, v1);
                } else if (EPI == 1) {
                    *(__half2*)((__half*)Cout + g) =
                        __floats2half2_rn(gelu_new(v0), gelu_new(v1));
                } else {
                    float2 rv = *(const float2*)(R + g);
                    float2 o; o.x = v0 + rv.x; o.y = v1 + rv.y;
                    *(float2*)((float*)Cout + g) = o;
                }
            }
        }
    }
}

// ---------------- layernorm: 4 rows/block, 64 thr/row, float4, 1 pass -------
__global__ __launch_bounds__(256)
void ln4_h(const float* __restrict__ in, const float* __restrict__ w,
           const float* __restrict__ b, __half* __restrict__ out) {
    const int tid = threadIdx.x;
    const int rloc = tid >> 6;            // 0..3
    const int t    = tid & 63;            // thread within row
    const int row  = blockIdx.x * 4 + rloc;
    const int lane = tid & 31;
    const int wIdx = (tid >> 5) & 1;      // warp within row

    const float4* xp = (const float4*)(in + (size_t)row * DM);
    float4 v[3];
    float s = 0.f, ss = 0.f;
    #pragma unroll
    for (int k = 0; k < 3; k++) {
        v[k] = xp[t + k * 64];
        s  += v[k].x + v[k].y + v[k].z + v[k].w;
        ss += v[k].x * v[k].x + v[k].y * v[k].y + v[k].z * v[k].z + v[k].w * v[k].w;
    }
    #pragma unroll
    for (int o = 16; o; o >>= 1) {
        s  += __shfl_xor_sync(0xffffffffu, s,  o);
        ss += __shfl_xor_sync(0xffffffffu, ss, o);
    }
    __shared__ float sb[4][2], qb[4][2];
    if (lane == 0) { sb[rloc][wIdx] = s; qb[rloc][wIdx] = ss; }
    __syncthreads();
    s  = sb[rloc][0] + sb[rloc][1];
    ss = qb[rloc][0] + qb[rloc][1];
    float mean = s * (1.f / DM);
    float inv  = rsqrtf(ss * (1.f / DM) - mean * mean + 1e-5f);

    const float4* wp = (const float4*)w;
    const float4* bp = (const float4*)b;
    __half2* op = (__half2*)(out + (size_t)row * DM);
    #pragma unroll
    for (int k = 0; k < 3; k++) {
        float4 wv = wp[t + k * 64], bv = bp[t + k * 64];
        float o0 = (v[k].x - mean) * inv * wv.x + bv.x;
        float o1 = (v[k].y - mean) * inv * wv.y + bv.y;
        float o2 = (v[k].z - mean) * inv * wv.z + bv.z;
        float o3 = (v[k].w - mean) * inv * wv.w + bv.w;
        op[(t + k * 64) * 2]     = __floats2half2_rn(o0, o1);
        op[(t + k * 64) * 2 + 1] = __floats2half2_rn(o2, o3);
    }
}

// ---------------- merged weight prep ----------------------------------------
// idx spans DM*DMLP; handles W_in/W_out cvt; sub-ranges handle QKV pack, W_O, bias.
__global__ void prep_weights(const float* __restrict__ WQ, const float* __restrict__ WK,
                             const float* __restrict__ WV, const float* __restrict__ WO,
                             const float* __restrict__ Win, const float* __restrict__ Wout,
                             const float* __restrict__ bQ, const float* __restrict__ bK,
                             const float* __restrict__ bV,
                             __half* __restrict__ Wqkv, __half* __restrict__ Wo_h,
                             __half* __restrict__ Win_h, __half* __restrict__ Wout_h,
                             float* __restrict__ bias) {
    int idx = blockIdx.x * 256 + threadIdx.x;
    if (idx < DM * DMLP) {
        Win_h[idx]  = __float2half_rn(Win[idx]);
        Wout_h[idx] = __float2half_rn(Wout[idx]);
    }
    if (idx < DM * DM) {
        Wo_h[idx] = __float2half_rn(WO[idx]);
        int k = idx / DM, n = idx % DM;
        int h = n >> 6, e = n & 63;
        int src = h * (DM * DH) + k * DH + e;
        Wqkv[(size_t)k * QKVN + n]          = __float2half_rn(WQ[src]);
        Wqkv[(size_t)k * QKVN + DM + n]     = __float2half_rn(WK[src]);
        Wqkv[(size_t)k * QKVN + 2 * DM + n] = __float2half_rn(WV[src]);
    }
    if (idx < DM) {
        bias[idx]          = bQ[idx];
        bias[DM + idx]     = bK[idx];
        bias[2 * DM + idx] = bV[idx];
    }
}

// ============== flash attention via fp16 mma.sync (causal, cp.async) ========
// 3-buffer K/V ring; ONE __syncthreads per K-tile.
#define LDH 72
#define AK_OFF (128*LDH)                     /* Q first: 9216 halves */
#define AV_OFF (AK_OFF + 3*64*LDH)           /* +13824 */
#define ATTNH_SMEM ((AV_OFF + 3*64*LDH)*2)   /* 73728 bytes */

__global__ __launch_bounds__(256, 2)
void attn_h(const __half* __restrict__ QKV, __half* __restrict__ Z) {
    extern __shared__ __half smh[];
    const uint32_t sbase = smem_u32(smh);

    const int tid = threadIdx.x, lane = tid & 31, wid = tid >> 5;
    const int r = lane >> 2, c = lane & 3;
    const int l15 = lane & 15, lhi = lane >> 4;
    const int qt = gridDim.x - 1 - blockIdx.x;       // heavy blocks first
    const int qt0 = qt * 128;
    const int h = blockIdx.y, b = blockIdx.z;

    const __half* qbase = QKV + ((size_t)(b * SEQ + qt0)) * QKVN + h * DH;
    const __half* kbase = QKV + ((size_t)b * SEQ) * QKVN + DM     + h * DH;
    const __half* vbase = QKV + ((size_t)b * SEQ) * QKVN + 2 * DM + h * DH;

    const int ntiles = qt0 / 64 + 2;

    auto issue_kv = [&](int kt, int buf) {
        const __half* kb = kbase + (size_t)(kt * 64) * QKVN;
        const __half* vb = vbase + (size_t)(kt * 64) * QKVN;
        const uint32_t ks = sbase + (uint32_t)(AK_OFF + buf * 64 * LDH) * 2u;
        const uint32_t vs = sbase + (uint32_t)(AV_OFF + buf * 64 * LDH) * 2u;
        #pragma unroll
        for (int t = 0; t < 2; t++) {
            int ci = tid + t * 256;
            int row = ci >> 3, ch = (ci & 7) * 8;
            CP_ASYNC16(ks + (uint32_t)(row * LDH + ch) * 2u,
                       kb + (size_t)row * QKVN + ch);
            CP_ASYNC16(vs + (uint32_t)(row * LDH + ch) * 2u,
                       vb + (size_t)row * QKVN + ch);
        }
        CP_COMMIT();
    };

    {   // group 0: Q + KV tile 0
        #pragma unroll
        for (int t = 0; t < 4; t++) {
            int ci = tid + t * 256;
            int row = ci >> 3, ch = (ci & 7) * 8;
            CP_ASYNC16(sbase + (uint32_t)(row * LDH + ch) * 2u,
                       qbase + (size_t)row * QKVN + ch);
        }
        const uint32_t ks = sbase + (uint32_t)AK_OFF * 2u;
        const uint32_t vs = sbase + (uint32_t)AV_OFF * 2u;
        #pragma unroll
        for (int t = 0; t < 2; t++) {
            int ci = tid + t * 256;
            int row = ci >> 3, ch = (ci & 7) * 8;
            CP_ASYNC16(ks + (uint32_t)(row * LDH + ch) * 2u,
                       kbase + (size_t)row * QKVN + ch);
            CP_ASYNC16(vs + (uint32_t)(row * LDH + ch) * 2u,
                       vbase + (size_t)row * QKVN + ch);
        }
        CP_COMMIT();
    }
    if (ntiles > 1) issue_kv(1, 1);

    float o[8][4];
    #pragma unroll
    for (int nj = 0; nj < 8; nj++)
        #pragma unroll
        for (int t = 0; t < 4; t++) o[nj][t] = 0.f;
    float m0 = -1e30f, m1 = -1e30f, l0 = 0.f, l1 = 0.f;

    const int q0g = qt0 + wid * 16 + r;
    const int qmax_warp = qt0 + wid * 16 + 15;

    uint32_t qa[4][4];

    for (int kt = 0; kt < ntiles; kt++) {
        if (kt + 1 < ntiles) { CP_WAIT(1); } else { CP_WAIT(0); }
        __syncthreads();     // tile kt ready; buf (kt+2)%3 fully consumed at kt-1
        if (kt + 2 < ntiles) issue_kv(kt + 2, (kt + 2) % 3);

        if (kt == 0) {
            const uint32_t qaddr = sbase + (uint32_t)(((wid * 16 + l15) * LDH + lhi * 8) * 2);
            __half2 sc = __floats2half2_rn(0.125f, 0.125f);
            #pragma unroll
            for (int kk = 0; kk < 4; kk++) {
                LDMX4(qa[kk], qaddr + (uint32_t)(kk * 16 * 2));
                #pragma unroll
                for (int j = 0; j < 4; j++) {
                    __half2 v = *reinterpret_cast<__half2*>(&qa[kk][j]);
                    v = __hmul2(v, sc);
                    qa[kk][j] = *reinterpret_cast<uint32_t*>(&v);
                }
            }
        }

        if (kt * 64 <= qmax_warp) {
            const int buf = kt % 3;
            const uint32_t Kb = sbase + (uint32_t)(AK_OFF + buf * 64 * LDH) * 2u;
            const uint32_t Vb = sbase + (uint32_t)(AV_OFF + buf * 64 * LDH) * 2u;

            // ---- S = Q @ K^T
            float s[8][4];
            #pragma unroll
            for (int nj = 0; nj < 8; nj++)
                #pragma unroll
                for (int t = 0; t < 4; t++) s[nj][t] = 0.f;

            const int g = lane >> 3;
            #pragma unroll
            for (int g2 = 0; g2 < 4; g2++) {
                const uint32_t rowb = Kb +
                    (uint32_t)(((16 * g2 + (g >> 1) * 8 + (lane & 7)) * LDH) * 2);
                #pragma unroll
                for (int kk = 0; kk < 4; kk++) {
                    uint32_t bk[4];
                    LDMX4(bk, rowb + (uint32_t)((kk * 16 + (g & 1) * 8) * 2));
                    mma_f16(s[2 * g2],     qa[kk], bk[0], bk[1]);
                    mma_f16(s[2 * g2 + 1], qa[kk], bk[2], bk[3]);
                }
            }

            if (kt * 64 + 63 > qt0 + wid * 16) {
                #pragma unroll
                for (int nj = 0; nj < 8; nj++) {
                    int k0c = kt * 64 + nj * 8 + c * 2;
                    if (k0c     > q0g)     s[nj][0] = -1e30f;
                    if (k0c + 1 > q0g)     s[nj][1] = -1e30f;
                    if (k0c     > q0g + 8) s[nj][2] = -1e30f;
                    if (k0c + 1 > q0g + 8) s[nj][3] = -1e30f;
                }
            }

            float mt0 = -1e30f, mt1 = -1e30f;
            #pragma unroll
            for (int nj = 0; nj < 8; nj++) {
                mt0 = fmaxf(mt0, fmaxf(s[nj][0], s[nj][1]));
                mt1 = fmaxf(mt1, fmaxf(s[nj][2], s[nj][3]));
            }
            mt0 = fmaxf(mt0, __shfl_xor_sync(0xffffffffu, mt0, 1));
            mt0 = fmaxf(mt0, __shfl_xor_sync(0xffffffffu, mt0, 2));
            mt1 = fmaxf(mt1, __shfl_xor_sync(0xffffffffu, mt1, 1));
            mt1 = fmaxf(mt1, __shfl_xor_sync(0xffffffffu, mt1, 2));

            float mn0 = fmaxf(m0, mt0), mn1 = fmaxf(m1, mt1);
            float cr0 = __expf(m0 - mn0), cr1 = __expf(m1 - mn1);
            float ls0 = 0.f, ls1 = 0.f;
            #pragma unroll
            for (int nj = 0; nj < 8; nj++) {
                s[nj][0] = __expf(s[nj][0] - mn0);
                s[nj][1] = __expf(s[nj][1] - mn0);
                s[nj][2] = __expf(s[nj][2] - mn1);
                s[nj][3] = __expf(s[nj][3] - mn1);
                ls0 += s[nj][0] + s[nj][1];
                ls1 += s[nj][2] + s[nj][3];
            }
            ls0 += __shfl_xor_sync(0xffffffffu, ls0, 1);
            ls0 += __shfl_xor_sync(0xffffffffu, ls0, 2);
            ls1 += __shfl_xor_sync(0xffffffffu, ls1, 1);
            ls1 += __shfl_xor_sync(0xffffffffu, ls1, 2);
            l0 = l0 * cr0 + ls0;
            l1 = l1 * cr1 + ls1;
            m0 = mn0; m1 = mn1;
            #pragma unroll
            for (int nj = 0; nj < 8; nj++) {
                o[nj][0] *= cr0; o[nj][1] *= cr0;
                o[nj][2] *= cr1; o[nj][3] *= cr1;
            }

            // ---- O += P @ V : P A-frags packed from S C-frags in registers
            #pragma unroll
            for (int kk = 0; kk < 4; kk++) {
                uint32_t pa[4];
                pa[0] = pack_h2(s[2 * kk][0],     s[2 * kk][1]);
                pa[1] = pack_h2(s[2 * kk][2],     s[2 * kk][3]);
                pa[2] = pack_h2(s[2 * kk + 1][0], s[2 * kk + 1][1]);
                pa[3] = pack_h2(s[2 * kk + 1][2], s[2 * kk + 1][3]);
                const uint32_t rowb = Vb + (uint32_t)(((kk * 16 + l15) * LDH + lhi * 8) * 2);
                #pragma unroll
                for (int nj2 = 0; nj2 < 4; nj2++) {
                    uint32_t bv[4];
                    LDMX4T(bv, rowb + (uint32_t)((nj2 * 16) * 2));
                    mma_f16(o[2 * nj2],     pa, bv[0], bv[1]);
                    mma_f16(o[2 * nj2 + 1], pa, bv[2], bv[3]);
                }
            }
        }
    }

    float inv0 = 1.f / l0, inv1 = 1.f / l1;
    #pragma unroll
    for (int nj = 0; nj < 8; nj++) {
        int col = h * DH + nj * 8 + c * 2;
        size_t g0 = (size_t)(b * SEQ + q0g) * DM + col;
        size_t g1 = (size_t)(b * SEQ + q0g + 8) * DM + col;
        *(__half2*)(Z + g0) = __floats2half2_rn(o[nj][0] * inv0, o[nj][1] * inv0);
        *(__half2*)(Z + g1) = __floats2half2_rn(o[nj][2] * inv1, o[nj][3] * inv1);
    }
}

// ---------------- launch -----------------------------------------------------
extern "C" void kernel_launch(void* const* d_in, const int* in_sizes, int n_in,
                              void* d_out, int out_size) {
    const float* resid_pre = (const float*)d_in[0];
    const float* W_Q   = (const float*)d_in[1];
    const float* b_Q   = (const float*)d_in[2];
    const float* W_K   = (const float*)d_in[3];
    const float* b_K   = (const float*)d_in[4];
    const float* W_V   = (const float*)d_in[5];
    const float* b_V   = (const float*)d_in[6];
    const float* W_O   = (const float*)d_in[7];
    const float* b_O   = (const float*)d_in[8];
    const float* ln1_w = (const float*)d_in[9];
    const float* ln1_b = (const float*)d_in[10];
    const float* ln2_w = (const float*)d_in[11];
    const float* ln2_b = (const float*)d_in[12];
    const float* W_in  = (const float*)d_in[13];
    const float* b_in  = (const float*)d_in[14];
    const float* W_out = (const float*)d_in[15];
    const float* b_out = (const float*)d_in[16];
    float* out = (float*)d_out;

    float *pbqkv, *pmid;
    __half *px_h, *pwqkv_h, *pqkv_h, *pz_h, *py_h, *ph_h, *pwo_h, *pwin_h, *pwout_h;
    cudaGetSymbolAddress((void**)&px_h,    g_x_h);
    cudaGetSymbolAddress((void**)&pwqkv_h, g_wqkv_h);
    cudaGetSymbolAddress((void**)&pbqkv,   g_bqkv);
    cudaGetSymbolAddress((void**)&pqkv_h,  g_qkv_h);
    cudaGetSymbolAddress((void**)&pz_h,    g_z_h);
    cudaGetSymbolAddress((void**)&pmid,    g_mid);
    cudaGetSymbolAddress((void**)&py_h,    g_y_h);
    cudaGetSymbolAddress((void**)&ph_h,    g_h_h);
    cudaGetSymbolAddress((void**)&pwo_h,   g_wo_h);
    cudaGetSymbolAddress((void**)&pwin_h,  g_win_h);
    cudaGetSymbolAddress((void**)&pwout_h, g_wout_h);

    cudaFuncSetAttribute((const void*)gemm_h<0,8>, cudaFuncAttributeMaxDynamicSharedMemorySize, GemmHCfg<8>::SMEM);
    cudaFuncSetAttribute((const void*)gemm_h<1,8>, cudaFuncAttributeMaxDynamicSharedMemorySize, GemmHCfg<8>::SMEM);
    cudaFuncSetAttribute((const void*)gemm_h<2,4>, cudaFuncAttributeMaxDynamicSharedMemorySize, GemmHCfg<4>::SMEM);
    cudaFuncSetAttribute((const void*)attn_h,      cudaFuncAttributeMaxDynamicSharedMemorySize, ATTNH_SMEM);

    prep_weights<<<(DM * DMLP + 255) / 256, 256>>>(
        W_Q, W_K, W_V, W_O, W_in, W_out, b_Q, b_K, b_V,
        pwqkv_h, pwo_h, pwin_h, pwout_h, pbqkv);

    ln4_h<<<ROWS / 4, 256>>>(resid_pre, ln1_w, ln1_b, px_h);
    gemm_h<0,8><<<dim3(QKVN / 128, ROWS / 128), 256, GemmHCfg<8>::SMEM>>>(
        px_h, pwqkv_h, pbqkv, nullptr, pqkv_h, ROWS, QKVN, DM);
    attn_h<<<dim3(SEQ / 128, NH, BATCH), 256, ATTNH_SMEM>>>(pqkv_h, pz_h);
    gemm_h<2,4><<<dim3(DM / 64, ROWS / 128), 256, GemmHCfg<4>::SMEM>>>(
        pz_h, pwo_h, b_O, resid_pre, pmid, ROWS, DM, DM);
    ln4_h<<<ROWS / 4, 256>>>(pmid, ln2_w, ln2_b, py_h);
    gemm_h<1,8><<<dim3(DMLP / 128, ROWS / 128), 256, GemmHCfg<8>::SMEM>>>(
        py_h, pwin_h, b_in, nullptr, ph_h, ROWS, DMLP, DM);
    gemm_h<2,4><<<dim3(DM / 64, ROWS / 128), 256, GemmHCfg<4>::SMEM>>>(
        ph_h, pwout_h, b_out, pmid, out, ROWS, DM, DMLP);
}

// round 11
// speedup vs baseline: 10.4574x; 1.0829x over previous
#include <cuda_runtime.h>
#include <cuda_fp16.h>
#include <cstdint>
#include <math.h>

#define DM    768
#define DMLP  3072
#define NH    12
#define DH    64
#define BATCH 2
#define SEQ   2048
#define ROWS  (BATCH*SEQ)     /* 4096 */
#define QKVN  (3*DM)          /* 2304 */

// ---------------- scratch (static device globals; no allocation) -----------
__device__ __align__(16) __half g_x_h   [ROWS*DM];     // ln1 output
__device__ __align__(16) __half g_wqkv_h[DM*QKVN];     // packed QKV W [K,N]
__device__ float g_bqkv [QKVN];
__device__ __align__(16) __half g_qkv_h [ROWS*QKVN];   // Q|K|V per token
__device__ __align__(16) __half g_z_h   [ROWS*DM];     // attention output
__device__ float g_mid  [ROWS*DM];                     // resid_mid (fp32)
__device__ __align__(16) __half g_y_h   [ROWS*DM];     // ln2 output
__device__ __align__(16) __half g_h_h   [ROWS*DMLP];   // MLP hidden
__device__ __align__(16) __half g_wo_h  [DM*DM];       // W_O   fp16 [K,N]
__device__ __align__(16) __half g_win_h [DM*DMLP];     // W_in  fp16 [K,N]
__device__ __align__(16) __half g_wout_h[DMLP*DM];     // W_out fp16 [K,N]

// ======================= helpers ============================================
__device__ __forceinline__ uint32_t smem_u32(const void* p) {
    uint32_t a;
    asm("{ .reg .u64 t; cvta.to.shared.u64 t, %1; cvt.u32.u64 %0, t; }"
        : "=r"(a) : "l"(p));
    return a;
}
__device__ __forceinline__ float gelu_new(float v) {
    float v3 = v * v * v;
    return 0.5f * v * (1.f + tanhf(0.7978845608028654f * (v + 0.044715f * v3)));
}
__device__ __forceinline__ uint32_t pack_h2(float a, float b) {
    __half2 h = __floats2half2_rn(a, b);
    return *reinterpret_cast<uint32_t*>(&h);
}
#define CP_ASYNC16(sa, gp) \
    asm volatile("cp.async.cg.shared.global [%0], [%1], 16;" :: "r"(sa), "l"(gp))
#define CP_COMMIT() asm volatile("cp.async.commit_group;" ::: "memory")
#define CP_WAIT(n)  asm volatile("cp.async.wait_group %0;" :: "n"(n) : "memory")

#define LDMX4(r, addr) \
    asm volatile("ldmatrix.sync.aligned.m8n8.x4.shared.b16 {%0,%1,%2,%3}, [%4];" \
        : "=r"((r)[0]), "=r"((r)[1]), "=r"((r)[2]), "=r"((r)[3]) : "r"(addr))
#define LDMX4T(r, addr) \
    asm volatile("ldmatrix.sync.aligned.m8n8.x4.trans.shared.b16 {%0,%1,%2,%3}, [%4];" \
        : "=r"((r)[0]), "=r"((r)[1]), "=r"((r)[2]), "=r"((r)[3]) : "r"(addr))

__device__ __forceinline__ void mma_f16(float* c, const uint32_t* a,
                                        uint32_t b0, uint32_t b1) {
    asm volatile(
        "mma.sync.aligned.m16n8k16.row.col.f32.f16.f16.f32 "
        "{%0,%1,%2,%3}, {%4,%5,%6,%7}, {%8,%9}, {%0,%1,%2,%3};\n"
        : "+f"(c[0]), "+f"(c[1]), "+f"(c[2]), "+f"(c[3])
        : "r"(a[0]), "r"(a[1]), "r"(a[2]), "r"(a[3]), "r"(b0), "r"(b1));
}

// ====== fp16 mma.sync GEMM (ldmatrix, BK=64): C[M,N] = A[M,K] @ B[K,N] ======
// BM=128, BN=NJ*16; 8 warps (4M x 2N). 3-stage cp.async, 1 sync per 64-K iter.
#define LDAH2 72
#define AH_STAGE2 (128*LDAH2)

template<int NJ> struct GemmHCfg {
    static const int BN      = NJ * 16;
    static const int LDBH_   = BN + 8;
    static const int B_STAGE = 64 * LDBH_;
    static const int STAGE   = AH_STAGE2 + B_STAGE;
    static const int SMEM    = 3 * STAGE * 2;
    static const int TBH     = BN / 32;          // B 16B-chunks per thread
};

// EPI: 0 = bias->half, 1 = bias+gelu->half, 2 = bias+residual->float
template<int EPI, int NJ>
__global__ __launch_bounds__(256, 2)
void gemm_h(const __half* __restrict__ A, const __half* __restrict__ B,
            const float* __restrict__ bias, const float* __restrict__ R,
            void* __restrict__ Cout, int M, int N, int K) {
    typedef GemmHCfg<NJ> CFG;
    extern __shared__ __half smh[];
    const uint32_t sbase = smem_u32(smh);
    const int tid = threadIdx.x, lane = tid & 31, wid = tid >> 5;
    const int wm = wid & 3, wn = wid >> 2;
    const int bm = blockIdx.y * 128, bn = blockIdx.x * CFG::BN;
    const int niter = K >> 6;

    int ar[4], ac[4];
    #pragma unroll
    for (int t = 0; t < 4; t++) {
        int ci = tid + t * 256;          // 0..1023 over 128 rows x 8 chunks
        ar[t] = ci >> 3;  ac[t] = (ci & 7) * 8;
    }
    int br[CFG::TBH], bc[CFG::TBH];
    #pragma unroll
    for (int t = 0; t < CFG::TBH; t++) {
        int ci = tid + t * 256;          // over 64 rows x BN/8 chunks
        br[t] = ci / (CFG::BN / 8);
        bc[t] = (ci % (CFG::BN / 8)) * 8;
    }

    float acc[2][NJ][4];
    #pragma unroll
    for (int mi = 0; mi < 2; mi++)
        #pragma unroll
        for (int nj = 0; nj < NJ; nj++)
            #pragma unroll
            for (int r = 0; r < 4; r++) acc[mi][nj][r] = 0.f;

    auto issue = [&](int ks, int buf) {
        const int k0 = ks << 6;
        const uint32_t s0 = sbase + (uint32_t)buf * CFG::STAGE * 2u;
        #pragma unroll
        for (int t = 0; t < 4; t++)
            CP_ASYNC16(s0 + (uint32_t)(ar[t] * LDAH2 + ac[t]) * 2u,
                       A + (size_t)(bm + ar[t]) * K + k0 + ac[t]);
        const uint32_t s1 = s0 + AH_STAGE2 * 2u;
        #pragma unroll
        for (int t = 0; t < CFG::TBH; t++)
            CP_ASYNC16(s1 + (uint32_t)(br[t] * CFG::LDBH_ + bc[t]) * 2u,
                       B + (size_t)(k0 + br[t]) * N + bn + bc[t]);
        CP_COMMIT();
    };

    issue(0, 0);
    issue(1, 1);

    const int l15 = lane & 15, lhi = lane >> 4;
    const uint32_t aAddrBase = (uint32_t)(((wm * 32 + l15) * LDAH2 + lhi * 8) * 2);
    const uint32_t bAddrBase = (uint32_t)((l15 * CFG::LDBH_ + wn * (NJ * 8) + lhi * 8) * 2);

    for (int i = 0; i < niter; i++) {
        if (i + 1 < niter) { CP_WAIT(1); } else { CP_WAIT(0); }
        __syncthreads();
        if (i + 2 < niter) issue(i + 2, (i + 2) % 3);

        const uint32_t sA = sbase + (uint32_t)((i % 3) * CFG::STAGE) * 2u;
        const uint32_t sB = sA + AH_STAGE2 * 2u;

        #pragma unroll
        for (int kk = 0; kk < 4; kk++) {
            uint32_t a[2][4];
            #pragma unroll
            for (int mi = 0; mi < 2; mi++)
                LDMX4(a[mi], sA + aAddrBase + (uint32_t)((mi * 16 * LDAH2 + kk * 16) * 2));
            #pragma unroll
            for (int nj2 = 0; nj2 < NJ / 2; nj2++) {
                uint32_t bf[4];
                LDMX4T(bf, sB + bAddrBase + (uint32_t)((kk * 16 * CFG::LDBH_ + nj2 * 16) * 2));
                #pragma unroll
                for (int hh = 0; hh < 2; hh++) {
                    #pragma unroll
                    for (int mi = 0; mi < 2; mi++)
                        mma_f16(acc[mi][nj2 * 2 + hh], a[mi], bf[hh * 2], bf[hh * 2 + 1]);
                }
            }
        }
    }

    #pragma unroll
    for (int mi = 0; mi < 2; mi++) {
        const int row0 = bm + wm * 32 + mi * 16 + (lane >> 2);
        #pragma unroll
        for (int nj = 0; nj < NJ; nj++) {
            const int col0 = bn + wn * (NJ * 8) + nj * 8 + (lane & 3) * 2;
            const float b0 = bias[col0], b1 = bias[col0 + 1];
            #pragma unroll
            for (int hh = 0; hh < 2; hh++) {
                const int row = row0 + hh * 8;
                float v0 = acc[mi][nj][hh * 2 + 0] + b0;
                float v1 = acc[mi][nj][hh * 2 + 1] + b1;
                size_t g = (size_t)row * N + col0;
                if (EPI == 0) {
                    *(__half2*)((__half*)Cout + g) = __floats2half2_rn(v0, v1);
                } else if (EPI == 1) {
                    *(__half2*)((__half*)Cout + g) =
                        __floats2half2_rn(gelu_new(v0), gelu_new(v1));
                } else {
                    float2 rv = *(const float2*)(R + g);
                    float2 o; o.x = v0 + rv.x; o.y = v1 + rv.y;
                    *(float2*)((float*)Cout + g) = o;
                }
            }
        }
    }
}

// ---------------- layernorm: 4 rows/block, 64 thr/row, float4, 1 pass -------
__global__ __launch_bounds__(256)
void ln4_h(const float* __restrict__ in, const float* __restrict__ w,
           const float* __restrict__ b, __half* __restrict__ out) {
    const int tid = threadIdx.x;
    const int rloc = tid >> 6;
    const int t    = tid & 63;
    const int row  = blockIdx.x * 4 + rloc;
    const int lane = tid & 31;
    const int wIdx = (tid >> 5) & 1;

    const float4* xp = (const float4*)(in + (size_t)row * DM);
    float4 v[3];
    float s = 0.f, ss = 0.f;
    #pragma unroll
    for (int k = 0; k < 3; k++) {
        v[k] = xp[t + k * 64];
        s  += v[k].x + v[k].y + v[k].z + v[k].w;
        ss += v[k].x * v[k].x + v[k].y * v[k].y + v[k].z * v[k].z + v[k].w * v[k].w;
    }
    #pragma unroll
    for (int o = 16; o; o >>= 1) {
        s  += __shfl_xor_sync(0xffffffffu, s,  o);
        ss += __shfl_xor_sync(0xffffffffu, ss, o);
    }
    __shared__ float sb[4][2], qb[4][2];
    if (lane == 0) { sb[rloc][wIdx] = s; qb[rloc][wIdx] = ss; }
    __syncthreads();
    s  = sb[rloc][0] + sb[rloc][1];
    ss = qb[rloc][0] + qb[rloc][1];
    float mean = s * (1.f / DM);
    float inv  = rsqrtf(ss * (1.f / DM) - mean * mean + 1e-5f);

    const float4* wp = (const float4*)w;
    const float4* bp = (const float4*)b;
    __half2* op = (__half2*)(out + (size_t)row * DM);
    #pragma unroll
    for (int k = 0; k < 3; k++) {
        float4 wv = wp[t + k * 64], bv = bp[t + k * 64];
        float o0 = (v[k].x - mean) * inv * wv.x + bv.x;
        float o1 = (v[k].y - mean) * inv * wv.y + bv.y;
        float o2 = (v[k].z - mean) * inv * wv.z + bv.z;
        float o3 = (v[k].w - mean) * inv * wv.w + bv.w;
        op[(t + k * 64) * 2]     = __floats2half2_rn(o0, o1);
        op[(t + k * 64) * 2 + 1] = __floats2half2_rn(o2, o3);
    }
}

// ---------------- merged weight prep (vectorized) ----------------------------
// idx range DM*DM == DM*DMLP/4 == 589824; each idx: 4-elem cvt of W_in/W_out +
// 1-elem QKV pack + W_O cvt; idx < DM also packs bias.
__global__ void prep_weights(const float* __restrict__ WQ, const float* __restrict__ WK,
                             const float* __restrict__ WV, const float* __restrict__ WO,
                             const float* __restrict__ Win, const float* __restrict__ Wout,
                             const float* __restrict__ bQ, const float* __restrict__ bK,
                             const float* __restrict__ bV,
                             __half* __restrict__ Wqkv, __half* __restrict__ Wo_h,
                             __half* __restrict__ Win_h, __half* __restrict__ Wout_h,
                             float* __restrict__ bias) {
    int idx = blockIdx.x * 256 + threadIdx.x;
    if (idx < DM * DM) {
        // vectorized W_in / W_out conversion (4 floats -> 2 half2)
        float4 wi = ((const float4*)Win)[idx];
        float4 wo = ((const float4*)Wout)[idx];
        ((__half2*)Win_h)[idx * 2]      = __floats2half2_rn(wi.x, wi.y);
        ((__half2*)Win_h)[idx * 2 + 1]  = __floats2half2_rn(wi.z, wi.w);
        ((__half2*)Wout_h)[idx * 2]     = __floats2half2_rn(wo.x, wo.y);
        ((__half2*)Wout_h)[idx * 2 + 1] = __floats2half2_rn(wo.z, wo.w);
        // scalar W_O + QKV pack
        Wo_h[idx] = __float2half_rn(WO[idx]);
        int k = idx / DM, n = idx % DM;
        int h = n >> 6, e = n & 63;
        int src = h * (DM * DH) + k * DH + e;
        Wqkv[(size_t)k * QKVN + n]          = __float2half_rn(WQ[src]);
        Wqkv[(size_t)k * QKVN + DM + n]     = __float2half_rn(WK[src]);
        Wqkv[(size_t)k * QKVN + 2 * DM + n] = __float2half_rn(WV[src]);
    }
    if (idx < DM) {
        bias[idx]          = bQ[idx];
        bias[DM + idx]     = bK[idx];
        bias[2 * DM + idx] = bV[idx];
    }
}

// ============== flash attention via fp16 mma.sync (causal, cp.async) ========
// 3-buffer K/V ring; ONE __syncthreads per K-tile. (unchanged from R10)
#define LDH 72
#define AK_OFF (128*LDH)
#define AV_OFF (AK_OFF + 3*64*LDH)
#define ATTNH_SMEM ((AV_OFF + 3*64*LDH)*2)

__global__ __launch_bounds__(256, 2)
void attn_h(const __half* __restrict__ QKV, __half* __restrict__ Z) {
    extern __shared__ __half smh[];
    const uint32_t sbase = smem_u32(smh);

    const int tid = threadIdx.x, lane = tid & 31, wid = tid >> 5;
    const int r = lane >> 2, c = lane & 3;
    const int l15 = lane & 15, lhi = lane >> 4;
    const int qt = gridDim.x - 1 - blockIdx.x;
    const int qt0 = qt * 128;
    const int h = blockIdx.y, b = blockIdx.z;

    const __half* qbase = QKV + ((size_t)(b * SEQ + qt0)) * QKVN + h * DH;
    const __half* kbase = QKV + ((size_t)b * SEQ) * QKVN + DM     + h * DH;
    const __half* vbase = QKV + ((size_t)b * SEQ) * QKVN + 2 * DM + h * DH;

    const int ntiles = qt0 / 64 + 2;

    auto issue_kv = [&](int kt, int buf) {
        const __half* kb = kbase + (size_t)(kt * 64) * QKVN;
        const __half* vb = vbase + (size_t)(kt * 64) * QKVN;
        const uint32_t ks = sbase + (uint32_t)(AK_OFF + buf * 64 * LDH) * 2u;
        const uint32_t vs = sbase + (uint32_t)(AV_OFF + buf * 64 * LDH) * 2u;
        #pragma unroll
        for (int t = 0; t < 2; t++) {
            int ci = tid + t * 256;
            int row = ci >> 3, ch = (ci & 7) * 8;
            CP_ASYNC16(ks + (uint32_t)(row * LDH + ch) * 2u,
                       kb + (size_t)row * QKVN + ch);
            CP_ASYNC16(vs + (uint32_t)(row * LDH + ch) * 2u,
                       vb + (size_t)row * QKVN + ch);
        }
        CP_COMMIT();
    };

    {
        #pragma unroll
        for (int t = 0; t < 4; t++) {
            int ci = tid + t * 256;
            int row = ci >> 3, ch = (ci & 7) * 8;
            CP_ASYNC16(sbase + (uint32_t)(row * LDH + ch) * 2u,
                       qbase + (size_t)row * QKVN + ch);
        }
        const uint32_t ks = sbase + (uint32_t)AK_OFF * 2u;
        const uint32_t vs = sbase + (uint32_t)AV_OFF * 2u;
        #pragma unroll
        for (int t = 0; t < 2; t++) {
            int ci = tid + t * 256;
            int row = ci >> 3, ch = (ci & 7) * 8;
            CP_ASYNC16(ks + (uint32_t)(row * LDH + ch) * 2u,
                       kbase + (size_t)row * QKVN + ch);
            CP_ASYNC16(vs + (uint32_t)(row * LDH + ch) * 2u,
                       vbase + (size_t)row * QKVN + ch);
        }
        CP_COMMIT();
    }
    if (ntiles > 1) issue_kv(1, 1);

    float o[8][4];
    #pragma unroll
    for (int nj = 0; nj < 8; nj++)
        #pragma unroll
        for (int t = 0; t < 4; t++) o[nj][t] = 0.f;
    float m0 = -1e30f, m1 = -1e30f, l0 = 0.f, l1 = 0.f;

    const int q0g = qt0 + wid * 16 + r;
    const int qmax_warp = qt0 + wid * 16 + 15;

    uint32_t qa[4][4];

    for (int kt = 0; kt < ntiles; kt++) {
        if (kt + 1 < ntiles) { CP_WAIT(1); } else { CP_WAIT(0); }
        __syncthreads();
        if (kt + 2 < ntiles) issue_kv(kt + 2, (kt + 2) % 3);

        if (kt == 0) {
            const uint32_t qaddr = sbase + (uint32_t)(((wid * 16 + l15) * LDH + lhi * 8) * 2);
            __half2 sc = __floats2half2_rn(0.125f, 0.125f);
            #pragma unroll
            for (int kk = 0; kk < 4; kk++) {
                LDMX4(qa[kk], qaddr + (uint32_t)(kk * 16 * 2));
                #pragma unroll
                for (int j = 0; j < 4; j++) {
                    __half2 v = *reinterpret_cast<__half2*>(&qa[kk][j]);
                    v = __hmul2(v, sc);
                    qa[kk][j] = *reinterpret_cast<uint32_t*>(&v);
                }
            }
        }

        if (kt * 64 <= qmax_warp) {
            const int buf = kt % 3;
            const uint32_t Kb = sbase + (uint32_t)(AK_OFF + buf * 64 * LDH) * 2u;
            const uint32_t Vb = sbase + (uint32_t)(AV_OFF + buf * 64 * LDH) * 2u;

            float s[8][4];
            #pragma unroll
            for (int nj = 0; nj < 8; nj++)
                #pragma unroll
                for (int t = 0; t < 4; t++) s[nj][t] = 0.f;

            const int g = lane >> 3;
            #pragma unroll
            for (int g2 = 0; g2 < 4; g2++) {
                const uint32_t rowb = Kb +
                    (uint32_t)(((16 * g2 + (g >> 1) * 8 + (lane & 7)) * LDH) * 2);
                #pragma unroll
                for (int kk = 0; kk < 4; kk++) {
                    uint32_t bk[4];
                    LDMX4(bk, rowb + (uint32_t)((kk * 16 + (g & 1) * 8) * 2));
                    mma_f16(s[2 * g2],     qa[kk], bk[0], bk[1]);
                    mma_f16(s[2 * g2 + 1], qa[kk], bk[2], bk[3]);
                }
            }

            if (kt * 64 + 63 > qt0 + wid * 16) {
                #pragma unroll
                for (int nj = 0; nj < 8; nj++) {
                    int k0c = kt * 64 + nj * 8 + c * 2;
                    if (k0c     > q0g)     s[nj][0] = -1e30f;
                    if (k0c + 1 > q0g)     s[nj][1] = -1e30f;
                    if (k0c     > q0g + 8) s[nj][2] = -1e30f;
                    if (k0c + 1 > q0g + 8) s[nj][3] = -1e30f;
                }
            }

            float mt0 = -1e30f, mt1 = -1e30f;
            #pragma unroll
            for (int nj = 0; nj < 8; nj++) {
                mt0 = fmaxf(mt0, fmaxf(s[nj][0], s[nj][1]));
                mt1 = fmaxf(mt1, fmaxf(s[nj][2], s[nj][3]));
            }
            mt0 = fmaxf(mt0, __shfl_xor_sync(0xffffffffu, mt0, 1));
            mt0 = fmaxf(mt0, __shfl_xor_sync(0xffffffffu, mt0, 2));
            mt1 = fmaxf(mt1, __shfl_xor_sync(0xffffffffu, mt1, 1));
            mt1 = fmaxf(mt1, __shfl_xor_sync(0xffffffffu, mt1, 2));

            float mn0 = fmaxf(m0, mt0), mn1 = fmaxf(m1, mt1);
            float cr0 = __expf(m0 - mn0), cr1 = __expf(m1 - mn1);
            float ls0 = 0.f, ls1 = 0.f;
            #pragma unroll
            for (int nj = 0; nj < 8; nj++) {
                s[nj][0] = __expf(s[nj][0] - mn0);
                s[nj][1] = __expf(s[nj][1] - mn0);
                s[nj][2] = __expf(s[nj][2] - mn1);
                s[nj][3] = __expf(s[nj][3] - mn1);
                ls0 += s[nj][0] + s[nj][1];
                ls1 += s[nj][2] + s[nj][3];
            }
            ls0 += __shfl_xor_sync(0xffffffffu, ls0, 1);
            ls0 += __shfl_xor_sync(0xffffffffu, ls0, 2);
            ls1 += __shfl_xor_sync(0xffffffffu, ls1, 1);
            ls1 += __shfl_xor_sync(0xffffffffu, ls1, 2);
            l0 = l0 * cr0 + ls0;
            l1 = l1 * cr1 + ls1;
            m0 = mn0; m1 = mn1;
            #pragma unroll
            for (int nj = 0; nj < 8; nj++) {
                o[nj][0] *= cr0; o[nj][1] *= cr0;
                o[nj][2] *= cr1; o[nj][3] *= cr1;
            }

            #pragma unroll
            for (int kk = 0; kk < 4; kk++) {
                uint32_t pa[4];
                pa[0] = pack_h2(s[2 * kk][0],     s[2 * kk][1]);
                pa[1] = pack_h2(s[2 * kk][2],     s[2 * kk][3]);
                pa[2] = pack_h2(s[2 * kk + 1][0], s[2 * kk + 1][1]);
                pa[3] = pack_h2(s[2 * kk + 1][2], s[2 * kk + 1][3]);
                const uint32_t rowb = Vb + (uint32_t)(((kk * 16 + l15) * LDH + lhi * 8) * 2);
                #pragma unroll
                for (int nj2 = 0; nj2 < 4; nj2++) {
                    uint32_t bv[4];
                    LDMX4T(bv, rowb + (uint32_t)((nj2 * 16) * 2));
                    mma_f16(o[2 * nj2],     pa, bv[0], bv[1]);
                    mma_f16(o[2 * nj2 + 1], pa, bv[2], bv[3]);
                }
            }
        }
    }

    float inv0 = 1.f / l0, inv1 = 1.f / l1;
    #pragma unroll
    for (int nj = 0; nj < 8; nj++) {
        int col = h * DH + nj * 8 + c * 2;
        size_t g0 = (size_t)(b * SEQ + q0g) * DM + col;
        size_t g1 = (size_t)(b * SEQ + q0g + 8) * DM + col;
        *(__half2*)(Z + g0) = __floats2half2_rn(o[nj][0] * inv0, o[nj][1] * inv0);
        *(__half2*)(Z + g1) = __floats2half2_rn(o[nj][2] * inv1, o[nj][3] * inv1);
    }
}

// ---------------- launch -----------------------------------------------------
extern "C" void kernel_launch(void* const* d_in, const int* in_sizes, int n_in,
                              void* d_out, int out_size) {
    const float* resid_pre = (const float*)d_in[0];
    const float* W_Q   = (const float*)d_in[1];
    const float* b_Q   = (const float*)d_in[2];
    const float* W_K   = (const float*)d_in[3];
    const float* b_K   = (const float*)d_in[4];
    const float* W_V   = (const float*)d_in[5];
    const float* b_V   = (const float*)d_in[6];
    const float* W_O   = (const float*)d_in[7];
    const float* b_O   = (const float*)d_in[8];
    const float* ln1_w = (const float*)d_in[9];
    const float* ln1_b = (const float*)d_in[10];
    const float* ln2_w = (const float*)d_in[11];
    const float* ln2_b = (const float*)d_in[12];
    const float* W_in  = (const float*)d_in[13];
    const float* b_in  = (const float*)d_in[14];
    const float* W_out = (const float*)d_in[15];
    const float* b_out = (const float*)d_in[16];
    float* out = (float*)d_out;

    float *pbqkv, *pmid;
    __half *px_h, *pwqkv_h, *pqkv_h, *pz_h, *py_h, *ph_h, *pwo_h, *pwin_h, *pwout_h;
    cudaGetSymbolAddress((void**)&px_h,    g_x_h);
    cudaGetSymbolAddress((void**)&pwqkv_h, g_wqkv_h);
    cudaGetSymbolAddress((void**)&pbqkv,   g_bqkv);
    cudaGetSymbolAddress((void**)&pqkv_h,  g_qkv_h);
    cudaGetSymbolAddress((void**)&pz_h,    g_z_h);
    cudaGetSymbolAddress((void**)&pmid,    g_mid);
    cudaGetSymbolAddress((void**)&py_h,    g_y_h);
    cudaGetSymbolAddress((void**)&ph_h,    g_h_h);
    cudaGetSymbolAddress((void**)&pwo_h,   g_wo_h);
    cudaGetSymbolAddress((void**)&pwin_h,  g_win_h);
    cudaGetSymbolAddress((void**)&pwout_h, g_wout_h);

    cudaFuncSetAttribute((const void*)gemm_h<0,8>, cudaFuncAttributeMaxDynamicSharedMemorySize, GemmHCfg<8>::SMEM);
    cudaFuncSetAttribute((const void*)gemm_h<1,8>, cudaFuncAttributeMaxDynamicSharedMemorySize, GemmHCfg<8>::SMEM);
    cudaFuncSetAttribute((const void*)gemm_h<2,4>, cudaFuncAttributeMaxDynamicSharedMemorySize, GemmHCfg<4>::SMEM);
    cudaFuncSetAttribute((const void*)attn_h,      cudaFuncAttributeMaxDynamicSharedMemorySize, ATTNH_SMEM);

    prep_weights<<<(DM * DM + 255) / 256, 256>>>(
        W_Q, W_K, W_V, W_O, W_in, W_out, b_Q, b_K, b_V,
        pwqkv_h, pwo_h, pwin_h, pwout_h, pbqkv);

    ln4_h<<<ROWS / 4, 256>>>(resid_pre, ln1_w, ln1_b, px_h);
    gemm_h<0,8><<<dim3(QKVN / 128, ROWS / 128), 256, GemmHCfg<8>::SMEM>>>(
        px_h, pwqkv_h, pbqkv, nullptr, pqkv_h, ROWS, QKVN, DM);
    attn_h<<<dim3(SEQ / 128, NH, BATCH), 256, ATTNH_SMEM>>>(pqkv_h, pz_h);
    gemm_h<2,4><<<dim3(DM / 64, ROWS / 128), 256, GemmHCfg<4>::SMEM>>>(
        pz_h, pwo_h, b_O, resid_pre, pmid, ROWS, DM, DM);
    ln4_h<<<ROWS / 4, 256>>>(pmid, ln2_w, ln2_b, py_h);
    gemm_h<1,8><<<dim3(DMLP / 128, ROWS / 128), 256, GemmHCfg<8>::SMEM>>>(
        py_h, pwin_h, b_in, nullptr, ph_h, ROWS, DMLP, DM);
    gemm_h<2,4><<<dim3(DM / 64, ROWS / 128), 256, GemmHCfg<4>::SMEM>>>(
        ph_h, pwout_h, b_out, pmid, out, ROWS, DM, DMLP);
}